// round 2
// baseline (speedup 1.0000x reference)
#include <cuda_runtime.h>
#include <cstdint>

// ---------------------------------------------------------------------------
// InteractionModule: PhysNet-style message passing + residual stack.
//   xa = ssp(x)
//   t_same = ssp(xa @ W_same^T + b_same)        [N,128]
//   t_diff = ssp(xa @ W_diff^T + b_diff)        [N,128]
//   gate   = edge_attr @ G_w^T                  [E,128]
//   aggr[dst] += t_diff[src] * gate             (scatter-add)
//   msged  = t_same + aggr                      (output #2)
//   t = msged; 3x { y = ssp(t)@W1^T+b1; t += ssp(y)@W2^T+b2 }
//   out1 = ssp(t)@W_last^T + b_last + x*u       (output #1)
// ---------------------------------------------------------------------------

#define SSP_LOG2 0.69314718055994530942f

__device__ __forceinline__ float sspf(float x) {
    // shifted softplus, numerically stable: max(x,0)+log(1+exp(-|x|)) - log2
    return fmaxf(x, 0.0f) + __logf(1.0f + __expf(-fabsf(x))) - SSP_LOG2;
}

constexpr int FD   = 128;
constexpr int NMAX = 50176;

// static scratch (no allocation allowed)
__device__ float    g_tdiff[NMAX * FD];
__device__ float    g_y[NMAX * FD];
__device__ float    g_t[NMAX * FD];
__device__ unsigned g_or;

// ---------------------------------------------------------------------------
// edge_index dtype detection: odd 32-bit words all zero <=> int64
// ---------------------------------------------------------------------------
__global__ void reset_or_kernel() { g_or = 0u; }

__global__ void scan_odd_kernel(const unsigned* __restrict__ w, int E) {
    unsigned v = 0;
    for (int i = blockIdx.x * blockDim.x + threadIdx.x; i < E;
         i += gridDim.x * blockDim.x)
        v |= w[2 * i + 1];
    v = __reduce_or_sync(0xffffffffu, v);
    if ((threadIdx.x & 31) == 0 && v) atomicOr(&g_or, 1u);
}

// ---------------------------------------------------------------------------
// Node GEMM: out[n,c] = post( sum_k ssp(in[n,k]) * W[c,k] + bias[c] )
// MODE 0: out = ssp(r)
// MODE 1: out = r
// MODE 2: out = r + add[n,c]
// MODE 3: out = r + add[n,c] * u[c]
// BM=128 rows, BN=128 (full), BK=32, 256 threads, 8x8 microtile.
// ---------------------------------------------------------------------------
enum { OUT_SSP = 0, OUT_PLAIN = 1, OUT_ADD = 2, OUT_XU = 3 };

template <int MODE>
__global__ __launch_bounds__(256, 2)
void node_gemm(const float* __restrict__ in, const float* __restrict__ W,
               const float* __restrict__ bias, float* __restrict__ out,
               const float* __restrict__ add, const float* __restrict__ u,
               int N)
{
    __shared__ float A_s[32][132];  // [k][m], padded
    __shared__ float W_s[32][132];  // [k][c], padded

    const int t    = threadIdx.x;
    const int tx   = t & 15;   // column group: cols {tx*4..+3} U {64+tx*4..+3}
    const int ty   = t >> 4;   // row group: rows ty*8..ty*8+7
    const int row0 = blockIdx.x * 128;

    // fill mapping: fkf in [0,8) float4 k-group, fm in [0,32) row, 4 passes
    const int fkf = t & 7;
    const int fm  = t >> 3;

    float acc[8][8];
#pragma unroll
    for (int i = 0; i < 8; i++)
#pragma unroll
        for (int j = 0; j < 8; j++) acc[i][j] = 0.0f;

    for (int kt = 0; kt < 128; kt += 32) {
#pragma unroll
        for (int p = 0; p < 4; p++) {
            int m  = fm + p * 32;
            int gr = row0 + m;
            float4 v = make_float4(0.f, 0.f, 0.f, 0.f);
            if (gr < N)
                v = *(const float4*)(in + (size_t)gr * 128 + kt + fkf * 4);
            A_s[fkf * 4 + 0][m] = sspf(v.x);
            A_s[fkf * 4 + 1][m] = sspf(v.y);
            A_s[fkf * 4 + 2][m] = sspf(v.z);
            A_s[fkf * 4 + 3][m] = sspf(v.w);
        }
#pragma unroll
        for (int p = 0; p < 4; p++) {
            int c = fm + p * 32;
            float4 v = *(const float4*)(W + (size_t)c * 128 + kt + fkf * 4);
            W_s[fkf * 4 + 0][c] = v.x;
            W_s[fkf * 4 + 1][c] = v.y;
            W_s[fkf * 4 + 2][c] = v.z;
            W_s[fkf * 4 + 3][c] = v.w;
        }
        __syncthreads();

#pragma unroll
        for (int kk = 0; kk < 32; kk++) {
            float a[8], w[8];
            *(float4*)&a[0] = *(const float4*)&A_s[kk][ty * 8];
            *(float4*)&a[4] = *(const float4*)&A_s[kk][ty * 8 + 4];
            *(float4*)&w[0] = *(const float4*)&W_s[kk][tx * 4];
            *(float4*)&w[4] = *(const float4*)&W_s[kk][64 + tx * 4];
#pragma unroll
            for (int i = 0; i < 8; i++)
#pragma unroll
                for (int j = 0; j < 8; j++)
                    acc[i][j] = fmaf(a[i], w[j], acc[i][j]);
        }
        __syncthreads();
    }

    // epilogue
    float b[8];
    *(float4*)&b[0] = *(const float4*)(bias + tx * 4);
    *(float4*)&b[4] = *(const float4*)(bias + 64 + tx * 4);
    float uu[8];
    if (MODE == OUT_XU) {
        *(float4*)&uu[0] = *(const float4*)(u + tx * 4);
        *(float4*)&uu[4] = *(const float4*)(u + 64 + tx * 4);
    }

#pragma unroll
    for (int i = 0; i < 8; i++) {
        int r = row0 + ty * 8 + i;
        if (r >= N) break;
#pragma unroll
        for (int h = 0; h < 2; h++) {
            int c0 = h * 64 + tx * 4;
            float4 o;
            o.x = acc[i][h * 4 + 0] + b[h * 4 + 0];
            o.y = acc[i][h * 4 + 1] + b[h * 4 + 1];
            o.z = acc[i][h * 4 + 2] + b[h * 4 + 2];
            o.w = acc[i][h * 4 + 3] + b[h * 4 + 3];
            if (MODE == OUT_SSP) {
                o.x = sspf(o.x); o.y = sspf(o.y);
                o.z = sspf(o.z); o.w = sspf(o.w);
            } else if (MODE == OUT_ADD) {
                float4 av = *(const float4*)(add + (size_t)r * 128 + c0);
                o.x += av.x; o.y += av.y; o.z += av.z; o.w += av.w;
            } else if (MODE == OUT_XU) {
                float4 av = *(const float4*)(add + (size_t)r * 128 + c0);
                o.x += av.x * uu[h * 4 + 0];
                o.y += av.y * uu[h * 4 + 1];
                o.z += av.z * uu[h * 4 + 2];
                o.w += av.w * uu[h * 4 + 3];
            }
            *(float4*)(out + (size_t)r * 128 + c0) = o;
        }
    }
}

// ---------------------------------------------------------------------------
// Edge kernel: per block, 64 edges. gate = edge_attr @ G_w^T (tiled GEMM),
// msg = gate * t_diff[src], red.add.v4 into aggr[dst].
// 256 threads: te = t>>4 (4 edges each), tf = t&15 (8 features, split frags).
// ---------------------------------------------------------------------------
__global__ __launch_bounds__(256)
void edge_kernel(const void* __restrict__ idx_raw,
                 const float* __restrict__ ea,
                 const float* __restrict__ Gw,
                 const float* __restrict__ tdiff,
                 float* __restrict__ aggr,
                 int E)
{
    extern __shared__ float sm[];
    float (*EA)[68]  = (float(*)[68])sm;              // [64 k][64 e] padded
    float (*Gs)[132] = (float(*)[132])(sm + 64 * 68); // [64 k][128 f] padded

    const int t  = threadIdx.x;
    const int tf = t & 15;
    const int te = t >> 4;
    const int e0 = blockIdx.x * 64;

    // fill EA: kf = t&15 over 16 float4 k-groups, e = t>>4 + pass*16
    const int kf = t & 15;
    const int fe = t >> 4;
#pragma unroll
    for (int p = 0; p < 4; p++) {
        int e = fe + p * 16;
        float4 v = make_float4(0.f, 0.f, 0.f, 0.f);
        if (e0 + e < E)
            v = *(const float4*)(ea + (size_t)(e0 + e) * 64 + kf * 4);
        EA[kf * 4 + 0][e] = v.x;
        EA[kf * 4 + 1][e] = v.y;
        EA[kf * 4 + 2][e] = v.z;
        EA[kf * 4 + 3][e] = v.w;
    }
    // fill Gs: G_w is [128 f][64 k] -> Gs[k][f]
#pragma unroll
    for (int p = 0; p < 8; p++) {
        int f = fe + p * 16;
        float4 v = *(const float4*)(Gw + (size_t)f * 64 + kf * 4);
        Gs[kf * 4 + 0][f] = v.x;
        Gs[kf * 4 + 1][f] = v.y;
        Gs[kf * 4 + 2][f] = v.z;
        Gs[kf * 4 + 3][f] = v.w;
    }
    __syncthreads();

    float acc[4][8];
#pragma unroll
    for (int i = 0; i < 4; i++)
#pragma unroll
        for (int j = 0; j < 8; j++) acc[i][j] = 0.0f;

#pragma unroll 16
    for (int kk = 0; kk < 64; kk++) {
        float e4[4], g[8];
        *(float4*)&e4[0] = *(const float4*)&EA[kk][te * 4];
        *(float4*)&g[0]  = *(const float4*)&Gs[kk][tf * 4];
        *(float4*)&g[4]  = *(const float4*)&Gs[kk][64 + tf * 4];
#pragma unroll
        for (int i = 0; i < 4; i++)
#pragma unroll
            for (int j = 0; j < 8; j++)
                acc[i][j] = fmaf(e4[i], g[j], acc[i][j]);
    }

    const bool idx64 = (*(volatile unsigned*)&g_or) == 0u;
    const long long* ll = (const long long*)idx_raw;
    const int*       ii = (const int*)idx_raw;

#pragma unroll
    for (int i = 0; i < 4; i++) {
        int e = e0 + te * 4 + i;
        if (e >= E) continue;
        long long s, d;
        if (idx64) { s = ll[e]; d = ll[E + e]; }
        else       { s = ii[e]; d = ii[E + e]; }

        const float* tsrc = tdiff + (size_t)s * 128;
        float4 t0 = *(const float4*)(tsrc + tf * 4);
        float4 t1 = *(const float4*)(tsrc + 64 + tf * 4);

        float4 m0, m1;
        m0.x = acc[i][0] * t0.x; m0.y = acc[i][1] * t0.y;
        m0.z = acc[i][2] * t0.z; m0.w = acc[i][3] * t0.w;
        m1.x = acc[i][4] * t1.x; m1.y = acc[i][5] * t1.y;
        m1.z = acc[i][6] * t1.z; m1.w = acc[i][7] * t1.w;

        float* p0 = aggr + (size_t)d * 128 + tf * 4;
        float* p1 = p0 + 64;
        asm volatile("red.global.add.v4.f32 [%0], {%1, %2, %3, %4};"
                     :: "l"(p0), "f"(m0.x), "f"(m0.y), "f"(m0.z), "f"(m0.w)
                     : "memory");
        asm volatile("red.global.add.v4.f32 [%0], {%1, %2, %3, %4};"
                     :: "l"(p1), "f"(m1.x), "f"(m1.y), "f"(m1.z), "f"(m1.w)
                     : "memory");
    }
}

// ---------------------------------------------------------------------------
// launch
// ---------------------------------------------------------------------------
extern "C" void kernel_launch(void* const* d_in, const int* in_sizes, int n_in,
                              void* d_out, int out_size)
{
    const float* x     = (const float*)d_in[0];
    const void*  ei    = d_in[1];
    const float* ea    = (const float*)d_in[2];
    const float* Wsame = (const float*)d_in[3];
    const float* bsame = (const float*)d_in[4];
    const float* Wdiff = (const float*)d_in[5];
    const float* bdiff = (const float*)d_in[6];
    const float* Gw    = (const float*)d_in[7];
    const float* rW1   = (const float*)d_in[8];
    const float* rb1   = (const float*)d_in[9];
    const float* rW2   = (const float*)d_in[10];
    const float* rb2   = (const float*)d_in[11];
    const float* Wlast = (const float*)d_in[12];
    const float* blast = (const float*)d_in[13];
    const float* u     = (const float*)d_in[14];

    const int N = in_sizes[0] / 128;
    const int E = in_sizes[2] / 64;
    const int R = in_sizes[8] / (128 * 128);

    float* out1  = (float*)d_out;
    float* msged = (float*)d_out + (size_t)N * 128;

    float *tdiff_p, *y_p, *t_p;
    cudaGetSymbolAddress((void**)&tdiff_p, g_tdiff);
    cudaGetSymbolAddress((void**)&y_p, g_y);
    cudaGetSymbolAddress((void**)&t_p, g_t);

    const int nblk = (N + 127) / 128;
    const int eblk = (E + 63) / 64;

    // index dtype detection (re-run every replay; deterministic)
    reset_or_kernel<<<1, 1>>>();
    scan_odd_kernel<<<256, 256>>>((const unsigned*)ei, E);

    // t_same -> msged (also initializes output #2 region each replay)
    node_gemm<OUT_SSP><<<nblk, 256>>>(x, Wsame, bsame, msged, nullptr, nullptr, N);
    // t_diff
    node_gemm<OUT_SSP><<<nblk, 256>>>(x, Wdiff, bdiff, tdiff_p, nullptr, nullptr, N);

    // edge gate + message + scatter-add into msged
    size_t esm = (size_t)(64 * 68 + 64 * 132) * sizeof(float); // 51200 B
    cudaFuncSetAttribute(edge_kernel,
                         cudaFuncAttributeMaxDynamicSharedMemorySize, (int)esm);
    edge_kernel<<<eblk, 256, esm>>>(ei, ea, Gw, tdiff_p, msged, E);

    // residual stack
    const float* tin = msged;
    for (int i = 0; i < R; i++) {
        node_gemm<OUT_PLAIN><<<nblk, 256>>>(tin, rW1 + (size_t)i * 128 * 128,
                                            rb1 + (size_t)i * 128, y_p,
                                            nullptr, nullptr, N);
        node_gemm<OUT_ADD><<<nblk, 256>>>(y_p, rW2 + (size_t)i * 128 * 128,
                                          rb2 + (size_t)i * 128, t_p,
                                          tin, nullptr, N);
        tin = t_p;
    }

    // final: out1 = ssp(t)@W_last^T + b_last + x*u
    node_gemm<OUT_XU><<<nblk, 256>>>(tin, Wlast, blast, out1, x, u, N);
}

// round 5
// speedup vs baseline: 1.2960x; 1.2960x over previous
#include <cuda_runtime.h>
#include <cuda_bf16.h>
#include <cstdint>

// ---------------------------------------------------------------------------
// InteractionModule (PhysNet message passing + residual stack)
//   xa = ssp(x)
//   t_same = ssp(xa @ W_same^T + b_same)        [N,128]
//   t_diff = ssp(xa @ W_diff^T + b_diff)        [N,128]
//   gate   = edge_attr @ G_w^T                  [E,128]
//   aggr[dst] += t_diff[src] * gate             (scatter-add)
//   msged  = t_same + aggr                      (output #2)
//   t = msged; 3x { y = ssp(t)@W1^T+b1; t += ssp(y)@W2^T+b2 }
//   out1 = ssp(t)@W_last^T + b_last + x*u       (output #1)
//
// Node GEMMs: warp-level HMMA (mma.sync m16n8k16 bf16, generic-PTX legal),
// bf16 hi/lo split 3-term emulation, f32 accumulators, K staged in halves.
// ---------------------------------------------------------------------------

#define SSP_LOG2 0.69314718055994530942f

__device__ __forceinline__ float sspf(float x) {
    return fmaxf(x, 0.0f) + __logf(1.0f + __expf(-fabsf(x))) - SSP_LOG2;
}

constexpr int FD   = 128;
constexpr int NMAX = 50176;

__device__ float    g_tdiff[NMAX * FD];
__device__ float    g_y[NMAX * FD];
__device__ float    g_t[NMAX * FD];
__device__ unsigned g_or;

// ---------------------------------------------------------------------------
// edge_index dtype detection: odd 32-bit words all zero <=> int64
// ---------------------------------------------------------------------------
__global__ void reset_or_kernel() { g_or = 0u; }
__global__ void scan_odd_kernel(const unsigned* __restrict__ w, int E) {
    unsigned v = 0;
    for (int i = blockIdx.x * blockDim.x + threadIdx.x; i < E;
         i += gridDim.x * blockDim.x)
        v |= w[2 * i + 1];
    v = __reduce_or_sync(0xffffffffu, v);
    if ((threadIdx.x & 31) == 0 && v) atomicOr(&g_or, 1u);
}

// ---------------------------------------------------------------------------
// warp MMA helpers (generic PTX, sm_80+)
// ---------------------------------------------------------------------------
__device__ __forceinline__ uint32_t smem_u32(const void* p) {
    uint32_t a;
    asm("{ .reg .u64 t; cvta.to.shared.u64 t, %1; cvt.u32.u64 %0, t; }"
        : "=r"(a) : "l"(p));
    return a;
}
__device__ __forceinline__ void ldmx4(uint32_t* r, uint32_t addr) {
    asm volatile("ldmatrix.sync.aligned.m8n8.x4.shared.b16 {%0,%1,%2,%3}, [%4];"
                 : "=r"(r[0]), "=r"(r[1]), "=r"(r[2]), "=r"(r[3]) : "r"(addr));
}
__device__ __forceinline__ void ldmx2(uint32_t* r, uint32_t addr) {
    asm volatile("ldmatrix.sync.aligned.m8n8.x2.shared.b16 {%0,%1}, [%2];"
                 : "=r"(r[0]), "=r"(r[1]) : "r"(addr));
}
__device__ __forceinline__ void mma16816(float* d, const uint32_t* a,
                                         const uint32_t* b) {
    asm volatile("mma.sync.aligned.m16n8k16.row.col.f32.bf16.bf16.f32 "
                 "{%0,%1,%2,%3}, {%4,%5,%6,%7}, {%8,%9}, {%0,%1,%2,%3};"
                 : "+f"(d[0]), "+f"(d[1]), "+f"(d[2]), "+f"(d[3])
                 : "r"(a[0]), "r"(a[1]), "r"(a[2]), "r"(a[3]),
                   "r"(b[0]), "r"(b[1]));
}

// ---------------------------------------------------------------------------
// HMMA node GEMM: out[n,c] = post( sum_k ssp(in[n,k]) * W[c,k] + bias[c] )
// 256 threads, CTA tile M=128 x N=128. K processed in 2 halves of 64.
// smem per half: A_hi, A_lo, W_hi, W_lo each [128 rows][144 B]
//   (64 bf16 payload = 128 B + 16 B pad -> ldmatrix 8-row reads conflict-free)
// ---------------------------------------------------------------------------
enum { OUT_SSP = 0, OUT_PLAIN = 1, OUT_ADD = 2, OUT_XU = 3 };

constexpr int RS      = 144;               // row stride bytes (9 x 16B)
constexpr int MAT_SZ  = 128 * RS;          // 18432 B per matrix (K-half)
constexpr int SM_AHI  = 0;
constexpr int SM_ALO  = MAT_SZ;
constexpr int SM_WHI  = 2 * MAT_SZ;
constexpr int SM_WLO  = 3 * MAT_SZ;
constexpr int SM_TOTAL = 4 * MAT_SZ;       // 73728 B

// fill one K-half (64 cols) of a [128 x K] fp32 source into hi/lo bf16 tiles
template <bool DO_SSP>
__device__ __forceinline__ void fill_half(char* smem, int hi_off, int lo_off,
                                          const float* __restrict__ src,
                                          int row0, int nrows, int kh, int t) {
    const int kg = t & 7;           // 16B chunk (8 bf16) within the 128B half
    const int r0 = t >> 3;          // 32 rows per pass
#pragma unroll
    for (int p = 0; p < 4; p++) {
        int row = r0 + p * 32;
        float v[8];
        if (row < nrows) {
            const float* rp = src + (size_t)(row0 + row) * 128 + kh * 64 + kg * 8;
            float4 va = *(const float4*)(rp);
            float4 vb = *(const float4*)(rp + 4);
            v[0] = va.x; v[1] = va.y; v[2] = va.z; v[3] = va.w;
            v[4] = vb.x; v[5] = vb.y; v[6] = vb.z; v[7] = vb.w;
        } else {
#pragma unroll
            for (int i = 0; i < 8; i++) v[i] = 0.0f;
        }
        uint32_t hi[4], lo[4];
#pragma unroll
        for (int i = 0; i < 4; i++) {
            float a = v[2 * i], b = v[2 * i + 1];
            if (DO_SSP) { a = sspf(a); b = sspf(b); }
            __nv_bfloat16 ah = __float2bfloat16(a);
            __nv_bfloat16 bh = __float2bfloat16(b);
            __nv_bfloat16 al = __float2bfloat16(a - __bfloat162float(ah));
            __nv_bfloat16 bl = __float2bfloat16(b - __bfloat162float(bh));
            hi[i] = ((uint32_t)*(uint16_t*)&bh << 16) | *(uint16_t*)&ah;
            lo[i] = ((uint32_t)*(uint16_t*)&bl << 16) | *(uint16_t*)&al;
        }
        uint32_t off = (uint32_t)row * RS + kg * 16;
        *(uint4*)(smem + hi_off + off) = make_uint4(hi[0], hi[1], hi[2], hi[3]);
        *(uint4*)(smem + lo_off + off) = make_uint4(lo[0], lo[1], lo[2], lo[3]);
    }
}

template <int MODE>
__global__ __launch_bounds__(256, 2)
void tc_gemm(const float* __restrict__ in, const float* __restrict__ W,
             const float* __restrict__ bias, float* __restrict__ out,
             const float* __restrict__ add, const float* __restrict__ u,
             int N)
{
    extern __shared__ char smem[];
    const uint32_t sbase = smem_u32(smem);
    const int t     = threadIdx.x;
    const int lane  = t & 31;
    const int w     = t >> 5;
    const int row0  = blockIdx.x * 128;
    const int nrows = min(128, N - row0);

    // warp grid: 2 (m) x 4 (n); warp tile 64 x 32
    const int m_warp = (w >> 2) * 64;
    const int n_warp = (w & 3) * 32;

    // ldmatrix lane addressing (within a K-half tile)
    const int a_row = m_warp + ((lane >> 3) & 1) * 8 + (lane & 7);
    const int a_kh  = (lane >> 4) * 16;
    uint32_t aHiA[4], aLoA[4];
#pragma unroll
    for (int mi = 0; mi < 4; mi++) {
        uint32_t off = (uint32_t)(a_row + 16 * mi) * RS + a_kh;
        aHiA[mi] = sbase + SM_AHI + off;
        aLoA[mi] = sbase + SM_ALO + off;
    }
    const int b_lane = lane & 15;
    const int b_rowl = b_lane & 7;
    const int b_kh   = ((b_lane >> 3) & 1) * 16;
    uint32_t bHiA[4], bLoA[4];
#pragma unroll
    for (int nj = 0; nj < 4; nj++) {
        uint32_t off = (uint32_t)(n_warp + 8 * nj + b_rowl) * RS + b_kh;
        bHiA[nj] = sbase + SM_WHI + off;
        bLoA[nj] = sbase + SM_WLO + off;
    }

    float acc[4][4][4];
#pragma unroll
    for (int mi = 0; mi < 4; mi++)
#pragma unroll
        for (int nj = 0; nj < 4; nj++)
#pragma unroll
            for (int q = 0; q < 4; q++) acc[mi][nj][q] = 0.0f;

#pragma unroll
    for (int kh = 0; kh < 2; kh++) {
        if (kh) __syncthreads();   // previous half fully consumed
        fill_half<true >(smem, SM_AHI, SM_ALO, in, row0, nrows, kh, t);
        fill_half<false>(smem, SM_WHI, SM_WLO, W, 0, 128, kh, t);
        __syncthreads();

#pragma unroll
        for (int ks = 0; ks < 4; ks++) {
            const uint32_t koff = ks * 32;   // 16 bf16 = 32 B per k-step
            uint32_t af[4][4], bh[4][2], bl[4][2];
#pragma unroll
            for (int mi = 0; mi < 4; mi++) ldmx4(af[mi], aHiA[mi] + koff);
#pragma unroll
            for (int nj = 0; nj < 4; nj++) {
                ldmx2(bh[nj], bHiA[nj] + koff);
                ldmx2(bl[nj], bLoA[nj] + koff);
            }
#pragma unroll
            for (int mi = 0; mi < 4; mi++)
#pragma unroll
                for (int nj = 0; nj < 4; nj++) {
                    mma16816(acc[mi][nj], af[mi], bh[nj]);
                    mma16816(acc[mi][nj], af[mi], bl[nj]);
                }
            // reuse af registers for A_lo
#pragma unroll
            for (int mi = 0; mi < 4; mi++) ldmx4(af[mi], aLoA[mi] + koff);
#pragma unroll
            for (int mi = 0; mi < 4; mi++)
#pragma unroll
                for (int nj = 0; nj < 4; nj++)
                    mma16816(acc[mi][nj], af[mi], bh[nj]);
        }
    }

    // epilogue (register fragments -> global)
    const int r_in  = lane >> 2;          // row within 8-row group
    const int c_in  = (lane & 3) * 2;     // column pair
#pragma unroll
    for (int mi = 0; mi < 4; mi++) {
#pragma unroll
        for (int half = 0; half < 2; half++) {
            const int row = m_warp + 16 * mi + half * 8 + r_in;
            if (row >= nrows) continue;
            const size_t grow = (size_t)(row0 + row) * 128;
#pragma unroll
            for (int nj = 0; nj < 4; nj++) {
                const int col = n_warp + 8 * nj + c_in;
                float2 o;
                o.x = acc[mi][nj][half * 2 + 0];
                o.y = acc[mi][nj][half * 2 + 1];
                float2 b2 = *(const float2*)(bias + col);
                o.x += b2.x; o.y += b2.y;
                if (MODE == OUT_SSP) {
                    o.x = sspf(o.x); o.y = sspf(o.y);
                } else if (MODE == OUT_ADD) {
                    float2 a2 = *(const float2*)(add + grow + col);
                    o.x += a2.x; o.y += a2.y;
                } else if (MODE == OUT_XU) {
                    float2 a2 = *(const float2*)(add + grow + col);
                    float2 u2 = *(const float2*)(u + col);
                    o.x += a2.x * u2.x; o.y += a2.y * u2.y;
                }
                *(float2*)(out + grow + col) = o;
            }
        }
    }
}

// ---------------------------------------------------------------------------
// Edge kernel: 64 edges/block. gate = edge_attr @ G_w^T (smem-tiled fp32),
// msg = gate * t_diff[src], red.add.v4 into aggr[dst].
// ---------------------------------------------------------------------------
__global__ __launch_bounds__(256)
void edge_kernel(const void* __restrict__ idx_raw,
                 const float* __restrict__ ea,
                 const float* __restrict__ Gw,
                 const float* __restrict__ tdiff,
                 float* __restrict__ aggr,
                 int E)
{
    extern __shared__ float sm[];
    float (*EA)[68]  = (float(*)[68])sm;
    float (*Gs)[132] = (float(*)[132])(sm + 64 * 68);

    const int t  = threadIdx.x;
    const int tf = t & 15;
    const int te = t >> 4;
    const int e0 = blockIdx.x * 64;

    const int kf = t & 15;
    const int fe = t >> 4;
#pragma unroll
    for (int p = 0; p < 4; p++) {
        int e = fe + p * 16;
        float4 v = make_float4(0.f, 0.f, 0.f, 0.f);
        if (e0 + e < E)
            v = *(const float4*)(ea + (size_t)(e0 + e) * 64 + kf * 4);
        EA[kf * 4 + 0][e] = v.x;
        EA[kf * 4 + 1][e] = v.y;
        EA[kf * 4 + 2][e] = v.z;
        EA[kf * 4 + 3][e] = v.w;
    }
#pragma unroll
    for (int p = 0; p < 8; p++) {
        int f = fe + p * 16;
        float4 v = *(const float4*)(Gw + (size_t)f * 64 + kf * 4);
        Gs[kf * 4 + 0][f] = v.x;
        Gs[kf * 4 + 1][f] = v.y;
        Gs[kf * 4 + 2][f] = v.z;
        Gs[kf * 4 + 3][f] = v.w;
    }
    __syncthreads();

    float acc[4][8];
#pragma unroll
    for (int i = 0; i < 4; i++)
#pragma unroll
        for (int j = 0; j < 8; j++) acc[i][j] = 0.0f;

#pragma unroll 16
    for (int kk = 0; kk < 64; kk++) {
        float e4[4], g[8];
        *(float4*)&e4[0] = *(const float4*)&EA[kk][te * 4];
        *(float4*)&g[0]  = *(const float4*)&Gs[kk][tf * 4];
        *(float4*)&g[4]  = *(const float4*)&Gs[kk][64 + tf * 4];
#pragma unroll
        for (int i = 0; i < 4; i++)
#pragma unroll
            for (int j = 0; j < 8; j++)
                acc[i][j] = fmaf(e4[i], g[j], acc[i][j]);
    }

    const bool idx64 = (*(volatile unsigned*)&g_or) == 0u;
    const long long* ll = (const long long*)idx_raw;
    const int*       ii = (const int*)idx_raw;

#pragma unroll
    for (int i = 0; i < 4; i++) {
        int e = e0 + te * 4 + i;
        if (e >= E) continue;
        long long s, d;
        if (idx64) { s = ll[e]; d = ll[E + e]; }
        else       { s = ii[e]; d = ii[E + e]; }

        const float* tsrc = tdiff + (size_t)s * 128;
        float4 t0 = *(const float4*)(tsrc + tf * 4);
        float4 t1 = *(const float4*)(tsrc + 64 + tf * 4);

        float4 m0, m1;
        m0.x = acc[i][0] * t0.x; m0.y = acc[i][1] * t0.y;
        m0.z = acc[i][2] * t0.z; m0.w = acc[i][3] * t0.w;
        m1.x = acc[i][4] * t1.x; m1.y = acc[i][5] * t1.y;
        m1.z = acc[i][6] * t1.z; m1.w = acc[i][7] * t1.w;

        float* p0 = aggr + (size_t)d * 128 + tf * 4;
        float* p1 = p0 + 64;
        asm volatile("red.global.add.v4.f32 [%0], {%1, %2, %3, %4};"
                     :: "l"(p0), "f"(m0.x), "f"(m0.y), "f"(m0.z), "f"(m0.w)
                     : "memory");
        asm volatile("red.global.add.v4.f32 [%0], {%1, %2, %3, %4};"
                     :: "l"(p1), "f"(m1.x), "f"(m1.y), "f"(m1.z), "f"(m1.w)
                     : "memory");
    }
}

// ---------------------------------------------------------------------------
// launch
// ---------------------------------------------------------------------------
extern "C" void kernel_launch(void* const* d_in, const int* in_sizes, int n_in,
                              void* d_out, int out_size)
{
    const float* x     = (const float*)d_in[0];
    const void*  ei    = d_in[1];
    const float* ea    = (const float*)d_in[2];
    const float* Wsame = (const float*)d_in[3];
    const float* bsame = (const float*)d_in[4];
    const float* Wdiff = (const float*)d_in[5];
    const float* bdiff = (const float*)d_in[6];
    const float* Gw    = (const float*)d_in[7];
    const float* rW1   = (const float*)d_in[8];
    const float* rb1   = (const float*)d_in[9];
    const float* rW2   = (const float*)d_in[10];
    const float* rb2   = (const float*)d_in[11];
    const float* Wlast = (const float*)d_in[12];
    const float* blast = (const float*)d_in[13];
    const float* u     = (const float*)d_in[14];

    const int N = in_sizes[0] / 128;
    const int E = in_sizes[2] / 64;
    const int R = in_sizes[8] / (128 * 128);

    float* out1  = (float*)d_out;
    float* msged = (float*)d_out + (size_t)N * 128;

    float *tdiff_p, *y_p, *t_p;
    cudaGetSymbolAddress((void**)&tdiff_p, g_tdiff);
    cudaGetSymbolAddress((void**)&y_p, g_y);
    cudaGetSymbolAddress((void**)&t_p, g_t);

    const int nblk = (N + 127) / 128;
    const int eblk = (E + 63) / 64;

    cudaFuncSetAttribute(tc_gemm<OUT_SSP>,
                         cudaFuncAttributeMaxDynamicSharedMemorySize, SM_TOTAL);
    cudaFuncSetAttribute(tc_gemm<OUT_PLAIN>,
                         cudaFuncAttributeMaxDynamicSharedMemorySize, SM_TOTAL);
    cudaFuncSetAttribute(tc_gemm<OUT_ADD>,
                         cudaFuncAttributeMaxDynamicSharedMemorySize, SM_TOTAL);
    cudaFuncSetAttribute(tc_gemm<OUT_XU>,
                         cudaFuncAttributeMaxDynamicSharedMemorySize, SM_TOTAL);

    // index dtype detection (deterministic, re-run every replay)
    reset_or_kernel<<<1, 1>>>();
    scan_odd_kernel<<<256, 256>>>((const unsigned*)ei, E);

    // t_same -> msged (initializes output #2 region each replay)
    tc_gemm<OUT_SSP><<<nblk, 256, SM_TOTAL>>>(x, Wsame, bsame, msged,
                                              nullptr, nullptr, N);
    // t_diff
    tc_gemm<OUT_SSP><<<nblk, 256, SM_TOTAL>>>(x, Wdiff, bdiff, tdiff_p,
                                              nullptr, nullptr, N);

    // edge gate + message + scatter-add into msged
    size_t esm = (size_t)(64 * 68 + 64 * 132) * sizeof(float);
    cudaFuncSetAttribute(edge_kernel,
                         cudaFuncAttributeMaxDynamicSharedMemorySize, (int)esm);
    edge_kernel<<<eblk, 256, esm>>>(ei, ea, Gw, tdiff_p, msged, E);

    // residual stack
    const float* tin = msged;
    for (int i = 0; i < R; i++) {
        tc_gemm<OUT_PLAIN><<<nblk, 256, SM_TOTAL>>>(tin, rW1 + (size_t)i * 128 * 128,
                                                    rb1 + (size_t)i * 128, y_p,
                                                    nullptr, nullptr, N);
        tc_gemm<OUT_ADD><<<nblk, 256, SM_TOTAL>>>(y_p, rW2 + (size_t)i * 128 * 128,
                                                  rb2 + (size_t)i * 128, t_p,
                                                  tin, nullptr, N);
        tin = t_p;
    }

    // final: out1 = ssp(t)@W_last^T + b_last + x*u
    tc_gemm<OUT_XU><<<nblk, 256, SM_TOTAL>>>(tin, Wlast, blast, out1, x, u, N);
}

// round 6
// speedup vs baseline: 1.6080x; 1.2407x over previous
#include <cuda_runtime.h>
#include <cuda_bf16.h>
#include <cstdint>

// ---------------------------------------------------------------------------
// InteractionModule (PhysNet message passing + residual stack)
//   xa = ssp(x)
//   t_same = ssp(xa @ W_same^T + b_same)        [N,128]
//   t_diff = ssp(xa @ W_diff^T + b_diff)        [N,128]
//   gate   = edge_attr @ G_w^T                  [E,128]
//   aggr[dst] += t_diff[src] * gate             (scatter-add)
//   msged  = t_same + aggr                      (output #2)
//   t = msged; 3x { y = ssp(t)@W1^T+b1; t += ssp(y)@W2^T+b2 }
//   out1 = ssp(t)@W_last^T + b_last + x*u       (output #1)
//
// All GEMMs (node + edge gate) on HMMA mma.sync m16n8k16 bf16,
// bf16 hi/lo split 3-term emulation, f32 accumulators.
// ---------------------------------------------------------------------------

#define SSP_LOG2 0.69314718055994530942f

__device__ __forceinline__ float sspf(float x) {
    return fmaxf(x, 0.0f) + __logf(1.0f + __expf(-fabsf(x))) - SSP_LOG2;
}

constexpr int FD   = 128;
constexpr int NMAX = 50176;

__device__ float    g_tdiff[NMAX * FD];
__device__ float    g_y[NMAX * FD];
__device__ float    g_t[NMAX * FD];
__device__ unsigned g_or;

// ---------------------------------------------------------------------------
// edge_index dtype detection: odd 32-bit words all zero <=> int64
// ---------------------------------------------------------------------------
__global__ void reset_or_kernel() { g_or = 0u; }
__global__ void scan_odd_kernel(const unsigned* __restrict__ w, int E) {
    unsigned v = 0;
    for (int i = blockIdx.x * blockDim.x + threadIdx.x; i < E;
         i += gridDim.x * blockDim.x)
        v |= w[2 * i + 1];
    v = __reduce_or_sync(0xffffffffu, v);
    if ((threadIdx.x & 31) == 0 && v) atomicOr(&g_or, 1u);
}

// ---------------------------------------------------------------------------
// warp MMA helpers (generic PTX, sm_80+)
// ---------------------------------------------------------------------------
__device__ __forceinline__ uint32_t smem_u32(const void* p) {
    uint32_t a;
    asm("{ .reg .u64 t; cvta.to.shared.u64 t, %1; cvt.u32.u64 %0, t; }"
        : "=r"(a) : "l"(p));
    return a;
}
__device__ __forceinline__ void ldmx4(uint32_t* r, uint32_t addr) {
    asm volatile("ldmatrix.sync.aligned.m8n8.x4.shared.b16 {%0,%1,%2,%3}, [%4];"
                 : "=r"(r[0]), "=r"(r[1]), "=r"(r[2]), "=r"(r[3]) : "r"(addr));
}
__device__ __forceinline__ void ldmx2(uint32_t* r, uint32_t addr) {
    asm volatile("ldmatrix.sync.aligned.m8n8.x2.shared.b16 {%0,%1}, [%2];"
                 : "=r"(r[0]), "=r"(r[1]) : "r"(addr));
}
__device__ __forceinline__ void mma16816(float* d, const uint32_t* a,
                                         const uint32_t* b) {
    asm volatile("mma.sync.aligned.m16n8k16.row.col.f32.bf16.bf16.f32 "
                 "{%0,%1,%2,%3}, {%4,%5,%6,%7}, {%8,%9}, {%0,%1,%2,%3};"
                 : "+f"(d[0]), "+f"(d[1]), "+f"(d[2]), "+f"(d[3])
                 : "r"(a[0]), "r"(a[1]), "r"(a[2]), "r"(a[3]),
                   "r"(b[0]), "r"(b[1]));
}

constexpr int RS      = 144;               // row stride bytes (9 x 16B)
constexpr int MAT_SZ  = 128 * RS;          // 18432 B per [128 x 64] bf16 tile
constexpr int SM_AHI  = 0;
constexpr int SM_ALO  = MAT_SZ;
constexpr int SM_WHI  = 2 * MAT_SZ;
constexpr int SM_WLO  = 3 * MAT_SZ;
constexpr int SM_TOTAL = 4 * MAT_SZ;       // 73728 B

// fill a [128 x 64] fp32 sub-tile (at col offset kh*64, row stride src_ld)
// into hi/lo bf16 smem tiles (row stride RS bytes)
template <bool DO_SSP>
__device__ __forceinline__ void fill_half(char* smem, int hi_off, int lo_off,
                                          const float* __restrict__ src,
                                          int src_ld, int row0, int nrows,
                                          int kh, int t) {
    const int kg = t & 7;           // 16B chunk (8 bf16) within the 128B half
    const int r0 = t >> 3;          // 32 rows per pass
#pragma unroll
    for (int p = 0; p < 4; p++) {
        int row = r0 + p * 32;
        float v[8];
        if (row < nrows) {
            const float* rp = src + (size_t)(row0 + row) * src_ld + kh * 64 + kg * 8;
            float4 va = *(const float4*)(rp);
            float4 vb = *(const float4*)(rp + 4);
            v[0] = va.x; v[1] = va.y; v[2] = va.z; v[3] = va.w;
            v[4] = vb.x; v[5] = vb.y; v[6] = vb.z; v[7] = vb.w;
        } else {
#pragma unroll
            for (int i = 0; i < 8; i++) v[i] = 0.0f;
        }
        uint32_t hi[4], lo[4];
#pragma unroll
        for (int i = 0; i < 4; i++) {
            float a = v[2 * i], b = v[2 * i + 1];
            if (DO_SSP) { a = sspf(a); b = sspf(b); }
            __nv_bfloat16 ah = __float2bfloat16(a);
            __nv_bfloat16 bh = __float2bfloat16(b);
            __nv_bfloat16 al = __float2bfloat16(a - __bfloat162float(ah));
            __nv_bfloat16 bl = __float2bfloat16(b - __bfloat162float(bh));
            hi[i] = ((uint32_t)*(uint16_t*)&bh << 16) | *(uint16_t*)&ah;
            lo[i] = ((uint32_t)*(uint16_t*)&bl << 16) | *(uint16_t*)&al;
        }
        uint32_t off = (uint32_t)row * RS + kg * 16;
        *(uint4*)(smem + hi_off + off) = make_uint4(hi[0], hi[1], hi[2], hi[3]);
        *(uint4*)(smem + lo_off + off) = make_uint4(lo[0], lo[1], lo[2], lo[3]);
    }
}

// ---------------------------------------------------------------------------
// HMMA node GEMM: out[n,c] = post( sum_k ssp(in[n,k]) * W[c,k] + bias[c] )
// 256 threads, CTA tile M=128 x N=128, K=128 in 2 halves of 64.
// ---------------------------------------------------------------------------
enum { OUT_SSP = 0, OUT_PLAIN = 1, OUT_ADD = 2, OUT_XU = 3 };

template <int MODE>
__global__ __launch_bounds__(256, 2)
void tc_gemm(const float* __restrict__ in, const float* __restrict__ W,
             const float* __restrict__ bias, float* __restrict__ out,
             const float* __restrict__ add, const float* __restrict__ u,
             int N)
{
    extern __shared__ char smem[];
    const uint32_t sbase = smem_u32(smem);
    const int t     = threadIdx.x;
    const int lane  = t & 31;
    const int w     = t >> 5;
    const int row0  = blockIdx.x * 128;
    const int nrows = min(128, N - row0);

    const int m_warp = (w >> 2) * 64;
    const int n_warp = (w & 3) * 32;

    const int a_row = m_warp + ((lane >> 3) & 1) * 8 + (lane & 7);
    const int a_kh  = (lane >> 4) * 16;
    uint32_t aHiA[4], aLoA[4];
#pragma unroll
    for (int mi = 0; mi < 4; mi++) {
        uint32_t off = (uint32_t)(a_row + 16 * mi) * RS + a_kh;
        aHiA[mi] = sbase + SM_AHI + off;
        aLoA[mi] = sbase + SM_ALO + off;
    }
    const int b_lane = lane & 15;
    const int b_rowl = b_lane & 7;
    const int b_kh   = ((b_lane >> 3) & 1) * 16;
    uint32_t bHiA[4], bLoA[4];
#pragma unroll
    for (int nj = 0; nj < 4; nj++) {
        uint32_t off = (uint32_t)(n_warp + 8 * nj + b_rowl) * RS + b_kh;
        bHiA[nj] = sbase + SM_WHI + off;
        bLoA[nj] = sbase + SM_WLO + off;
    }

    float acc[4][4][4];
#pragma unroll
    for (int mi = 0; mi < 4; mi++)
#pragma unroll
        for (int nj = 0; nj < 4; nj++)
#pragma unroll
            for (int q = 0; q < 4; q++) acc[mi][nj][q] = 0.0f;

#pragma unroll
    for (int kh = 0; kh < 2; kh++) {
        if (kh) __syncthreads();
        fill_half<true >(smem, SM_AHI, SM_ALO, in, 128, row0, nrows, kh, t);
        fill_half<false>(smem, SM_WHI, SM_WLO, W, 128, 0, 128, kh, t);
        __syncthreads();

#pragma unroll
        for (int ks = 0; ks < 4; ks++) {
            const uint32_t koff = ks * 32;
            uint32_t af[4][4], bh[4][2], bl[4][2];
#pragma unroll
            for (int mi = 0; mi < 4; mi++) ldmx4(af[mi], aHiA[mi] + koff);
#pragma unroll
            for (int nj = 0; nj < 4; nj++) {
                ldmx2(bh[nj], bHiA[nj] + koff);
                ldmx2(bl[nj], bLoA[nj] + koff);
            }
#pragma unroll
            for (int mi = 0; mi < 4; mi++)
#pragma unroll
                for (int nj = 0; nj < 4; nj++) {
                    mma16816(acc[mi][nj], af[mi], bh[nj]);
                    mma16816(acc[mi][nj], af[mi], bl[nj]);
                }
#pragma unroll
            for (int mi = 0; mi < 4; mi++) ldmx4(af[mi], aLoA[mi] + koff);
#pragma unroll
            for (int mi = 0; mi < 4; mi++)
#pragma unroll
                for (int nj = 0; nj < 4; nj++)
                    mma16816(acc[mi][nj], af[mi], bh[nj]);
        }
    }

    const int r_in  = lane >> 2;
    const int c_in  = (lane & 3) * 2;
#pragma unroll
    for (int mi = 0; mi < 4; mi++) {
#pragma unroll
        for (int half = 0; half < 2; half++) {
            const int row = m_warp + 16 * mi + half * 8 + r_in;
            if (row >= nrows) continue;
            const size_t grow = (size_t)(row0 + row) * 128;
#pragma unroll
            for (int nj = 0; nj < 4; nj++) {
                const int col = n_warp + 8 * nj + c_in;
                float2 o;
                o.x = acc[mi][nj][half * 2 + 0];
                o.y = acc[mi][nj][half * 2 + 1];
                float2 b2 = *(const float2*)(bias + col);
                o.x += b2.x; o.y += b2.y;
                if (MODE == OUT_SSP) {
                    o.x = sspf(o.x); o.y = sspf(o.y);
                } else if (MODE == OUT_ADD) {
                    float2 a2 = *(const float2*)(add + grow + col);
                    o.x += a2.x; o.y += a2.y;
                } else if (MODE == OUT_XU) {
                    float2 a2 = *(const float2*)(add + grow + col);
                    float2 u2 = *(const float2*)(u + col);
                    o.x += a2.x * u2.x; o.y += a2.y * u2.y;
                }
                *(float2*)(out + grow + col) = o;
            }
        }
    }
}

// ---------------------------------------------------------------------------
// HMMA edge kernel: 128 edges/block.
//   gate[128,128] = edge_attr[128,64] @ G_w^T  (bf16 hi/lo 3-term HMMA)
//   stage gate through smem, then per-edge: msg = gate * t_diff[src],
//   red.global.add.v4 into aggr[dst].
// ---------------------------------------------------------------------------
constexpr int GSTR = 136;   // gate smem row stride in floats
constexpr int ESM_TOTAL = SM_TOTAL;  // 73728 >= 128*136*4 = 69632

__global__ __launch_bounds__(256, 2)
void edge_kernel(const void* __restrict__ idx_raw,
                 const float* __restrict__ ea,
                 const float* __restrict__ Gw,
                 const float* __restrict__ tdiff,
                 float* __restrict__ aggr,
                 int E)
{
    extern __shared__ char smem[];
    const uint32_t sbase = smem_u32(smem);
    float* gsm = (float*)smem;

    const int t    = threadIdx.x;
    const int lane = t & 31;
    const int w    = t >> 5;
    const int e0   = blockIdx.x * 128;
    const int nrows = min(128, E - e0);

    const int m_warp = (w >> 2) * 64;
    const int n_warp = (w & 3) * 32;

    // tile fills: A = edge_attr rows (stride 64), B = G_w rows (stride 64)
    fill_half<false>(smem, SM_AHI, SM_ALO, ea, 64, e0, nrows, 0, t);
    fill_half<false>(smem, SM_WHI, SM_WLO, Gw, 64, 0, 128, 0, t);
    __syncthreads();

    const int a_row = m_warp + ((lane >> 3) & 1) * 8 + (lane & 7);
    const int a_kh  = (lane >> 4) * 16;
    uint32_t aHiA[4], aLoA[4];
#pragma unroll
    for (int mi = 0; mi < 4; mi++) {
        uint32_t off = (uint32_t)(a_row + 16 * mi) * RS + a_kh;
        aHiA[mi] = sbase + SM_AHI + off;
        aLoA[mi] = sbase + SM_ALO + off;
    }
    const int b_lane = lane & 15;
    const int b_rowl = b_lane & 7;
    const int b_kh   = ((b_lane >> 3) & 1) * 16;
    uint32_t bHiA[4], bLoA[4];
#pragma unroll
    for (int nj = 0; nj < 4; nj++) {
        uint32_t off = (uint32_t)(n_warp + 8 * nj + b_rowl) * RS + b_kh;
        bHiA[nj] = sbase + SM_WHI + off;
        bLoA[nj] = sbase + SM_WLO + off;
    }

    float acc[4][4][4];
#pragma unroll
    for (int mi = 0; mi < 4; mi++)
#pragma unroll
        for (int nj = 0; nj < 4; nj++)
#pragma unroll
            for (int q = 0; q < 4; q++) acc[mi][nj][q] = 0.0f;

#pragma unroll
    for (int ks = 0; ks < 4; ks++) {   // K = 64
        const uint32_t koff = ks * 32;
        uint32_t af[4][4], bh[4][2], bl[4][2];
#pragma unroll
        for (int mi = 0; mi < 4; mi++) ldmx4(af[mi], aHiA[mi] + koff);
#pragma unroll
        for (int nj = 0; nj < 4; nj++) {
            ldmx2(bh[nj], bHiA[nj] + koff);
            ldmx2(bl[nj], bLoA[nj] + koff);
        }
#pragma unroll
        for (int mi = 0; mi < 4; mi++)
#pragma unroll
            for (int nj = 0; nj < 4; nj++) {
                mma16816(acc[mi][nj], af[mi], bh[nj]);
                mma16816(acc[mi][nj], af[mi], bl[nj]);
            }
#pragma unroll
        for (int mi = 0; mi < 4; mi++) ldmx4(af[mi], aLoA[mi] + koff);
#pragma unroll
        for (int mi = 0; mi < 4; mi++)
#pragma unroll
            for (int nj = 0; nj < 4; nj++)
                mma16816(acc[mi][nj], af[mi], bh[nj]);
    }

    __syncthreads();   // tiles fully consumed; reuse smem for gate f32

    const int r_in = lane >> 2;
    const int c_in = (lane & 3) * 2;
#pragma unroll
    for (int mi = 0; mi < 4; mi++)
#pragma unroll
        for (int half = 0; half < 2; half++) {
            const int row = m_warp + 16 * mi + half * 8 + r_in;
#pragma unroll
            for (int nj = 0; nj < 4; nj++) {
                const int col = n_warp + 8 * nj + c_in;
                float2 o;
                o.x = acc[mi][nj][half * 2 + 0];
                o.y = acc[mi][nj][half * 2 + 1];
                *(float2*)(gsm + (size_t)row * GSTR + col) = o;
            }
        }
    __syncthreads();

    // scatter phase: warp w owns edges [w*16, w*16+16)
    const bool idx64 = (*(volatile unsigned*)&g_or) == 0u;
    const long long* ll = (const long long*)idx_raw;
    const int*       ii = (const int*)idx_raw;

#pragma unroll 4
    for (int el = w * 16; el < w * 16 + 16; el++) {
        int e = e0 + el;
        if (e >= E) break;
        long long s, d;
        if (idx64) { s = ll[e]; d = ll[E + e]; }
        else       { s = ii[e]; d = ii[E + e]; }

        float4 g4 = *(const float4*)(gsm + (size_t)el * GSTR + lane * 4);
        float4 t4 = *(const float4*)(tdiff + (size_t)s * 128 + lane * 4);
        float4 m;
        m.x = g4.x * t4.x; m.y = g4.y * t4.y;
        m.z = g4.z * t4.z; m.w = g4.w * t4.w;

        float* p = aggr + (size_t)d * 128 + lane * 4;
        asm volatile("red.global.add.v4.f32 [%0], {%1, %2, %3, %4};"
                     :: "l"(p), "f"(m.x), "f"(m.y), "f"(m.z), "f"(m.w)
                     : "memory");
    }
}

// ---------------------------------------------------------------------------
// launch
// ---------------------------------------------------------------------------
extern "C" void kernel_launch(void* const* d_in, const int* in_sizes, int n_in,
                              void* d_out, int out_size)
{
    const float* x     = (const float*)d_in[0];
    const void*  ei    = d_in[1];
    const float* ea    = (const float*)d_in[2];
    const float* Wsame = (const float*)d_in[3];
    const float* bsame = (const float*)d_in[4];
    const float* Wdiff = (const float*)d_in[5];
    const float* bdiff = (const float*)d_in[6];
    const float* Gw    = (const float*)d_in[7];
    const float* rW1   = (const float*)d_in[8];
    const float* rb1   = (const float*)d_in[9];
    const float* rW2   = (const float*)d_in[10];
    const float* rb2   = (const float*)d_in[11];
    const float* Wlast = (const float*)d_in[12];
    const float* blast = (const float*)d_in[13];
    const float* u     = (const float*)d_in[14];

    const int N = in_sizes[0] / 128;
    const int E = in_sizes[2] / 64;
    const int R = in_sizes[8] / (128 * 128);

    float* out1  = (float*)d_out;
    float* msged = (float*)d_out + (size_t)N * 128;

    float *tdiff_p, *y_p, *t_p;
    cudaGetSymbolAddress((void**)&tdiff_p, g_tdiff);
    cudaGetSymbolAddress((void**)&y_p, g_y);
    cudaGetSymbolAddress((void**)&t_p, g_t);

    const int nblk = (N + 127) / 128;
    const int eblk = (E + 127) / 128;

    cudaFuncSetAttribute(tc_gemm<OUT_SSP>,
                         cudaFuncAttributeMaxDynamicSharedMemorySize, SM_TOTAL);
    cudaFuncSetAttribute(tc_gemm<OUT_PLAIN>,
                         cudaFuncAttributeMaxDynamicSharedMemorySize, SM_TOTAL);
    cudaFuncSetAttribute(tc_gemm<OUT_ADD>,
                         cudaFuncAttributeMaxDynamicSharedMemorySize, SM_TOTAL);
    cudaFuncSetAttribute(tc_gemm<OUT_XU>,
                         cudaFuncAttributeMaxDynamicSharedMemorySize, SM_TOTAL);
    cudaFuncSetAttribute(edge_kernel,
                         cudaFuncAttributeMaxDynamicSharedMemorySize, ESM_TOTAL);

    // index dtype detection (deterministic, re-run every replay)
    reset_or_kernel<<<1, 1>>>();
    scan_odd_kernel<<<256, 256>>>((const unsigned*)ei, E);

    // t_same -> msged (initializes output #2 region each replay)
    tc_gemm<OUT_SSP><<<nblk, 256, SM_TOTAL>>>(x, Wsame, bsame, msged,
                                              nullptr, nullptr, N);
    // t_diff
    tc_gemm<OUT_SSP><<<nblk, 256, SM_TOTAL>>>(x, Wdiff, bdiff, tdiff_p,
                                              nullptr, nullptr, N);

    // edge gate + message + scatter-add into msged
    edge_kernel<<<eblk, 256, ESM_TOTAL>>>(ei, ea, Gw, tdiff_p, msged, E);

    // residual stack
    const float* tin = msged;
    for (int i = 0; i < R; i++) {
        tc_gemm<OUT_PLAIN><<<nblk, 256, SM_TOTAL>>>(tin, rW1 + (size_t)i * 128 * 128,
                                                    rb1 + (size_t)i * 128, y_p,
                                                    nullptr, nullptr, N);
        tc_gemm<OUT_ADD><<<nblk, 256, SM_TOTAL>>>(y_p, rW2 + (size_t)i * 128 * 128,
                                                  rb2 + (size_t)i * 128, t_p,
                                                  tin, nullptr, N);
        tin = t_p;
    }

    // final: out1 = ssp(t)@W_last^T + b_last + x*u
    tc_gemm<OUT_XU><<<nblk, 256, SM_TOTAL>>>(tin, Wlast, blast, out1, x, u, N);
}

// round 7
// speedup vs baseline: 1.6768x; 1.0428x over previous
#include <cuda_runtime.h>
#include <cuda_bf16.h>
#include <cstdint>

// ---------------------------------------------------------------------------
// InteractionModule (PhysNet message passing + residual stack)
// All GEMMs on HMMA mma.sync m16n8k16 bf16, hi/lo split 3-term emulation.
// Residual layers fused in pairs (y kept in-CTA, never hits global memory).
// ---------------------------------------------------------------------------

#define SSP_LOG2 0.69314718055994530942f

__device__ __forceinline__ float sspf(float x) {
    return fmaxf(x, 0.0f) + __logf(1.0f + __expf(-fabsf(x))) - SSP_LOG2;
}

constexpr int FD   = 128;
constexpr int NMAX = 50176;

__device__ float    g_tdiff[NMAX * FD];
__device__ float    g_t[NMAX * FD];
__device__ unsigned g_or;

// ---------------------------------------------------------------------------
// edge_index dtype detection: odd 32-bit words all zero <=> int64
// ---------------------------------------------------------------------------
__global__ void reset_or_kernel() { g_or = 0u; }
__global__ void scan_odd_kernel(const unsigned* __restrict__ w, int E) {
    unsigned v = 0;
    for (int i = blockIdx.x * blockDim.x + threadIdx.x; i < E;
         i += gridDim.x * blockDim.x)
        v |= w[2 * i + 1];
    v = __reduce_or_sync(0xffffffffu, v);
    if ((threadIdx.x & 31) == 0 && v) atomicOr(&g_or, 1u);
}

// ---------------------------------------------------------------------------
// warp MMA helpers (generic PTX, sm_80+)
// ---------------------------------------------------------------------------
__device__ __forceinline__ uint32_t smem_u32(const void* p) {
    uint32_t a;
    asm("{ .reg .u64 t; cvta.to.shared.u64 t, %1; cvt.u32.u64 %0, t; }"
        : "=r"(a) : "l"(p));
    return a;
}
__device__ __forceinline__ void ldmx4(uint32_t* r, uint32_t addr) {
    asm volatile("ldmatrix.sync.aligned.m8n8.x4.shared.b16 {%0,%1,%2,%3}, [%4];"
                 : "=r"(r[0]), "=r"(r[1]), "=r"(r[2]), "=r"(r[3]) : "r"(addr));
}
__device__ __forceinline__ void ldmx2(uint32_t* r, uint32_t addr) {
    asm volatile("ldmatrix.sync.aligned.m8n8.x2.shared.b16 {%0,%1}, [%2];"
                 : "=r"(r[0]), "=r"(r[1]) : "r"(addr));
}
__device__ __forceinline__ void mma16816(float* d, const uint32_t* a,
                                         const uint32_t* b) {
    asm volatile("mma.sync.aligned.m16n8k16.row.col.f32.bf16.bf16.f32 "
                 "{%0,%1,%2,%3}, {%4,%5,%6,%7}, {%8,%9}, {%0,%1,%2,%3};"
                 : "+f"(d[0]), "+f"(d[1]), "+f"(d[2]), "+f"(d[3])
                 : "r"(a[0]), "r"(a[1]), "r"(a[2]), "r"(a[3]),
                   "r"(b[0]), "r"(b[1]));
}

constexpr int RS      = 144;               // row stride bytes (9 x 16B)
constexpr int MAT_SZ  = 128 * RS;          // 18432 B per [128 x 64] bf16 tile
// 4-buffer layout (tc_gemm / edge_kernel)
constexpr int SM_AHI  = 0;
constexpr int SM_ALO  = MAT_SZ;
constexpr int SM_WHI  = 2 * MAT_SZ;
constexpr int SM_WLO  = 3 * MAT_SZ;
constexpr int SM_TOTAL = 4 * MAT_SZ;       // 73728 B
// 6-buffer layout (res_pair): BUF0..BUF5
constexpr int SM_TOTAL6 = 6 * MAT_SZ;      // 110592 B

__device__ __forceinline__ void split_pack(float a, float b,
                                           uint32_t& hi, uint32_t& lo) {
    __nv_bfloat16 ah = __float2bfloat16(a);
    __nv_bfloat16 bh = __float2bfloat16(b);
    __nv_bfloat16 al = __float2bfloat16(a - __bfloat162float(ah));
    __nv_bfloat16 bl = __float2bfloat16(b - __bfloat162float(bh));
    hi = ((uint32_t)*(uint16_t*)&bh << 16) | *(uint16_t*)&ah;
    lo = ((uint32_t)*(uint16_t*)&bl << 16) | *(uint16_t*)&al;
}

// fill a [128 x 64] fp32 sub-tile (col offset kh*64, row stride src_ld)
// into hi/lo bf16 smem tiles (row stride RS bytes)
template <bool DO_SSP>
__device__ __forceinline__ void fill_half(char* smem, int hi_off, int lo_off,
                                          const float* __restrict__ src,
                                          int src_ld, int row0, int nrows,
                                          int kh, int t) {
    const int kg = t & 7;
    const int r0 = t >> 3;
#pragma unroll
    for (int p = 0; p < 4; p++) {
        int row = r0 + p * 32;
        float v[8];
        if (row < nrows) {
            const float* rp = src + (size_t)(row0 + row) * src_ld + kh * 64 + kg * 8;
            float4 va = *(const float4*)(rp);
            float4 vb = *(const float4*)(rp + 4);
            v[0] = va.x; v[1] = va.y; v[2] = va.z; v[3] = va.w;
            v[4] = vb.x; v[5] = vb.y; v[6] = vb.z; v[7] = vb.w;
        } else {
#pragma unroll
            for (int i = 0; i < 8; i++) v[i] = 0.0f;
        }
        uint32_t hi[4], lo[4];
#pragma unroll
        for (int i = 0; i < 4; i++) {
            float a = v[2 * i], b = v[2 * i + 1];
            if (DO_SSP) { a = sspf(a); b = sspf(b); }
            split_pack(a, b, hi[i], lo[i]);
        }
        uint32_t off = (uint32_t)row * RS + kg * 16;
        *(uint4*)(smem + hi_off + off) = make_uint4(hi[0], hi[1], hi[2], hi[3]);
        *(uint4*)(smem + lo_off + off) = make_uint4(lo[0], lo[1], lo[2], lo[3]);
    }
}

// one K=64 MMA pass over current A/W smem tiles (3-term hi/lo emulation)
__device__ __forceinline__ void mma_pass(float acc[4][4][4],
                                         const uint32_t aHiA[4],
                                         const uint32_t aLoA[4],
                                         const uint32_t bHiA[4],
                                         const uint32_t bLoA[4]) {
#pragma unroll
    for (int ks = 0; ks < 4; ks++) {
        const uint32_t koff = ks * 32;
        uint32_t af[4][4], bh[4][2], bl[4][2];
#pragma unroll
        for (int mi = 0; mi < 4; mi++) ldmx4(af[mi], aHiA[mi] + koff);
#pragma unroll
        for (int nj = 0; nj < 4; nj++) {
            ldmx2(bh[nj], bHiA[nj] + koff);
            ldmx2(bl[nj], bLoA[nj] + koff);
        }
#pragma unroll
        for (int mi = 0; mi < 4; mi++)
#pragma unroll
            for (int nj = 0; nj < 4; nj++) {
                mma16816(acc[mi][nj], af[mi], bh[nj]);
                mma16816(acc[mi][nj], af[mi], bl[nj]);
            }
#pragma unroll
        for (int mi = 0; mi < 4; mi++) ldmx4(af[mi], aLoA[mi] + koff);
#pragma unroll
        for (int mi = 0; mi < 4; mi++)
#pragma unroll
            for (int nj = 0; nj < 4; nj++)
                mma16816(acc[mi][nj], af[mi], bh[nj]);
    }
}

// ---------------------------------------------------------------------------
// HMMA node GEMM: out[n,c] = post( sum_k ssp(in[n,k]) * W[c,k] + bias[c] )
// ---------------------------------------------------------------------------
enum { OUT_SSP = 0, OUT_PLAIN = 1, OUT_ADD = 2, OUT_XU = 3 };

template <int MODE>
__global__ __launch_bounds__(256, 2)
void tc_gemm(const float* __restrict__ in, const float* __restrict__ W,
             const float* __restrict__ bias, float* __restrict__ out,
             const float* __restrict__ add, const float* __restrict__ u,
             int N)
{
    extern __shared__ char smem[];
    const uint32_t sbase = smem_u32(smem);
    const int t     = threadIdx.x;
    const int lane  = t & 31;
    const int w     = t >> 5;
    const int row0  = blockIdx.x * 128;
    const int nrows = min(128, N - row0);

    const int m_warp = (w >> 2) * 64;
    const int n_warp = (w & 3) * 32;

    const int a_row = m_warp + ((lane >> 3) & 1) * 8 + (lane & 7);
    const int a_kh  = (lane >> 4) * 16;
    uint32_t aHiA[4], aLoA[4];
#pragma unroll
    for (int mi = 0; mi < 4; mi++) {
        uint32_t off = (uint32_t)(a_row + 16 * mi) * RS + a_kh;
        aHiA[mi] = sbase + SM_AHI + off;
        aLoA[mi] = sbase + SM_ALO + off;
    }
    const int b_lane = lane & 15;
    const int b_rowl = b_lane & 7;
    const int b_kh   = ((b_lane >> 3) & 1) * 16;
    uint32_t bHiA[4], bLoA[4];
#pragma unroll
    for (int nj = 0; nj < 4; nj++) {
        uint32_t off = (uint32_t)(n_warp + 8 * nj + b_rowl) * RS + b_kh;
        bHiA[nj] = sbase + SM_WHI + off;
        bLoA[nj] = sbase + SM_WLO + off;
    }

    float acc[4][4][4];
#pragma unroll
    for (int mi = 0; mi < 4; mi++)
#pragma unroll
        for (int nj = 0; nj < 4; nj++)
#pragma unroll
            for (int q = 0; q < 4; q++) acc[mi][nj][q] = 0.0f;

#pragma unroll
    for (int kh = 0; kh < 2; kh++) {
        if (kh) __syncthreads();
        fill_half<true >(smem, SM_AHI, SM_ALO, in, 128, row0, nrows, kh, t);
        fill_half<false>(smem, SM_WHI, SM_WLO, W, 128, 0, 128, kh, t);
        __syncthreads();
        mma_pass(acc, aHiA, aLoA, bHiA, bLoA);
    }

    const int r_in  = lane >> 2;
    const int c_in  = (lane & 3) * 2;
#pragma unroll
    for (int mi = 0; mi < 4; mi++) {
#pragma unroll
        for (int half = 0; half < 2; half++) {
            const int row = m_warp + 16 * mi + half * 8 + r_in;
            if (row >= nrows) continue;
            const size_t grow = (size_t)(row0 + row) * 128;
#pragma unroll
            for (int nj = 0; nj < 4; nj++) {
                const int col = n_warp + 8 * nj + c_in;
                float2 o;
                o.x = acc[mi][nj][half * 2 + 0];
                o.y = acc[mi][nj][half * 2 + 1];
                float2 b2 = *(const float2*)(bias + col);
                o.x += b2.x; o.y += b2.y;
                if (MODE == OUT_SSP) {
                    o.x = sspf(o.x); o.y = sspf(o.y);
                } else if (MODE == OUT_ADD) {
                    float2 a2 = *(const float2*)(add + grow + col);
                    o.x += a2.x; o.y += a2.y;
                } else if (MODE == OUT_XU) {
                    float2 a2 = *(const float2*)(add + grow + col);
                    float2 u2 = *(const float2*)(u + col);
                    o.x += a2.x * u2.x; o.y += a2.y * u2.y;
                }
                *(float2*)(out + grow + col) = o;
            }
        }
    }
}

// ---------------------------------------------------------------------------
// Fused residual pair:
//   y  = ssp(t) @ W1^T + b1      (HMMA, y never leaves the CTA)
//   t' = t + ssp(y) @ W2^T + b2  (HMMA)
// smem: 6 buffers. Phase1: BUF0/1 = A1 hi/lo (per K-half), BUF2/3 = W1 hi/lo.
// Phase2: A2 = BUF0/1 (K-half 0) + BUF4/5 (K-half 1); W2 refills BUF2/3.
// ---------------------------------------------------------------------------
__global__ __launch_bounds__(256, 2)
void res_pair(const float* __restrict__ tin, float* __restrict__ tout,
              const float* __restrict__ W1, const float* __restrict__ b1,
              const float* __restrict__ W2, const float* __restrict__ b2,
              int N)
{
    extern __shared__ char smem[];
    const uint32_t sbase = smem_u32(smem);
    const int t     = threadIdx.x;
    const int lane  = t & 31;
    const int w     = t >> 5;
    const int row0  = blockIdx.x * 128;
    const int nrows = min(128, N - row0);

    const int m_warp = (w >> 2) * 64;
    const int n_warp = (w & 3) * 32;

    const int a_row = m_warp + ((lane >> 3) & 1) * 8 + (lane & 7);
    const int a_kh  = (lane >> 4) * 16;
    uint32_t aOff[4];
#pragma unroll
    for (int mi = 0; mi < 4; mi++)
        aOff[mi] = (uint32_t)(a_row + 16 * mi) * RS + a_kh;

    const int b_lane = lane & 15;
    const int b_rowl = b_lane & 7;
    const int b_kh   = ((b_lane >> 3) & 1) * 16;
    uint32_t bHiA[4], bLoA[4];
#pragma unroll
    for (int nj = 0; nj < 4; nj++) {
        uint32_t off = (uint32_t)(n_warp + 8 * nj + b_rowl) * RS + b_kh;
        bHiA[nj] = sbase + 2 * MAT_SZ + off;   // W hi = BUF2
        bLoA[nj] = sbase + 3 * MAT_SZ + off;   // W lo = BUF3
    }

    float acc[4][4][4];
#pragma unroll
    for (int mi = 0; mi < 4; mi++)
#pragma unroll
        for (int nj = 0; nj < 4; nj++)
#pragma unroll
            for (int q = 0; q < 4; q++) acc[mi][nj][q] = 0.0f;

    // ---- phase 1: acc = ssp(t) @ W1^T ----
    uint32_t aHiA[4], aLoA[4];
#pragma unroll
    for (int mi = 0; mi < 4; mi++) {
        aHiA[mi] = sbase + 0 * MAT_SZ + aOff[mi];   // BUF0
        aLoA[mi] = sbase + 1 * MAT_SZ + aOff[mi];   // BUF1
    }
#pragma unroll
    for (int kh = 0; kh < 2; kh++) {
        if (kh) __syncthreads();
        fill_half<true >(smem, 0 * MAT_SZ, 1 * MAT_SZ, tin, 128, row0, nrows, kh, t);
        fill_half<false>(smem, 2 * MAT_SZ, 3 * MAT_SZ, W1, 128, 0, 128, kh, t);
        __syncthreads();
        mma_pass(acc, aHiA, aLoA, bHiA, bLoA);
    }
    __syncthreads();   // all warps done with MMA1; BUF0/1 now reusable

    // ---- convert y -> A2 tiles (ssp(y) hi/lo) ----
    const int r_in = lane >> 2;
    const int c_in = (lane & 3) * 2;
    {
        // A2 buffer bases: kh0 hi=BUF0 lo=BUF1, kh1 hi=BUF4 lo=BUF5
        const int hiB[2] = {0 * MAT_SZ, 4 * MAT_SZ};
        const int loB[2] = {1 * MAT_SZ, 5 * MAT_SZ};
#pragma unroll
        for (int mi = 0; mi < 4; mi++)
#pragma unroll
            for (int half = 0; half < 2; half++) {
                const int row = m_warp + 16 * mi + half * 8 + r_in;
#pragma unroll
                for (int nj = 0; nj < 4; nj++) {
                    const int col = n_warp + 8 * nj + c_in;
                    float2 bb = *(const float2*)(b1 + col);
                    float a = sspf(acc[mi][nj][half * 2 + 0] + bb.x);
                    float b = sspf(acc[mi][nj][half * 2 + 1] + bb.y);
                    uint32_t hi, lo;
                    split_pack(a, b, hi, lo);
                    const int kh = col >> 6;
                    uint32_t off = (uint32_t)row * RS + (col & 63) * 2;
                    *(uint32_t*)(smem + hiB[kh] + off) = hi;
                    *(uint32_t*)(smem + loB[kh] + off) = lo;
                }
            }
    }

    // zero accumulators for phase 2
#pragma unroll
    for (int mi = 0; mi < 4; mi++)
#pragma unroll
        for (int nj = 0; nj < 4; nj++)
#pragma unroll
            for (int q = 0; q < 4; q++) acc[mi][nj][q] = 0.0f;

    // ---- phase 2: acc = ssp(y) @ W2^T ----
#pragma unroll
    for (int kh = 0; kh < 2; kh++) {
        __syncthreads();   // kh0: conversion done; kh1: W2 kh0 consumed
        fill_half<false>(smem, 2 * MAT_SZ, 3 * MAT_SZ, W2, 128, 0, 128, kh, t);
        __syncthreads();
        uint32_t a2Hi[4], a2Lo[4];
        const int hiB = kh ? 4 * MAT_SZ : 0 * MAT_SZ;
        const int loB = kh ? 5 * MAT_SZ : 1 * MAT_SZ;
#pragma unroll
        for (int mi = 0; mi < 4; mi++) {
            a2Hi[mi] = sbase + hiB + aOff[mi];
            a2Lo[mi] = sbase + loB + aOff[mi];
        }
        mma_pass(acc, a2Hi, a2Lo, bHiA, bLoA);
    }

    // ---- epilogue: t' = t + acc + b2 ----
#pragma unroll
    for (int mi = 0; mi < 4; mi++)
#pragma unroll
        for (int half = 0; half < 2; half++) {
            const int row = m_warp + 16 * mi + half * 8 + r_in;
            if (row >= nrows) continue;
            const size_t grow = (size_t)(row0 + row) * 128;
#pragma unroll
            for (int nj = 0; nj < 4; nj++) {
                const int col = n_warp + 8 * nj + c_in;
                float2 bb = *(const float2*)(b2 + col);
                float2 tv = *(const float2*)(tin + grow + col);
                float2 o;
                o.x = acc[mi][nj][half * 2 + 0] + bb.x + tv.x;
                o.y = acc[mi][nj][half * 2 + 1] + bb.y + tv.y;
                *(float2*)(tout + grow + col) = o;
            }
        }
}

// ---------------------------------------------------------------------------
// HMMA edge kernel: 128 edges/block.
//   gate[128,128] = edge_attr[128,64] @ G_w^T, stage through smem,
//   msg = gate * t_diff[src], red.global.add.v4 into aggr[dst].
// ---------------------------------------------------------------------------
constexpr int GSTR = 136;

__global__ __launch_bounds__(256, 2)
void edge_kernel(const void* __restrict__ idx_raw,
                 const float* __restrict__ ea,
                 const float* __restrict__ Gw,
                 const float* __restrict__ tdiff,
                 float* __restrict__ aggr,
                 int E)
{
    extern __shared__ char smem[];
    const uint32_t sbase = smem_u32(smem);
    float* gsm = (float*)smem;

    const int t    = threadIdx.x;
    const int lane = t & 31;
    const int w    = t >> 5;
    const int e0   = blockIdx.x * 128;
    const int nrows = min(128, E - e0);

    const int m_warp = (w >> 2) * 64;
    const int n_warp = (w & 3) * 32;

    fill_half<false>(smem, SM_AHI, SM_ALO, ea, 64, e0, nrows, 0, t);
    fill_half<false>(smem, SM_WHI, SM_WLO, Gw, 64, 0, 128, 0, t);
    __syncthreads();

    const int a_row = m_warp + ((lane >> 3) & 1) * 8 + (lane & 7);
    const int a_kh  = (lane >> 4) * 16;
    uint32_t aHiA[4], aLoA[4];
#pragma unroll
    for (int mi = 0; mi < 4; mi++) {
        uint32_t off = (uint32_t)(a_row + 16 * mi) * RS + a_kh;
        aHiA[mi] = sbase + SM_AHI + off;
        aLoA[mi] = sbase + SM_ALO + off;
    }
    const int b_lane = lane & 15;
    const int b_rowl = b_lane & 7;
    const int b_kh   = ((b_lane >> 3) & 1) * 16;
    uint32_t bHiA[4], bLoA[4];
#pragma unroll
    for (int nj = 0; nj < 4; nj++) {
        uint32_t off = (uint32_t)(n_warp + 8 * nj + b_rowl) * RS + b_kh;
        bHiA[nj] = sbase + SM_WHI + off;
        bLoA[nj] = sbase + SM_WLO + off;
    }

    float acc[4][4][4];
#pragma unroll
    for (int mi = 0; mi < 4; mi++)
#pragma unroll
        for (int nj = 0; nj < 4; nj++)
#pragma unroll
            for (int q = 0; q < 4; q++) acc[mi][nj][q] = 0.0f;

    mma_pass(acc, aHiA, aLoA, bHiA, bLoA);

    __syncthreads();

    const int r_in = lane >> 2;
    const int c_in = (lane & 3) * 2;
#pragma unroll
    for (int mi = 0; mi < 4; mi++)
#pragma unroll
        for (int half = 0; half < 2; half++) {
            const int row = m_warp + 16 * mi + half * 8 + r_in;
#pragma unroll
            for (int nj = 0; nj < 4; nj++) {
                const int col = n_warp + 8 * nj + c_in;
                float2 o;
                o.x = acc[mi][nj][half * 2 + 0];
                o.y = acc[mi][nj][half * 2 + 1];
                *(float2*)(gsm + (size_t)row * GSTR + col) = o;
            }
        }
    __syncthreads();

    const bool idx64 = (*(volatile unsigned*)&g_or) == 0u;
    const long long* ll = (const long long*)idx_raw;
    const int*       ii = (const int*)idx_raw;

#pragma unroll 4
    for (int el = w * 16; el < w * 16 + 16; el++) {
        int e = e0 + el;
        if (e >= E) break;
        long long s, d;
        if (idx64) { s = ll[e]; d = ll[E + e]; }
        else       { s = ii[e]; d = ii[E + e]; }

        float4 g4 = *(const float4*)(gsm + (size_t)el * GSTR + lane * 4);
        float4 t4 = *(const float4*)(tdiff + (size_t)s * 128 + lane * 4);
        float4 m;
        m.x = g4.x * t4.x; m.y = g4.y * t4.y;
        m.z = g4.z * t4.z; m.w = g4.w * t4.w;

        float* p = aggr + (size_t)d * 128 + lane * 4;
        asm volatile("red.global.add.v4.f32 [%0], {%1, %2, %3, %4};"
                     :: "l"(p), "f"(m.x), "f"(m.y), "f"(m.z), "f"(m.w)
                     : "memory");
    }
}

// ---------------------------------------------------------------------------
// launch
// ---------------------------------------------------------------------------
extern "C" void kernel_launch(void* const* d_in, const int* in_sizes, int n_in,
                              void* d_out, int out_size)
{
    const float* x     = (const float*)d_in[0];
    const void*  ei    = d_in[1];
    const float* ea    = (const float*)d_in[2];
    const float* Wsame = (const float*)d_in[3];
    const float* bsame = (const float*)d_in[4];
    const float* Wdiff = (const float*)d_in[5];
    const float* bdiff = (const float*)d_in[6];
    const float* Gw    = (const float*)d_in[7];
    const float* rW1   = (const float*)d_in[8];
    const float* rb1   = (const float*)d_in[9];
    const float* rW2   = (const float*)d_in[10];
    const float* rb2   = (const float*)d_in[11];
    const float* Wlast = (const float*)d_in[12];
    const float* blast = (const float*)d_in[13];
    const float* u     = (const float*)d_in[14];

    const int N = in_sizes[0] / 128;
    const int E = in_sizes[2] / 64;
    const int R = in_sizes[8] / (128 * 128);

    float* out1  = (float*)d_out;
    float* msged = (float*)d_out + (size_t)N * 128;

    float *tdiff_p, *t_p;
    cudaGetSymbolAddress((void**)&tdiff_p, g_tdiff);
    cudaGetSymbolAddress((void**)&t_p, g_t);

    const int nblk = (N + 127) / 128;
    const int eblk = (E + 127) / 128;

    cudaFuncSetAttribute(tc_gemm<OUT_SSP>,
                         cudaFuncAttributeMaxDynamicSharedMemorySize, SM_TOTAL);
    cudaFuncSetAttribute(tc_gemm<OUT_XU>,
                         cudaFuncAttributeMaxDynamicSharedMemorySize, SM_TOTAL);
    cudaFuncSetAttribute(edge_kernel,
                         cudaFuncAttributeMaxDynamicSharedMemorySize, SM_TOTAL);
    cudaFuncSetAttribute(res_pair,
                         cudaFuncAttributeMaxDynamicSharedMemorySize, SM_TOTAL6);

    // index dtype detection (deterministic, re-run every replay)
    reset_or_kernel<<<1, 1>>>();
    scan_odd_kernel<<<256, 256>>>((const unsigned*)ei, E);

    // t_same -> msged (initializes output #2 region each replay)
    tc_gemm<OUT_SSP><<<nblk, 256, SM_TOTAL>>>(x, Wsame, bsame, msged,
                                              nullptr, nullptr, N);
    // t_diff
    tc_gemm<OUT_SSP><<<nblk, 256, SM_TOTAL>>>(x, Wdiff, bdiff, tdiff_p,
                                              nullptr, nullptr, N);

    // edge gate + message + scatter-add into msged
    edge_kernel<<<eblk, 256, SM_TOTAL>>>(ei, ea, Gw, tdiff_p, msged, E);

    // fused residual stack: layer 0 msged -> t_p, layers 1.. in place
    const float* tin = msged;
    float* tout = t_p;
    for (int i = 0; i < R; i++) {
        res_pair<<<nblk, 256, SM_TOTAL6>>>(tin, tout,
                                           rW1 + (size_t)i * 128 * 128,
                                           rb1 + (size_t)i * 128,
                                           rW2 + (size_t)i * 128 * 128,
                                           rb2 + (size_t)i * 128, N);
        tin = tout;   // in-place from layer 1 on (row-local, safe)
    }

    // final: out1 = ssp(t)@W_last^T + b_last + x*u
    tc_gemm<OUT_XU><<<nblk, 256, SM_TOTAL>>>(tin, Wlast, blast, out1, x, u, N);
}

// round 8
// speedup vs baseline: 1.7851x; 1.0646x over previous
#include <cuda_runtime.h>
#include <cuda_bf16.h>
#include <cstdint>

// ---------------------------------------------------------------------------
// InteractionModule (PhysNet message passing + residual stack)
// All GEMMs on HMMA mma.sync m16n8k16 bf16, hi/lo split 3-term emulation.
// 5 launches total: detect x2, tc_dual, edge_kernel, res_chain.
// ---------------------------------------------------------------------------

#define SSP_LOG2 0.69314718055994530942f

__device__ __forceinline__ float sspf(float x) {
    return fmaxf(x, 0.0f) + __logf(1.0f + __expf(-fabsf(x))) - SSP_LOG2;
}

constexpr int FD   = 128;
constexpr int NMAX = 50176;

__device__ float    g_tdiff[NMAX * FD];
__device__ float    g_t[NMAX * FD];
__device__ unsigned g_or;

// ---------------------------------------------------------------------------
// edge_index dtype detection: odd 32-bit words all zero <=> int64
// ---------------------------------------------------------------------------
__global__ void reset_or_kernel() { g_or = 0u; }
__global__ void scan_odd_kernel(const unsigned* __restrict__ w, int E) {
    unsigned v = 0;
    for (int i = blockIdx.x * blockDim.x + threadIdx.x; i < E;
         i += gridDim.x * blockDim.x)
        v |= w[2 * i + 1];
    v = __reduce_or_sync(0xffffffffu, v);
    if ((threadIdx.x & 31) == 0 && v) atomicOr(&g_or, 1u);
}

// ---------------------------------------------------------------------------
// warp MMA helpers (generic PTX, sm_80+)
// ---------------------------------------------------------------------------
__device__ __forceinline__ uint32_t smem_u32(const void* p) {
    uint32_t a;
    asm("{ .reg .u64 t; cvta.to.shared.u64 t, %1; cvt.u32.u64 %0, t; }"
        : "=r"(a) : "l"(p));
    return a;
}
__device__ __forceinline__ void ldmx4(uint32_t* r, uint32_t addr) {
    asm volatile("ldmatrix.sync.aligned.m8n8.x4.shared.b16 {%0,%1,%2,%3}, [%4];"
                 : "=r"(r[0]), "=r"(r[1]), "=r"(r[2]), "=r"(r[3]) : "r"(addr));
}
__device__ __forceinline__ void ldmx2(uint32_t* r, uint32_t addr) {
    asm volatile("ldmatrix.sync.aligned.m8n8.x2.shared.b16 {%0,%1}, [%2];"
                 : "=r"(r[0]), "=r"(r[1]) : "r"(addr));
}
__device__ __forceinline__ void mma16816(float* d, const uint32_t* a,
                                         const uint32_t* b) {
    asm volatile("mma.sync.aligned.m16n8k16.row.col.f32.bf16.bf16.f32 "
                 "{%0,%1,%2,%3}, {%4,%5,%6,%7}, {%8,%9}, {%0,%1,%2,%3};"
                 : "+f"(d[0]), "+f"(d[1]), "+f"(d[2]), "+f"(d[3])
                 : "r"(a[0]), "r"(a[1]), "r"(a[2]), "r"(a[3]),
                   "r"(b[0]), "r"(b[1]));
}

constexpr int RS      = 144;               // row stride bytes (9 x 16B)
constexpr int MAT_SZ  = 128 * RS;          // 18432 B per [128 x 64] bf16 tile
constexpr int SM_TOTAL  = 4 * MAT_SZ;      // edge kernel: 73728 B
constexpr int SM_TOTAL6 = 6 * MAT_SZ;      // dual / chain: 110592 B
// buffer roles (6-buf kernels): A kh0 hi/lo = BUF0/1, W hi/lo = BUF2/3,
// A kh1 hi/lo = BUF4/5.

__device__ __forceinline__ void split_pack(float a, float b,
                                           uint32_t& hi, uint32_t& lo) {
    __nv_bfloat16 ah = __float2bfloat16(a);
    __nv_bfloat16 bh = __float2bfloat16(b);
    __nv_bfloat16 al = __float2bfloat16(a - __bfloat162float(ah));
    __nv_bfloat16 bl = __float2bfloat16(b - __bfloat162float(bh));
    hi = ((uint32_t)*(uint16_t*)&bh << 16) | *(uint16_t*)&ah;
    lo = ((uint32_t)*(uint16_t*)&bl << 16) | *(uint16_t*)&al;
}

// fill a [128 x 64] fp32 sub-tile (col offset kh*64, row stride src_ld)
// into hi/lo bf16 smem tiles (row stride RS bytes)
template <bool DO_SSP>
__device__ __forceinline__ void fill_half(char* smem, int hi_off, int lo_off,
                                          const float* __restrict__ src,
                                          int src_ld, int row0, int nrows,
                                          int kh, int t) {
    const int kg = t & 7;
    const int r0 = t >> 3;
#pragma unroll
    for (int p = 0; p < 4; p++) {
        int row = r0 + p * 32;
        float v[8];
        if (row < nrows) {
            const float* rp = src + (size_t)(row0 + row) * src_ld + kh * 64 + kg * 8;
            float4 va = *(const float4*)(rp);
            float4 vb = *(const float4*)(rp + 4);
            v[0] = va.x; v[1] = va.y; v[2] = va.z; v[3] = va.w;
            v[4] = vb.x; v[5] = vb.y; v[6] = vb.z; v[7] = vb.w;
        } else {
#pragma unroll
            for (int i = 0; i < 8; i++) v[i] = 0.0f;
        }
        uint32_t hi[4], lo[4];
#pragma unroll
        for (int i = 0; i < 4; i++) {
            float a = v[2 * i], b = v[2 * i + 1];
            if (DO_SSP) { a = sspf(a); b = sspf(b); }
            split_pack(a, b, hi[i], lo[i]);
        }
        uint32_t off = (uint32_t)row * RS + kg * 16;
        *(uint4*)(smem + hi_off + off) = make_uint4(hi[0], hi[1], hi[2], hi[3]);
        *(uint4*)(smem + lo_off + off) = make_uint4(lo[0], lo[1], lo[2], lo[3]);
    }
}

// one K=64 MMA pass (3-term hi/lo emulation)
__device__ __forceinline__ void mma_pass(float acc[4][4][4],
                                         const uint32_t aHiA[4],
                                         const uint32_t aLoA[4],
                                         const uint32_t bHiA[4],
                                         const uint32_t bLoA[4]) {
#pragma unroll
    for (int ks = 0; ks < 4; ks++) {
        const uint32_t koff = ks * 32;
        uint32_t af[4][4], bh[4][2], bl[4][2];
#pragma unroll
        for (int mi = 0; mi < 4; mi++) ldmx4(af[mi], aHiA[mi] + koff);
#pragma unroll
        for (int nj = 0; nj < 4; nj++) {
            ldmx2(bh[nj], bHiA[nj] + koff);
            ldmx2(bl[nj], bLoA[nj] + koff);
        }
#pragma unroll
        for (int mi = 0; mi < 4; mi++)
#pragma unroll
            for (int nj = 0; nj < 4; nj++) {
                mma16816(acc[mi][nj], af[mi], bh[nj]);
                mma16816(acc[mi][nj], af[mi], bl[nj]);
            }
#pragma unroll
        for (int mi = 0; mi < 4; mi++) ldmx4(af[mi], aLoA[mi] + koff);
#pragma unroll
        for (int mi = 0; mi < 4; mi++)
#pragma unroll
            for (int nj = 0; nj < 4; nj++)
                mma16816(acc[mi][nj], af[mi], bh[nj]);
    }
}

#define ZERO_ACC(acc) do {                                                    \
    _Pragma("unroll") for (int mi = 0; mi < 4; mi++)                          \
    _Pragma("unroll") for (int nj = 0; nj < 4; nj++)                          \
    _Pragma("unroll") for (int q = 0; q < 4; q++) (acc)[mi][nj][q] = 0.0f;    \
} while (0)

// common per-thread tile coordinates
struct TileIds {
    int lane, w, m_warp, n_warp, r_in, c_in;
    uint32_t aOff[4];       // A ldmatrix offsets (relative to buffer base)
    uint32_t bOff[4];       // W ldmatrix offsets
};
__device__ __forceinline__ TileIds make_ids(int t) {
    TileIds id;
    id.lane  = t & 31;
    id.w     = t >> 5;
    id.m_warp = (id.w >> 2) * 64;
    id.n_warp = (id.w & 3) * 32;
    id.r_in  = id.lane >> 2;
    id.c_in  = (id.lane & 3) * 2;
    const int a_row = id.m_warp + ((id.lane >> 3) & 1) * 8 + (id.lane & 7);
    const int a_kh  = (id.lane >> 4) * 16;
#pragma unroll
    for (int mi = 0; mi < 4; mi++)
        id.aOff[mi] = (uint32_t)(a_row + 16 * mi) * RS + a_kh;
    const int b_lane = id.lane & 15;
    const int b_rowl = b_lane & 7;
    const int b_kh   = ((b_lane >> 3) & 1) * 16;
#pragma unroll
    for (int nj = 0; nj < 4; nj++)
        id.bOff[nj] = (uint32_t)(id.n_warp + 8 * nj + b_rowl) * RS + b_kh;
    return id;
}

// ---------------------------------------------------------------------------
// tc_dual: A = ssp(x) filled once; two GEMMs (W_same -> msged, W_diff -> tdiff),
// both epilogues apply ssp. A resident in BUF0/1 (kh0) + BUF4/5 (kh1).
// ---------------------------------------------------------------------------
__global__ __launch_bounds__(256, 2)
void tc_dual(const float* __restrict__ x,
             const float* __restrict__ Wsame, const float* __restrict__ bsame,
             const float* __restrict__ Wdiff, const float* __restrict__ bdiff,
             float* __restrict__ msged, float* __restrict__ tdiff, int N)
{
    extern __shared__ char smem[];
    const uint32_t sbase = smem_u32(smem);
    const int t     = threadIdx.x;
    const int row0  = blockIdx.x * 128;
    const int nrows = min(128, N - row0);
    TileIds id = make_ids(t);

    uint32_t aHi[2][4], aLo[2][4], bHi[4], bLo[4];
#pragma unroll
    for (int mi = 0; mi < 4; mi++) {
        aHi[0][mi] = sbase + 0 * MAT_SZ + id.aOff[mi];
        aLo[0][mi] = sbase + 1 * MAT_SZ + id.aOff[mi];
        aHi[1][mi] = sbase + 4 * MAT_SZ + id.aOff[mi];
        aLo[1][mi] = sbase + 5 * MAT_SZ + id.aOff[mi];
    }
#pragma unroll
    for (int nj = 0; nj < 4; nj++) {
        bHi[nj] = sbase + 2 * MAT_SZ + id.bOff[nj];
        bLo[nj] = sbase + 3 * MAT_SZ + id.bOff[nj];
    }

    // A = ssp(x), both K-halves
    fill_half<true>(smem, 0 * MAT_SZ, 1 * MAT_SZ, x, 128, row0, nrows, 0, t);
    fill_half<true>(smem, 4 * MAT_SZ, 5 * MAT_SZ, x, 128, row0, nrows, 1, t);

    float acc[4][4][4];
    const float* Wp[2] = {Wsame, Wdiff};
    const float* bp[2] = {bsame, bdiff};
    float*       op[2] = {msged, tdiff};

#pragma unroll
    for (int g = 0; g < 2; g++) {
        ZERO_ACC(acc);
#pragma unroll
        for (int kh = 0; kh < 2; kh++) {
            __syncthreads();
            fill_half<false>(smem, 2 * MAT_SZ, 3 * MAT_SZ, Wp[g], 128, 0, 128, kh, t);
            __syncthreads();
            mma_pass(acc, aHi[kh], aLo[kh], bHi, bLo);
        }
        // epilogue: ssp(acc + bias) -> out
#pragma unroll
        for (int mi = 0; mi < 4; mi++)
#pragma unroll
            for (int half = 0; half < 2; half++) {
                const int row = id.m_warp + 16 * mi + half * 8 + id.r_in;
                if (row >= nrows) continue;
                const size_t grow = (size_t)(row0 + row) * 128;
#pragma unroll
                for (int nj = 0; nj < 4; nj++) {
                    const int col = id.n_warp + 8 * nj + id.c_in;
                    float2 bb = *(const float2*)(bp[g] + col);
                    float2 o;
                    o.x = sspf(acc[mi][nj][half * 2 + 0] + bb.x);
                    o.y = sspf(acc[mi][nj][half * 2 + 1] + bb.y);
                    *(float2*)(op[g] + grow + col) = o;
                }
            }
    }
}

// ---------------------------------------------------------------------------
// res_chain: R fused residual layers + final GEMM, one kernel.
//   per layer: y = ssp(t)@W1^T+b1 ; t' = t + ssp(y)@W2^T+b2
//   t' fragments convert directly into next layer's A tiles (smem);
//   t' goes to global only as next layer's fp32 addend (skipped on last layer).
//   final: out1 = ssp(t)@Wlast^T + blast + x*u
// ---------------------------------------------------------------------------
__global__ __launch_bounds__(256, 2)
void res_chain(const float* __restrict__ msged, float* __restrict__ tbuf,
               const float* __restrict__ rW1, const float* __restrict__ rb1,
               const float* __restrict__ rW2, const float* __restrict__ rb2,
               const float* __restrict__ Wlast, const float* __restrict__ blast,
               const float* __restrict__ x, const float* __restrict__ u,
               float* __restrict__ out1, int N, int R)
{
    extern __shared__ char smem[];
    const uint32_t sbase = smem_u32(smem);
    const int t     = threadIdx.x;
    const int row0  = blockIdx.x * 128;
    const int nrows = min(128, N - row0);
    TileIds id = make_ids(t);

    uint32_t aHi[2][4], aLo[2][4], bHi[4], bLo[4];
#pragma unroll
    for (int mi = 0; mi < 4; mi++) {
        aHi[0][mi] = sbase + 0 * MAT_SZ + id.aOff[mi];
        aLo[0][mi] = sbase + 1 * MAT_SZ + id.aOff[mi];
        aHi[1][mi] = sbase + 4 * MAT_SZ + id.aOff[mi];
        aLo[1][mi] = sbase + 5 * MAT_SZ + id.aOff[mi];
    }
#pragma unroll
    for (int nj = 0; nj < 4; nj++) {
        bHi[nj] = sbase + 2 * MAT_SZ + id.bOff[nj];
        bLo[nj] = sbase + 3 * MAT_SZ + id.bOff[nj];
    }
    const int hiB[2] = {0 * MAT_SZ, 4 * MAT_SZ};
    const int loB[2] = {1 * MAT_SZ, 5 * MAT_SZ};

    // initial A = ssp(msged)
    fill_half<true>(smem, hiB[0], loB[0], msged, 128, row0, nrows, 0, t);
    fill_half<true>(smem, hiB[1], loB[1], msged, 128, row0, nrows, 1, t);

    const float* tin = msged;
    float acc[4][4][4];

    for (int i = 0; i < R; i++) {
        const float* W1 = rW1 + (size_t)i * 128 * 128;
        const float* b1 = rb1 + (size_t)i * 128;
        const float* W2 = rW2 + (size_t)i * 128 * 128;
        const float* b2 = rb2 + (size_t)i * 128;

        // phase 1: acc = ssp(t) @ W1^T
        ZERO_ACC(acc);
#pragma unroll
        for (int kh = 0; kh < 2; kh++) {
            __syncthreads();
            fill_half<false>(smem, 2 * MAT_SZ, 3 * MAT_SZ, W1, 128, 0, 128, kh, t);
            __syncthreads();
            mma_pass(acc, aHi[kh], aLo[kh], bHi, bLo);
        }
        __syncthreads();   // A tiles dead

        // convert y = ssp(acc + b1) -> A tiles
#pragma unroll
        for (int mi = 0; mi < 4; mi++)
#pragma unroll
            for (int half = 0; half < 2; half++) {
                const int row = id.m_warp + 16 * mi + half * 8 + id.r_in;
#pragma unroll
                for (int nj = 0; nj < 4; nj++) {
                    const int col = id.n_warp + 8 * nj + id.c_in;
                    float2 bb = *(const float2*)(b1 + col);
                    float a = sspf(acc[mi][nj][half * 2 + 0] + bb.x);
                    float b = sspf(acc[mi][nj][half * 2 + 1] + bb.y);
                    uint32_t hi, lo;
                    split_pack(a, b, hi, lo);
                    const int kh = col >> 6;
                    uint32_t off = (uint32_t)row * RS + (col & 63) * 2;
                    *(uint32_t*)(smem + hiB[kh] + off) = hi;
                    *(uint32_t*)(smem + loB[kh] + off) = lo;
                }
            }

        // phase 2: acc = ssp(y) @ W2^T
        ZERO_ACC(acc);
#pragma unroll
        for (int kh = 0; kh < 2; kh++) {
            __syncthreads();
            fill_half<false>(smem, 2 * MAT_SZ, 3 * MAT_SZ, W2, 128, 0, 128, kh, t);
            __syncthreads();
            mma_pass(acc, aHi[kh], aLo[kh], bHi, bLo);
        }
        __syncthreads();   // y tiles dead

        // t' = t + acc + b2 : write to global (addend for next layer, unless
        // last layer), convert ssp(t') into A tiles for the next GEMM
        const bool wr = (i < R - 1);
#pragma unroll
        for (int mi = 0; mi < 4; mi++)
#pragma unroll
            for (int half = 0; half < 2; half++) {
                const int row = id.m_warp + 16 * mi + half * 8 + id.r_in;
                const bool ok = row < nrows;
                const size_t grow = (size_t)(row0 + row) * 128;
#pragma unroll
                for (int nj = 0; nj < 4; nj++) {
                    const int col = id.n_warp + 8 * nj + id.c_in;
                    float2 bb = *(const float2*)(b2 + col);
                    float2 tv = ok ? *(const float2*)(tin + grow + col)
                                   : make_float2(0.f, 0.f);
                    float ox = acc[mi][nj][half * 2 + 0] + bb.x + tv.x;
                    float oy = acc[mi][nj][half * 2 + 1] + bb.y + tv.y;
                    if (wr && ok) *(float2*)(tbuf + grow + col) = make_float2(ox, oy);
                    uint32_t hi, lo;
                    split_pack(sspf(ox), sspf(oy), hi, lo);
                    const int kh = col >> 6;
                    uint32_t off = (uint32_t)row * RS + (col & 63) * 2;
                    *(uint32_t*)(smem + hiB[kh] + off) = hi;
                    *(uint32_t*)(smem + loB[kh] + off) = lo;
                }
            }
        tin = tbuf;
    }

    // final: out1 = ssp(t)@Wlast^T + blast + x*u
    ZERO_ACC(acc);
#pragma unroll
    for (int kh = 0; kh < 2; kh++) {
        __syncthreads();
        fill_half<false>(smem, 2 * MAT_SZ, 3 * MAT_SZ, Wlast, 128, 0, 128, kh, t);
        __syncthreads();
        mma_pass(acc, aHi[kh], aLo[kh], bHi, bLo);
    }
#pragma unroll
    for (int mi = 0; mi < 4; mi++)
#pragma unroll
        for (int half = 0; half < 2; half++) {
            const int row = id.m_warp + 16 * mi + half * 8 + id.r_in;
            if (row >= nrows) continue;
            const size_t grow = (size_t)(row0 + row) * 128;
#pragma unroll
            for (int nj = 0; nj < 4; nj++) {
                const int col = id.n_warp + 8 * nj + id.c_in;
                float2 bb = *(const float2*)(blast + col);
                float2 xv = *(const float2*)(x + grow + col);
                float2 uv = *(const float2*)(u + col);
                float2 o;
                o.x = acc[mi][nj][half * 2 + 0] + bb.x + xv.x * uv.x;
                o.y = acc[mi][nj][half * 2 + 1] + bb.y + xv.y * uv.y;
                *(float2*)(out1 + grow + col) = o;
            }
        }
}

// ---------------------------------------------------------------------------
// HMMA edge kernel: 128 edges/block.
//   gate[128,128] = edge_attr[128,64] @ G_w^T, stage through smem,
//   msg = gate * t_diff[src], red.global.add.v4 into aggr[dst].
//   (src,dst) prefetched into registers before the MMA, shfl-broadcast at use.
// ---------------------------------------------------------------------------
constexpr int GSTR = 136;

__global__ __launch_bounds__(256, 2)
void edge_kernel(const void* __restrict__ idx_raw,
                 const float* __restrict__ ea,
                 const float* __restrict__ Gw,
                 const float* __restrict__ tdiff,
                 float* __restrict__ aggr,
                 int E)
{
    extern __shared__ char smem[];
    const uint32_t sbase = smem_u32(smem);
    float* gsm = (float*)smem;

    const int t    = threadIdx.x;
    const int lane = t & 31;
    const int w    = t >> 5;
    const int e0   = blockIdx.x * 128;
    const int nrows = min(128, E - e0);
    TileIds id = make_ids(t);

    fill_half<false>(smem, 0 * MAT_SZ, 1 * MAT_SZ, ea, 64, e0, nrows, 0, t);
    fill_half<false>(smem, 2 * MAT_SZ, 3 * MAT_SZ, Gw, 64, 0, 128, 0, t);

    // prefetch this warp's 16 (src,dst) pairs; DRAM latency hides under MMA
    const bool idx64 = (*(volatile unsigned*)&g_or) == 0u;
    const long long* ll = (const long long*)idx_raw;
    const int*       ii = (const int*)idx_raw;
    long long sReg = 0, dReg = 0;
    if (lane < 16) {
        int e = e0 + w * 16 + lane;
        if (e < E) {
            if (idx64) { sReg = ll[e]; dReg = ll[E + e]; }
            else       { sReg = ii[e]; dReg = ii[E + e]; }
        }
    }
    __syncthreads();

    uint32_t aHiA[4], aLoA[4], bHiA[4], bLoA[4];
#pragma unroll
    for (int mi = 0; mi < 4; mi++) {
        aHiA[mi] = sbase + 0 * MAT_SZ + id.aOff[mi];
        aLoA[mi] = sbase + 1 * MAT_SZ + id.aOff[mi];
    }
#pragma unroll
    for (int nj = 0; nj < 4; nj++) {
        bHiA[nj] = sbase + 2 * MAT_SZ + id.bOff[nj];
        bLoA[nj] = sbase + 3 * MAT_SZ + id.bOff[nj];
    }

    float acc[4][4][4];
    ZERO_ACC(acc);
    mma_pass(acc, aHiA, aLoA, bHiA, bLoA);

    __syncthreads();   // tiles consumed; reuse smem for fp32 gate

#pragma unroll
    for (int mi = 0; mi < 4; mi++)
#pragma unroll
        for (int half = 0; half < 2; half++) {
            const int row = id.m_warp + 16 * mi + half * 8 + id.r_in;
#pragma unroll
            for (int nj = 0; nj < 4; nj++) {
                const int col = id.n_warp + 8 * nj + id.c_in;
                float2 o;
                o.x = acc[mi][nj][half * 2 + 0];
                o.y = acc[mi][nj][half * 2 + 1];
                *(float2*)(gsm + (size_t)row * GSTR + col) = o;
            }
        }
    __syncthreads();

    // scatter: warp w owns edges [w*16, w*16+16)
#pragma unroll 4
    for (int el = 0; el < 16; el++) {
        int e = e0 + w * 16 + el;
        if (e >= E) break;
        long long s = __shfl_sync(0xffffffffu, sReg, el);
        long long d = __shfl_sync(0xffffffffu, dReg, el);

        float4 g4 = *(const float4*)(gsm + (size_t)(w * 16 + el) * GSTR + lane * 4);
        float4 t4 = *(const float4*)(tdiff + (size_t)s * 128 + lane * 4);
        float4 m;
        m.x = g4.x * t4.x; m.y = g4.y * t4.y;
        m.z = g4.z * t4.z; m.w = g4.w * t4.w;

        float* p = aggr + (size_t)d * 128 + lane * 4;
        asm volatile("red.global.add.v4.f32 [%0], {%1, %2, %3, %4};"
                     :: "l"(p), "f"(m.x), "f"(m.y), "f"(m.z), "f"(m.w)
                     : "memory");
    }
}

// ---------------------------------------------------------------------------
// launch
// ---------------------------------------------------------------------------
extern "C" void kernel_launch(void* const* d_in, const int* in_sizes, int n_in,
                              void* d_out, int out_size)
{
    const float* x     = (const float*)d_in[0];
    const void*  ei    = d_in[1];
    const float* ea    = (const float*)d_in[2];
    const float* Wsame = (const float*)d_in[3];
    const float* bsame = (const float*)d_in[4];
    const float* Wdiff = (const float*)d_in[5];
    const float* bdiff = (const float*)d_in[6];
    const float* Gw    = (const float*)d_in[7];
    const float* rW1   = (const float*)d_in[8];
    const float* rb1   = (const float*)d_in[9];
    const float* rW2   = (const float*)d_in[10];
    const float* rb2   = (const float*)d_in[11];
    const float* Wlast = (const float*)d_in[12];
    const float* blast = (const float*)d_in[13];
    const float* u     = (const float*)d_in[14];

    const int N = in_sizes[0] / 128;
    const int E = in_sizes[2] / 64;
    const int R = in_sizes[8] / (128 * 128);

    float* out1  = (float*)d_out;
    float* msged = (float*)d_out + (size_t)N * 128;

    float *tdiff_p, *t_p;
    cudaGetSymbolAddress((void**)&tdiff_p, g_tdiff);
    cudaGetSymbolAddress((void**)&t_p, g_t);

    const int nblk = (N + 127) / 128;
    const int eblk = (E + 127) / 128;

    cudaFuncSetAttribute(tc_dual,
                         cudaFuncAttributeMaxDynamicSharedMemorySize, SM_TOTAL6);
    cudaFuncSetAttribute(res_chain,
                         cudaFuncAttributeMaxDynamicSharedMemorySize, SM_TOTAL6);
    cudaFuncSetAttribute(edge_kernel,
                         cudaFuncAttributeMaxDynamicSharedMemorySize, SM_TOTAL);

    // index dtype detection (deterministic, re-run every replay)
    reset_or_kernel<<<1, 1>>>();
    scan_odd_kernel<<<256, 256>>>((const unsigned*)ei, E);

    // t_same -> msged, t_diff -> g_tdiff (shared A fill)
    tc_dual<<<nblk, 256, SM_TOTAL6>>>(x, Wsame, bsame, Wdiff, bdiff,
                                      msged, tdiff_p, N);

    // edge gate + message + scatter-add into msged
    edge_kernel<<<eblk, 256, SM_TOTAL>>>(ei, ea, Gw, tdiff_p, msged, E);

    // residual stack + final GEMM, one kernel
    res_chain<<<nblk, 256, SM_TOTAL6>>>(msged, t_p, rW1, rb1, rW2, rb2,
                                        Wlast, blast, x, u, out1, N, R);
}

// round 9
// speedup vs baseline: 1.9278x; 1.0799x over previous
#include <cuda_runtime.h>
#include <cuda_bf16.h>
#include <cstdint>

// ---------------------------------------------------------------------------
// InteractionModule (PhysNet message passing + residual stack)
// All GEMMs on HMMA mma.sync m16n8k16 bf16, hi/lo split 3-term emulation.
// 5 launches: detect x2, tc_dual, edge_kernel, res_chain.
// ---------------------------------------------------------------------------

#define SSP_LOG2 0.69314718055994530942f

__device__ __forceinline__ float sspf(float x) {
    return fmaxf(x, 0.0f) + __logf(1.0f + __expf(-fabsf(x))) - SSP_LOG2;
}

constexpr int FD   = 128;
constexpr int NMAX = 50176;

__device__ float    g_tdiff[NMAX * FD];
__device__ float    g_t[NMAX * FD];
__device__ unsigned g_or;

// ---------------------------------------------------------------------------
// edge_index dtype detection: odd 32-bit words all zero <=> int64
// ---------------------------------------------------------------------------
__global__ void reset_or_kernel() { g_or = 0u; }
__global__ void scan_odd_kernel(const unsigned* __restrict__ w, int E) {
    unsigned v = 0;
    for (int i = blockIdx.x * blockDim.x + threadIdx.x; i < E;
         i += gridDim.x * blockDim.x)
        v |= w[2 * i + 1];
    v = __reduce_or_sync(0xffffffffu, v);
    if ((threadIdx.x & 31) == 0 && v) atomicOr(&g_or, 1u);
}

// ---------------------------------------------------------------------------
// warp MMA helpers (generic PTX, sm_80+)
// ---------------------------------------------------------------------------
__device__ __forceinline__ uint32_t smem_u32(const void* p) {
    uint32_t a;
    asm("{ .reg .u64 t; cvta.to.shared.u64 t, %1; cvt.u32.u64 %0, t; }"
        : "=r"(a) : "l"(p));
    return a;
}
__device__ __forceinline__ void ldmx4(uint32_t* r, uint32_t addr) {
    asm volatile("ldmatrix.sync.aligned.m8n8.x4.shared.b16 {%0,%1,%2,%3}, [%4];"
                 : "=r"(r[0]), "=r"(r[1]), "=r"(r[2]), "=r"(r[3]) : "r"(addr));
}
__device__ __forceinline__ void ldmx2(uint32_t* r, uint32_t addr) {
    asm volatile("ldmatrix.sync.aligned.m8n8.x2.shared.b16 {%0,%1}, [%2];"
                 : "=r"(r[0]), "=r"(r[1]) : "r"(addr));
}
__device__ __forceinline__ void mma16816(float* d, const uint32_t* a,
                                         const uint32_t* b) {
    asm volatile("mma.sync.aligned.m16n8k16.row.col.f32.bf16.bf16.f32 "
                 "{%0,%1,%2,%3}, {%4,%5,%6,%7}, {%8,%9}, {%0,%1,%2,%3};"
                 : "+f"(d[0]), "+f"(d[1]), "+f"(d[2]), "+f"(d[3])
                 : "r"(a[0]), "r"(a[1]), "r"(a[2]), "r"(a[3]),
                   "r"(b[0]), "r"(b[1]));
}

constexpr int RS      = 144;               // row stride bytes (9 x 16B)
constexpr int MAT_SZ  = 128 * RS;          // 18432 B per [128 x 64] bf16 tile
constexpr int SM_TOTAL6 = 6 * MAT_SZ;      // dual / chain: 110592 B

__device__ __forceinline__ void split_pack(float a, float b,
                                           uint32_t& hi, uint32_t& lo) {
    __nv_bfloat16 ah = __float2bfloat16(a);
    __nv_bfloat16 bh = __float2bfloat16(b);
    __nv_bfloat16 al = __float2bfloat16(a - __bfloat162float(ah));
    __nv_bfloat16 bl = __float2bfloat16(b - __bfloat162float(bh));
    hi = ((uint32_t)*(uint16_t*)&bh << 16) | *(uint16_t*)&ah;
    lo = ((uint32_t)*(uint16_t*)&bl << 16) | *(uint16_t*)&al;
}

// fill a [128 x 64] fp32 sub-tile (col offset kh*64, row stride src_ld)
// into hi/lo bf16 smem tiles (row stride RS bytes)
template <bool DO_SSP>
__device__ __forceinline__ void fill_half(char* smem, int hi_off, int lo_off,
                                          const float* __restrict__ src,
                                          int src_ld, int row0, int nrows,
                                          int kh, int t) {
    const int kg = t & 7;
    const int r0 = t >> 3;
#pragma unroll
    for (int p = 0; p < 4; p++) {
        int row = r0 + p * 32;
        float v[8];
        if (row < nrows) {
            const float* rp = src + (size_t)(row0 + row) * src_ld + kh * 64 + kg * 8;
            float4 va = *(const float4*)(rp);
            float4 vb = *(const float4*)(rp + 4);
            v[0] = va.x; v[1] = va.y; v[2] = va.z; v[3] = va.w;
            v[4] = vb.x; v[5] = vb.y; v[6] = vb.z; v[7] = vb.w;
        } else {
#pragma unroll
            for (int i = 0; i < 8; i++) v[i] = 0.0f;
        }
        uint32_t hi[4], lo[4];
#pragma unroll
        for (int i = 0; i < 4; i++) {
            float a = v[2 * i], b = v[2 * i + 1];
            if (DO_SSP) { a = sspf(a); b = sspf(b); }
            split_pack(a, b, hi[i], lo[i]);
        }
        uint32_t off = (uint32_t)row * RS + kg * 16;
        *(uint4*)(smem + hi_off + off) = make_uint4(hi[0], hi[1], hi[2], hi[3]);
        *(uint4*)(smem + lo_off + off) = make_uint4(lo[0], lo[1], lo[2], lo[3]);
    }
}

// fill a [64 x 64] fp32 tile (row stride src_ld) into hi/lo bf16 smem tiles
__device__ __forceinline__ void fill_64(char* smem, int hi_off, int lo_off,
                                        const float* __restrict__ src,
                                        int src_ld, int row0, int nrows, int t) {
    const int kg = t & 7;
    const int r0 = t >> 3;
#pragma unroll
    for (int p = 0; p < 2; p++) {
        int row = r0 + p * 32;
        float v[8];
        if (row < nrows) {
            const float* rp = src + (size_t)(row0 + row) * src_ld + kg * 8;
            float4 va = *(const float4*)(rp);
            float4 vb = *(const float4*)(rp + 4);
            v[0] = va.x; v[1] = va.y; v[2] = va.z; v[3] = va.w;
            v[4] = vb.x; v[5] = vb.y; v[6] = vb.z; v[7] = vb.w;
        } else {
#pragma unroll
            for (int i = 0; i < 8; i++) v[i] = 0.0f;
        }
        uint32_t hi[4], lo[4];
#pragma unroll
        for (int i = 0; i < 4; i++)
            split_pack(v[2 * i], v[2 * i + 1], hi[i], lo[i]);
        uint32_t off = (uint32_t)row * RS + kg * 16;
        *(uint4*)(smem + hi_off + off) = make_uint4(hi[0], hi[1], hi[2], hi[3]);
        *(uint4*)(smem + lo_off + off) = make_uint4(lo[0], lo[1], lo[2], lo[3]);
    }
}

// one K=64 MMA pass (3-term hi/lo emulation), M-tiles parametric
template <int MI>
__device__ __forceinline__ void mma_passM(float acc[MI][4][4],
                                          const uint32_t aHiA[MI],
                                          const uint32_t aLoA[MI],
                                          const uint32_t bHiA[4],
                                          const uint32_t bLoA[4]) {
#pragma unroll
    for (int ks = 0; ks < 4; ks++) {
        const uint32_t koff = ks * 32;
        uint32_t af[MI][4], bh[4][2], bl[4][2];
#pragma unroll
        for (int mi = 0; mi < MI; mi++) ldmx4(af[mi], aHiA[mi] + koff);
#pragma unroll
        for (int nj = 0; nj < 4; nj++) {
            ldmx2(bh[nj], bHiA[nj] + koff);
            ldmx2(bl[nj], bLoA[nj] + koff);
        }
#pragma unroll
        for (int mi = 0; mi < MI; mi++)
#pragma unroll
            for (int nj = 0; nj < 4; nj++) {
                mma16816(acc[mi][nj], af[mi], bh[nj]);
                mma16816(acc[mi][nj], af[mi], bl[nj]);
            }
#pragma unroll
        for (int mi = 0; mi < MI; mi++) ldmx4(af[mi], aLoA[mi] + koff);
#pragma unroll
        for (int mi = 0; mi < MI; mi++)
#pragma unroll
            for (int nj = 0; nj < 4; nj++)
                mma16816(acc[mi][nj], af[mi], bh[nj]);
    }
}

#define ZERO_ACC4(acc) do {                                                   \
    _Pragma("unroll") for (int mi = 0; mi < 4; mi++)                          \
    _Pragma("unroll") for (int nj = 0; nj < 4; nj++)                          \
    _Pragma("unroll") for (int q = 0; q < 4; q++) (acc)[mi][nj][q] = 0.0f;    \
} while (0)

struct TileIds {
    int lane, w, m_warp, n_warp, r_in, c_in;
    uint32_t aOff[4];
    uint32_t bOff[4];
};
__device__ __forceinline__ TileIds make_ids(int t) {
    TileIds id;
    id.lane  = t & 31;
    id.w     = t >> 5;
    id.m_warp = (id.w >> 2) * 64;
    id.n_warp = (id.w & 3) * 32;
    id.r_in  = id.lane >> 2;
    id.c_in  = (id.lane & 3) * 2;
    const int a_row = id.m_warp + ((id.lane >> 3) & 1) * 8 + (id.lane & 7);
    const int a_kh  = (id.lane >> 4) * 16;
#pragma unroll
    for (int mi = 0; mi < 4; mi++)
        id.aOff[mi] = (uint32_t)(a_row + 16 * mi) * RS + a_kh;
    const int b_lane = id.lane & 15;
    const int b_rowl = b_lane & 7;
    const int b_kh   = ((b_lane >> 3) & 1) * 16;
#pragma unroll
    for (int nj = 0; nj < 4; nj++)
        id.bOff[nj] = (uint32_t)(id.n_warp + 8 * nj + b_rowl) * RS + b_kh;
    return id;
}

// ---------------------------------------------------------------------------
// tc_dual: A = ssp(x) filled once; two GEMMs (W_same -> msged, W_diff -> tdiff)
// ---------------------------------------------------------------------------
__global__ __launch_bounds__(256, 2)
void tc_dual(const float* __restrict__ x,
             const float* __restrict__ Wsame, const float* __restrict__ bsame,
             const float* __restrict__ Wdiff, const float* __restrict__ bdiff,
             float* __restrict__ msged, float* __restrict__ tdiff, int N)
{
    extern __shared__ char smem[];
    const uint32_t sbase = smem_u32(smem);
    const int t     = threadIdx.x;
    const int row0  = blockIdx.x * 128;
    const int nrows = min(128, N - row0);
    TileIds id = make_ids(t);

    uint32_t aHi[2][4], aLo[2][4], bHi[4], bLo[4];
#pragma unroll
    for (int mi = 0; mi < 4; mi++) {
        aHi[0][mi] = sbase + 0 * MAT_SZ + id.aOff[mi];
        aLo[0][mi] = sbase + 1 * MAT_SZ + id.aOff[mi];
        aHi[1][mi] = sbase + 4 * MAT_SZ + id.aOff[mi];
        aLo[1][mi] = sbase + 5 * MAT_SZ + id.aOff[mi];
    }
#pragma unroll
    for (int nj = 0; nj < 4; nj++) {
        bHi[nj] = sbase + 2 * MAT_SZ + id.bOff[nj];
        bLo[nj] = sbase + 3 * MAT_SZ + id.bOff[nj];
    }

    fill_half<true>(smem, 0 * MAT_SZ, 1 * MAT_SZ, x, 128, row0, nrows, 0, t);
    fill_half<true>(smem, 4 * MAT_SZ, 5 * MAT_SZ, x, 128, row0, nrows, 1, t);

    float acc[4][4][4];
    const float* Wp[2] = {Wsame, Wdiff};
    const float* bp[2] = {bsame, bdiff};
    float*       op[2] = {msged, tdiff};

#pragma unroll
    for (int g = 0; g < 2; g++) {
        ZERO_ACC4(acc);
#pragma unroll
        for (int kh = 0; kh < 2; kh++) {
            __syncthreads();
            fill_half<false>(smem, 2 * MAT_SZ, 3 * MAT_SZ, Wp[g], 128, 0, 128, kh, t);
            __syncthreads();
            mma_passM<4>(acc, aHi[kh], aLo[kh], bHi, bLo);
        }
#pragma unroll
        for (int mi = 0; mi < 4; mi++)
#pragma unroll
            for (int half = 0; half < 2; half++) {
                const int row = id.m_warp + 16 * mi + half * 8 + id.r_in;
                if (row >= nrows) continue;
                const size_t grow = (size_t)(row0 + row) * 128;
#pragma unroll
                for (int nj = 0; nj < 4; nj++) {
                    const int col = id.n_warp + 8 * nj + id.c_in;
                    float2 bb = *(const float2*)(bp[g] + col);
                    float2 o;
                    o.x = sspf(acc[mi][nj][half * 2 + 0] + bb.x);
                    o.y = sspf(acc[mi][nj][half * 2 + 1] + bb.y);
                    *(float2*)(op[g] + grow + col) = o;
                }
            }
    }
}

// ---------------------------------------------------------------------------
// res_chain: R fused residual layers + final GEMM, one kernel.
// ---------------------------------------------------------------------------
__global__ __launch_bounds__(256, 2)
void res_chain(const float* __restrict__ msged, float* __restrict__ tbuf,
               const float* __restrict__ rW1, const float* __restrict__ rb1,
               const float* __restrict__ rW2, const float* __restrict__ rb2,
               const float* __restrict__ Wlast, const float* __restrict__ blast,
               const float* __restrict__ x, const float* __restrict__ u,
               float* __restrict__ out1, int N, int R)
{
    extern __shared__ char smem[];
    const uint32_t sbase = smem_u32(smem);
    const int t     = threadIdx.x;
    const int row0  = blockIdx.x * 128;
    const int nrows = min(128, N - row0);
    TileIds id = make_ids(t);

    uint32_t aHi[2][4], aLo[2][4], bHi[4], bLo[4];
#pragma unroll
    for (int mi = 0; mi < 4; mi++) {
        aHi[0][mi] = sbase + 0 * MAT_SZ + id.aOff[mi];
        aLo[0][mi] = sbase + 1 * MAT_SZ + id.aOff[mi];
        aHi[1][mi] = sbase + 4 * MAT_SZ + id.aOff[mi];
        aLo[1][mi] = sbase + 5 * MAT_SZ + id.aOff[mi];
    }
#pragma unroll
    for (int nj = 0; nj < 4; nj++) {
        bHi[nj] = sbase + 2 * MAT_SZ + id.bOff[nj];
        bLo[nj] = sbase + 3 * MAT_SZ + id.bOff[nj];
    }
    const int hiB[2] = {0 * MAT_SZ, 4 * MAT_SZ};
    const int loB[2] = {1 * MAT_SZ, 5 * MAT_SZ};

    fill_half<true>(smem, hiB[0], loB[0], msged, 128, row0, nrows, 0, t);
    fill_half<true>(smem, hiB[1], loB[1], msged, 128, row0, nrows, 1, t);

    const float* tin = msged;
    float acc[4][4][4];

    for (int i = 0; i < R; i++) {
        const float* W1 = rW1 + (size_t)i * 128 * 128;
        const float* b1 = rb1 + (size_t)i * 128;
        const float* W2 = rW2 + (size_t)i * 128 * 128;
        const float* b2 = rb2 + (size_t)i * 128;

        ZERO_ACC4(acc);
#pragma unroll
        for (int kh = 0; kh < 2; kh++) {
            __syncthreads();
            fill_half<false>(smem, 2 * MAT_SZ, 3 * MAT_SZ, W1, 128, 0, 128, kh, t);
            __syncthreads();
            mma_passM<4>(acc, aHi[kh], aLo[kh], bHi, bLo);
        }
        __syncthreads();

#pragma unroll
        for (int mi = 0; mi < 4; mi++)
#pragma unroll
            for (int half = 0; half < 2; half++) {
                const int row = id.m_warp + 16 * mi + half * 8 + id.r_in;
#pragma unroll
                for (int nj = 0; nj < 4; nj++) {
                    const int col = id.n_warp + 8 * nj + id.c_in;
                    float2 bb = *(const float2*)(b1 + col);
                    float a = sspf(acc[mi][nj][half * 2 + 0] + bb.x);
                    float b = sspf(acc[mi][nj][half * 2 + 1] + bb.y);
                    uint32_t hi, lo;
                    split_pack(a, b, hi, lo);
                    const int kh = col >> 6;
                    uint32_t off = (uint32_t)row * RS + (col & 63) * 2;
                    *(uint32_t*)(smem + hiB[kh] + off) = hi;
                    *(uint32_t*)(smem + loB[kh] + off) = lo;
                }
            }

        ZERO_ACC4(acc);
#pragma unroll
        for (int kh = 0; kh < 2; kh++) {
            __syncthreads();
            fill_half<false>(smem, 2 * MAT_SZ, 3 * MAT_SZ, W2, 128, 0, 128, kh, t);
            __syncthreads();
            mma_passM<4>(acc, aHi[kh], aLo[kh], bHi, bLo);
        }
        __syncthreads();

        const bool wr = (i < R - 1);
#pragma unroll
        for (int mi = 0; mi < 4; mi++)
#pragma unroll
            for (int half = 0; half < 2; half++) {
                const int row = id.m_warp + 16 * mi + half * 8 + id.r_in;
                const bool ok = row < nrows;
                const size_t grow = (size_t)(row0 + row) * 128;
#pragma unroll
                for (int nj = 0; nj < 4; nj++) {
                    const int col = id.n_warp + 8 * nj + id.c_in;
                    float2 bb = *(const float2*)(b2 + col);
                    float2 tv = ok ? *(const float2*)(tin + grow + col)
                                   : make_float2(0.f, 0.f);
                    float ox = acc[mi][nj][half * 2 + 0] + bb.x + tv.x;
                    float oy = acc[mi][nj][half * 2 + 1] + bb.y + tv.y;
                    if (wr && ok) *(float2*)(tbuf + grow + col) = make_float2(ox, oy);
                    uint32_t hi, lo;
                    split_pack(sspf(ox), sspf(oy), hi, lo);
                    const int kh = col >> 6;
                    uint32_t off = (uint32_t)row * RS + (col & 63) * 2;
                    *(uint32_t*)(smem + hiB[kh] + off) = hi;
                    *(uint32_t*)(smem + loB[kh] + off) = lo;
                }
            }
        tin = tbuf;
    }

    ZERO_ACC4(acc);
#pragma unroll
    for (int kh = 0; kh < 2; kh++) {
        __syncthreads();
        fill_half<false>(smem, 2 * MAT_SZ, 3 * MAT_SZ, Wlast, 128, 0, 128, kh, t);
        __syncthreads();
        mma_passM<4>(acc, aHi[kh], aLo[kh], bHi, bLo);
    }
#pragma unroll
    for (int mi = 0; mi < 4; mi++)
#pragma unroll
        for (int half = 0; half < 2; half++) {
            const int row = id.m_warp + 16 * mi + half * 8 + id.r_in;
            if (row >= nrows) continue;
            const size_t grow = (size_t)(row0 + row) * 128;
#pragma unroll
            for (int nj = 0; nj < 4; nj++) {
                const int col = id.n_warp + 8 * nj + id.c_in;
                float2 bb = *(const float2*)(blast + col);
                float2 xv = *(const float2*)(x + grow + col);
                float2 uv = *(const float2*)(u + col);
                float2 o;
                o.x = acc[mi][nj][half * 2 + 0] + bb.x + xv.x * uv.x;
                o.y = acc[mi][nj][half * 2 + 1] + bb.y + xv.y * uv.y;
                *(float2*)(out1 + grow + col) = o;
            }
        }
}

// ---------------------------------------------------------------------------
// edge_kernel v2: 64 edges/block, 3 CTAs/SM, batch-prefetched gathers.
//   gate[64,128] = edge_attr[64,64] @ G_w^T (HMMA), stage via smem,
//   msg = gate * t_diff[src], red.global.add.v4 into aggr[dst].
// smem: A hi/lo 64x144 x2 = 18432; W hi/lo 128x144 x2 = 36864; total 55296.
// ---------------------------------------------------------------------------
constexpr int EA_HI  = 0;
constexpr int EA_LO  = 64 * RS;            //  9216
constexpr int EW_HI  = 2 * 64 * RS;        // 18432
constexpr int EW_LO  = EW_HI + MAT_SZ;     // 36864
constexpr int ESM_TOT = EW_LO + MAT_SZ;    // 55296
constexpr int GSTR = 136;                  // gate rows: 64*136*4 = 34816 B

__global__ __launch_bounds__(256, 3)
void edge_kernel(const void* __restrict__ idx_raw,
                 const float* __restrict__ ea,
                 const float* __restrict__ Gw,
                 const float* __restrict__ tdiff,
                 float* __restrict__ aggr,
                 int E)
{
    extern __shared__ char smem[];
    const uint32_t sbase = smem_u32(smem);
    float* gsm = (float*)smem;

    const int t    = threadIdx.x;
    const int lane = t & 31;
    const int w    = t >> 5;
    const int e0   = blockIdx.x * 64;
    const int nrows = min(64, E - e0);

    // warp grid: 2 (m) x 4 (n); warp tile 32 x 32
    const int m_warp = (w >> 2) * 32;
    const int n_warp = (w & 3) * 32;

    fill_64(smem, EA_HI, EA_LO, ea, 64, e0, nrows, t);
    fill_half<false>(smem, EW_HI, EW_LO, Gw, 64, 0, 128, 0, t);

    // prefetch this warp's 8 (src,dst) pairs; latency hides under the MMA
    const bool idx64 = (*(volatile unsigned*)&g_or) == 0u;
    const long long* ll = (const long long*)idx_raw;
    const int*       ii = (const int*)idx_raw;
    long long sReg = 0, dReg = 0;
    if (lane < 8) {
        int e = e0 + w * 8 + lane;
        if (e < E) {
            if (idx64) { sReg = ll[e]; dReg = ll[E + e]; }
            else       { sReg = ii[e]; dReg = ii[E + e]; }
        }
    }
    __syncthreads();

    const int a_row = m_warp + ((lane >> 3) & 1) * 8 + (lane & 7);
    const int a_kh  = (lane >> 4) * 16;
    uint32_t aHiA[2], aLoA[2];
#pragma unroll
    for (int mi = 0; mi < 2; mi++) {
        uint32_t off = (uint32_t)(a_row + 16 * mi) * RS + a_kh;
        aHiA[mi] = sbase + EA_HI + off;
        aLoA[mi] = sbase + EA_LO + off;
    }
    const int b_lane = lane & 15;
    const int b_rowl = b_lane & 7;
    const int b_kh   = ((b_lane >> 3) & 1) * 16;
    uint32_t bHiA[4], bLoA[4];
#pragma unroll
    for (int nj = 0; nj < 4; nj++) {
        uint32_t off = (uint32_t)(n_warp + 8 * nj + b_rowl) * RS + b_kh;
        bHiA[nj] = sbase + EW_HI + off;
        bLoA[nj] = sbase + EW_LO + off;
    }

    float acc[2][4][4];
#pragma unroll
    for (int mi = 0; mi < 2; mi++)
#pragma unroll
        for (int nj = 0; nj < 4; nj++)
#pragma unroll
            for (int q = 0; q < 4; q++) acc[mi][nj][q] = 0.0f;

    mma_passM<2>(acc, aHiA, aLoA, bHiA, bLoA);

    __syncthreads();   // tiles consumed; reuse smem for fp32 gate

    const int r_in = lane >> 2;
    const int c_in = (lane & 3) * 2;
#pragma unroll
    for (int mi = 0; mi < 2; mi++)
#pragma unroll
        for (int half = 0; half < 2; half++) {
            const int row = m_warp + 16 * mi + half * 8 + r_in;
#pragma unroll
            for (int nj = 0; nj < 4; nj++) {
                const int col = n_warp + 8 * nj + c_in;
                float2 o;
                o.x = acc[mi][nj][half * 2 + 0];
                o.y = acc[mi][nj][half * 2 + 1];
                *(float2*)(gsm + (size_t)row * GSTR + col) = o;
            }
        }
    __syncthreads();

    // scatter: warp w owns edges [w*8, w*8+8). Batch-issue all 8 gathers
    // (MLP=8), then multiply + red.
    float4 t4[8];
#pragma unroll
    for (int el = 0; el < 8; el++) {
        long long s = __shfl_sync(0xffffffffu, sReg, el);
        t4[el] = *(const float4*)(tdiff + (size_t)s * 128 + lane * 4);
    }
#pragma unroll
    for (int el = 0; el < 8; el++) {
        int e = e0 + w * 8 + el;
        if (e >= E) break;
        long long d = __shfl_sync(0xffffffffu, dReg, el);
        float4 g4 = *(const float4*)(gsm + (size_t)(w * 8 + el) * GSTR + lane * 4);
        float4 m;
        m.x = g4.x * t4[el].x; m.y = g4.y * t4[el].y;
        m.z = g4.z * t4[el].z; m.w = g4.w * t4[el].w;
        float* p = aggr + (size_t)d * 128 + lane * 4;
        asm volatile("red.global.add.v4.f32 [%0], {%1, %2, %3, %4};"
                     :: "l"(p), "f"(m.x), "f"(m.y), "f"(m.z), "f"(m.w)
                     : "memory");
    }
}

// ---------------------------------------------------------------------------
// launch
// ---------------------------------------------------------------------------
extern "C" void kernel_launch(void* const* d_in, const int* in_sizes, int n_in,
                              void* d_out, int out_size)
{
    const float* x     = (const float*)d_in[0];
    const void*  ei    = d_in[1];
    const float* ea    = (const float*)d_in[2];
    const float* Wsame = (const float*)d_in[3];
    const float* bsame = (const float*)d_in[4];
    const float* Wdiff = (const float*)d_in[5];
    const float* bdiff = (const float*)d_in[6];
    const float* Gw    = (const float*)d_in[7];
    const float* rW1   = (const float*)d_in[8];
    const float* rb1   = (const float*)d_in[9];
    const float* rW2   = (const float*)d_in[10];
    const float* rb2   = (const float*)d_in[11];
    const float* Wlast = (const float*)d_in[12];
    const float* blast = (const float*)d_in[13];
    const float* u     = (const float*)d_in[14];

    const int N = in_sizes[0] / 128;
    const int E = in_sizes[2] / 64;
    const int R = in_sizes[8] / (128 * 128);

    float* out1  = (float*)d_out;
    float* msged = (float*)d_out + (size_t)N * 128;

    float *tdiff_p, *t_p;
    cudaGetSymbolAddress((void**)&tdiff_p, g_tdiff);
    cudaGetSymbolAddress((void**)&t_p, g_t);

    const int nblk = (N + 127) / 128;
    const int eblk = (E + 63) / 64;

    cudaFuncSetAttribute(tc_dual,
                         cudaFuncAttributeMaxDynamicSharedMemorySize, SM_TOTAL6);
    cudaFuncSetAttribute(res_chain,
                         cudaFuncAttributeMaxDynamicSharedMemorySize, SM_TOTAL6);
    cudaFuncSetAttribute(edge_kernel,
                         cudaFuncAttributeMaxDynamicSharedMemorySize, ESM_TOT);

    // index dtype detection (deterministic, re-run every replay)
    reset_or_kernel<<<1, 1>>>();
    scan_odd_kernel<<<256, 256>>>((const unsigned*)ei, E);

    // t_same -> msged, t_diff -> g_tdiff (shared A fill)
    tc_dual<<<nblk, 256, SM_TOTAL6>>>(x, Wsame, bsame, Wdiff, bdiff,
                                      msged, tdiff_p, N);

    // edge gate + message + scatter-add into msged
    edge_kernel<<<eblk, 256, ESM_TOT>>>(ei, ea, Gw, tdiff_p, msged, E);

    // residual stack + final GEMM, one kernel
    res_chain<<<nblk, 256, SM_TOTAL6>>>(msged, t_p, rW1, rb1, rW2, rb2,
                                        Wlast, blast, x, u, out1, N, R);
}

// round 10
// speedup vs baseline: 2.0728x; 1.0753x over previous
#include <cuda_runtime.h>
#include <cuda_bf16.h>
#include <cstdint>

// ---------------------------------------------------------------------------
// InteractionModule (PhysNet message passing + residual stack)
// All GEMMs on HMMA mma.sync m16n8k16 bf16, hi/lo split 3-term emulation.
// Weights pre-converted to bf16 hi/lo smem images once per replay (prep_w).
// Launches: reset, scan, prep_w, tc_dual, edge_kernel, res_chain.
// ---------------------------------------------------------------------------

#define SSP_LOG2 0.69314718055994530942f

__device__ __forceinline__ float sspf(float x) {
    return fmaxf(x, 0.0f) + __logf(1.0f + __expf(-fabsf(x))) - SSP_LOG2;
}

constexpr int FD   = 128;
constexpr int NMAX = 50176;

constexpr int RS      = 144;               // row stride bytes (9 x 16B)
constexpr int MAT_SZ  = 128 * RS;          // 18432 B per [128 x 64] bf16 tile
constexpr int IMG_SZ  = 2 * MAT_SZ;        // hi|lo image: 36864 B
constexpr int SM_TOTAL6 = 6 * MAT_SZ;      // dual / chain: 110592 B

__device__ float    g_tdiff[NMAX * FD];
__device__ float    g_t[NMAX * FD];
__device__ char     g_wimg[40 * IMG_SZ];   // weight images (slots*2 + Gw)
__device__ unsigned g_or;

// ---------------------------------------------------------------------------
// edge_index dtype detection: odd 32-bit words all zero <=> int64
// ---------------------------------------------------------------------------
__global__ void reset_or_kernel() { g_or = 0u; }
__global__ void scan_odd_kernel(const unsigned* __restrict__ w, int E) {
    unsigned v = 0;
    for (int i = blockIdx.x * blockDim.x + threadIdx.x; i < E;
         i += gridDim.x * blockDim.x)
        v |= w[2 * i + 1];
    v = __reduce_or_sync(0xffffffffu, v);
    if ((threadIdx.x & 31) == 0 && v) atomicOr(&g_or, 1u);
}

// ---------------------------------------------------------------------------
// warp MMA helpers (generic PTX, sm_80+)
// ---------------------------------------------------------------------------
__device__ __forceinline__ uint32_t smem_u32(const void* p) {
    uint32_t a;
    asm("{ .reg .u64 t; cvta.to.shared.u64 t, %1; cvt.u32.u64 %0, t; }"
        : "=r"(a) : "l"(p));
    return a;
}
__device__ __forceinline__ void ldmx4(uint32_t* r, uint32_t addr) {
    asm volatile("ldmatrix.sync.aligned.m8n8.x4.shared.b16 {%0,%1,%2,%3}, [%4];"
                 : "=r"(r[0]), "=r"(r[1]), "=r"(r[2]), "=r"(r[3]) : "r"(addr));
}
__device__ __forceinline__ void ldmx2(uint32_t* r, uint32_t addr) {
    asm volatile("ldmatrix.sync.aligned.m8n8.x2.shared.b16 {%0,%1}, [%2];"
                 : "=r"(r[0]), "=r"(r[1]) : "r"(addr));
}
__device__ __forceinline__ void mma16816(float* d, const uint32_t* a,
                                         const uint32_t* b) {
    asm volatile("mma.sync.aligned.m16n8k16.row.col.f32.bf16.bf16.f32 "
                 "{%0,%1,%2,%3}, {%4,%5,%6,%7}, {%8,%9}, {%0,%1,%2,%3};"
                 : "+f"(d[0]), "+f"(d[1]), "+f"(d[2]), "+f"(d[3])
                 : "r"(a[0]), "r"(a[1]), "r"(a[2]), "r"(a[3]),
                   "r"(b[0]), "r"(b[1]));
}

__device__ __forceinline__ void split_pack(float a, float b,
                                           uint32_t& hi, uint32_t& lo) {
    __nv_bfloat16 ah = __float2bfloat16(a);
    __nv_bfloat16 bh = __float2bfloat16(b);
    __nv_bfloat16 al = __float2bfloat16(a - __bfloat162float(ah));
    __nv_bfloat16 bl = __float2bfloat16(b - __bfloat162float(bh));
    hi = ((uint32_t)*(uint16_t*)&bh << 16) | *(uint16_t*)&ah;
    lo = ((uint32_t)*(uint16_t*)&bl << 16) | *(uint16_t*)&al;
}

// fill a [128 x 64] fp32 sub-tile (col offset kh*64, row stride src_ld)
// into hi/lo bf16 tiles (row stride RS bytes); dst may be smem or global
template <bool DO_SSP>
__device__ __forceinline__ void fill_half(char* dst, int hi_off, int lo_off,
                                          const float* __restrict__ src,
                                          int src_ld, int row0, int nrows,
                                          int kh, int t) {
    const int kg = t & 7;
    const int r0 = t >> 3;
#pragma unroll
    for (int p = 0; p < 4; p++) {
        int row = r0 + p * 32;
        float v[8];
        if (row < nrows) {
            const float* rp = src + (size_t)(row0 + row) * src_ld + kh * 64 + kg * 8;
            float4 va = *(const float4*)(rp);
            float4 vb = *(const float4*)(rp + 4);
            v[0] = va.x; v[1] = va.y; v[2] = va.z; v[3] = va.w;
            v[4] = vb.x; v[5] = vb.y; v[6] = vb.z; v[7] = vb.w;
        } else {
#pragma unroll
            for (int i = 0; i < 8; i++) v[i] = 0.0f;
        }
        uint32_t hi[4], lo[4];
#pragma unroll
        for (int i = 0; i < 4; i++) {
            float a = v[2 * i], b = v[2 * i + 1];
            if (DO_SSP) { a = sspf(a); b = sspf(b); }
            split_pack(a, b, hi[i], lo[i]);
        }
        uint32_t off = (uint32_t)row * RS + kg * 16;
        *(uint4*)(dst + hi_off + off) = make_uint4(hi[0], hi[1], hi[2], hi[3]);
        *(uint4*)(dst + lo_off + off) = make_uint4(lo[0], lo[1], lo[2], lo[3]);
    }
}

// fill a [64 x 64] fp32 tile into hi/lo bf16 smem tiles
__device__ __forceinline__ void fill_64(char* dst, int hi_off, int lo_off,
                                        const float* __restrict__ src,
                                        int src_ld, int row0, int nrows, int t) {
    const int kg = t & 7;
    const int r0 = t >> 3;
#pragma unroll
    for (int p = 0; p < 2; p++) {
        int row = r0 + p * 32;
        float v[8];
        if (row < nrows) {
            const float* rp = src + (size_t)(row0 + row) * src_ld + kg * 8;
            float4 va = *(const float4*)(rp);
            float4 vb = *(const float4*)(rp + 4);
            v[0] = va.x; v[1] = va.y; v[2] = va.z; v[3] = va.w;
            v[4] = vb.x; v[5] = vb.y; v[6] = vb.z; v[7] = vb.w;
        } else {
#pragma unroll
            for (int i = 0; i < 8; i++) v[i] = 0.0f;
        }
        uint32_t hi[4], lo[4];
#pragma unroll
        for (int i = 0; i < 4; i++)
            split_pack(v[2 * i], v[2 * i + 1], hi[i], lo[i]);
        uint32_t off = (uint32_t)row * RS + kg * 16;
        *(uint4*)(dst + hi_off + off) = make_uint4(hi[0], hi[1], hi[2], hi[3]);
        *(uint4*)(dst + lo_off + off) = make_uint4(lo[0], lo[1], lo[2], lo[3]);
    }
}

// copy one hi|lo weight image (36864 B) from global scratch into smem
__device__ __forceinline__ void copy_w(char* dst, const char* img, int t) {
    const uint4* s = (const uint4*)img;
    uint4* d = (uint4*)dst;
#pragma unroll
    for (int i = 0; i < 9; i++) d[t + i * 256] = s[t + i * 256];
}

// one K=64 MMA pass (3-term hi/lo emulation), M-tiles parametric
template <int MI>
__device__ __forceinline__ void mma_passM(float acc[MI][4][4],
                                          const uint32_t aHiA[MI],
                                          const uint32_t aLoA[MI],
                                          const uint32_t bHiA[4],
                                          const uint32_t bLoA[4]) {
#pragma unroll
    for (int ks = 0; ks < 4; ks++) {
        const uint32_t koff = ks * 32;
        uint32_t af[MI][4], bh[4][2], bl[4][2];
#pragma unroll
        for (int mi = 0; mi < MI; mi++) ldmx4(af[mi], aHiA[mi] + koff);
#pragma unroll
        for (int nj = 0; nj < 4; nj++) {
            ldmx2(bh[nj], bHiA[nj] + koff);
            ldmx2(bl[nj], bLoA[nj] + koff);
        }
#pragma unroll
        for (int mi = 0; mi < MI; mi++)
#pragma unroll
            for (int nj = 0; nj < 4; nj++) {
                mma16816(acc[mi][nj], af[mi], bh[nj]);
                mma16816(acc[mi][nj], af[mi], bl[nj]);
            }
#pragma unroll
        for (int mi = 0; mi < MI; mi++) ldmx4(af[mi], aLoA[mi] + koff);
#pragma unroll
        for (int mi = 0; mi < MI; mi++)
#pragma unroll
            for (int nj = 0; nj < 4; nj++)
                mma16816(acc[mi][nj], af[mi], bh[nj]);
    }
}

#define ZERO_ACC4(acc) do {                                                   \
    _Pragma("unroll") for (int mi = 0; mi < 4; mi++)                          \
    _Pragma("unroll") for (int nj = 0; nj < 4; nj++)                          \
    _Pragma("unroll") for (int q = 0; q < 4; q++) (acc)[mi][nj][q] = 0.0f;    \
} while (0)

struct TileIds {
    int lane, w, m_warp, n_warp, r_in, c_in;
    uint32_t aOff[4];
    uint32_t bOff[4];
};
__device__ __forceinline__ TileIds make_ids(int t) {
    TileIds id;
    id.lane  = t & 31;
    id.w     = t >> 5;
    id.m_warp = (id.w >> 2) * 64;
    id.n_warp = (id.w & 3) * 32;
    id.r_in  = id.lane >> 2;
    id.c_in  = (id.lane & 3) * 2;
    const int a_row = id.m_warp + ((id.lane >> 3) & 1) * 8 + (id.lane & 7);
    const int a_kh  = (id.lane >> 4) * 16;
#pragma unroll
    for (int mi = 0; mi < 4; mi++)
        id.aOff[mi] = (uint32_t)(a_row + 16 * mi) * RS + a_kh;
    const int b_lane = id.lane & 15;
    const int b_rowl = b_lane & 7;
    const int b_kh   = ((b_lane >> 3) & 1) * 16;
#pragma unroll
    for (int nj = 0; nj < 4; nj++)
        id.bOff[nj] = (uint32_t)(id.n_warp + 8 * nj + b_rowl) * RS + b_kh;
    return id;
}

// ---------------------------------------------------------------------------
// prep_w: convert all weights to bf16 hi/lo images once per replay.
// slots: 0=Wsame, 1=Wdiff, 2+2i=W1[i], 3+2i=W2[i], 2+2R=Wlast (kh in {0,1});
// block (3+2R)*2 = Gw (K=64, single image).
// ---------------------------------------------------------------------------
__global__ void prep_w(const float* __restrict__ Wsame,
                       const float* __restrict__ Wdiff,
                       const float* __restrict__ rW1,
                       const float* __restrict__ rW2,
                       const float* __restrict__ Wlast,
                       const float* __restrict__ Gw, int R)
{
    const int b = blockIdx.x, t = threadIdx.x;
    const int nsq = 3 + 2 * R;
    if (b < 2 * nsq) {
        const int slot = b >> 1, kh = b & 1;
        const float* W;
        if (slot == 0) W = Wsame;
        else if (slot == 1) W = Wdiff;
        else if (slot < 2 + 2 * R) {
            int i = (slot - 2) >> 1;
            W = ((slot - 2) & 1) ? rW2 + (size_t)i * 16384
                                 : rW1 + (size_t)i * 16384;
        } else W = Wlast;
        char* img = g_wimg + (size_t)b * IMG_SZ;
        fill_half<false>(img, 0, MAT_SZ, W, 128, 0, 128, kh, t);
    } else {
        char* img = g_wimg + (size_t)(2 * nsq) * IMG_SZ;
        fill_half<false>(img, 0, MAT_SZ, Gw, 64, 0, 128, 0, t);
    }
}

// ---------------------------------------------------------------------------
// tc_dual: A = ssp(x) filled once; two GEMMs (W_same -> msged, W_diff -> tdiff)
// ---------------------------------------------------------------------------
__global__ __launch_bounds__(256, 2)
void tc_dual(const float* __restrict__ x,
             const float* __restrict__ bsame, const float* __restrict__ bdiff,
             float* __restrict__ msged, float* __restrict__ tdiff, int N)
{
    extern __shared__ char smem[];
    const uint32_t sbase = smem_u32(smem);
    const int t     = threadIdx.x;
    const int row0  = blockIdx.x * 128;
    const int nrows = min(128, N - row0);
    TileIds id = make_ids(t);

    uint32_t aHi[2][4], aLo[2][4], bHi[4], bLo[4];
#pragma unroll
    for (int mi = 0; mi < 4; mi++) {
        aHi[0][mi] = sbase + 0 * MAT_SZ + id.aOff[mi];
        aLo[0][mi] = sbase + 1 * MAT_SZ + id.aOff[mi];
        aHi[1][mi] = sbase + 4 * MAT_SZ + id.aOff[mi];
        aLo[1][mi] = sbase + 5 * MAT_SZ + id.aOff[mi];
    }
#pragma unroll
    for (int nj = 0; nj < 4; nj++) {
        bHi[nj] = sbase + 2 * MAT_SZ + id.bOff[nj];
        bLo[nj] = sbase + 3 * MAT_SZ + id.bOff[nj];
    }

    fill_half<true>(smem, 0 * MAT_SZ, 1 * MAT_SZ, x, 128, row0, nrows, 0, t);
    fill_half<true>(smem, 4 * MAT_SZ, 5 * MAT_SZ, x, 128, row0, nrows, 1, t);

    float acc[4][4][4];
    const float* bp[2] = {bsame, bdiff};
    float*       op[2] = {msged, tdiff};

#pragma unroll
    for (int g = 0; g < 2; g++) {
        ZERO_ACC4(acc);
#pragma unroll
        for (int kh = 0; kh < 2; kh++) {
            __syncthreads();
            copy_w(smem + 2 * MAT_SZ, g_wimg + (size_t)(g * 2 + kh) * IMG_SZ, t);
            __syncthreads();
            mma_passM<4>(acc, aHi[kh], aLo[kh], bHi, bLo);
        }
#pragma unroll
        for (int mi = 0; mi < 4; mi++)
#pragma unroll
            for (int half = 0; half < 2; half++) {
                const int row = id.m_warp + 16 * mi + half * 8 + id.r_in;
                if (row >= nrows) continue;
                const size_t grow = (size_t)(row0 + row) * 128;
#pragma unroll
                for (int nj = 0; nj < 4; nj++) {
                    const int col = id.n_warp + 8 * nj + id.c_in;
                    float2 bb = *(const float2*)(bp[g] + col);
                    float2 o;
                    o.x = sspf(acc[mi][nj][half * 2 + 0] + bb.x);
                    o.y = sspf(acc[mi][nj][half * 2 + 1] + bb.y);
                    *(float2*)(op[g] + grow + col) = o;
                }
            }
    }
}

// ---------------------------------------------------------------------------
// res_chain: R fused residual layers + final GEMM, one kernel.
// ---------------------------------------------------------------------------
__global__ __launch_bounds__(256, 2)
void res_chain(const float* __restrict__ msged, float* __restrict__ tbuf,
               const float* __restrict__ rb1, const float* __restrict__ rb2,
               const float* __restrict__ blast,
               const float* __restrict__ x, const float* __restrict__ u,
               float* __restrict__ out1, int N, int R)
{
    extern __shared__ char smem[];
    const uint32_t sbase = smem_u32(smem);
    const int t     = threadIdx.x;
    const int row0  = blockIdx.x * 128;
    const int nrows = min(128, N - row0);
    TileIds id = make_ids(t);

    uint32_t aHi[2][4], aLo[2][4], bHi[4], bLo[4];
#pragma unroll
    for (int mi = 0; mi < 4; mi++) {
        aHi[0][mi] = sbase + 0 * MAT_SZ + id.aOff[mi];
        aLo[0][mi] = sbase + 1 * MAT_SZ + id.aOff[mi];
        aHi[1][mi] = sbase + 4 * MAT_SZ + id.aOff[mi];
        aLo[1][mi] = sbase + 5 * MAT_SZ + id.aOff[mi];
    }
#pragma unroll
    for (int nj = 0; nj < 4; nj++) {
        bHi[nj] = sbase + 2 * MAT_SZ + id.bOff[nj];
        bLo[nj] = sbase + 3 * MAT_SZ + id.bOff[nj];
    }
    const int hiB[2] = {0 * MAT_SZ, 4 * MAT_SZ};
    const int loB[2] = {1 * MAT_SZ, 5 * MAT_SZ};

    fill_half<true>(smem, hiB[0], loB[0], msged, 128, row0, nrows, 0, t);
    fill_half<true>(smem, hiB[1], loB[1], msged, 128, row0, nrows, 1, t);

    const float* tin = msged;
    float acc[4][4][4];

    for (int i = 0; i < R; i++) {
        const float* b1 = rb1 + (size_t)i * 128;
        const float* b2 = rb2 + (size_t)i * 128;
        const char* img1 = g_wimg + (size_t)((2 + 2 * i) * 2) * IMG_SZ;
        const char* img2 = g_wimg + (size_t)((3 + 2 * i) * 2) * IMG_SZ;

        ZERO_ACC4(acc);
#pragma unroll
        for (int kh = 0; kh < 2; kh++) {
            __syncthreads();
            copy_w(smem + 2 * MAT_SZ, img1 + (size_t)kh * IMG_SZ, t);
            __syncthreads();
            mma_passM<4>(acc, aHi[kh], aLo[kh], bHi, bLo);
        }
        __syncthreads();

#pragma unroll
        for (int mi = 0; mi < 4; mi++)
#pragma unroll
            for (int half = 0; half < 2; half++) {
                const int row = id.m_warp + 16 * mi + half * 8 + id.r_in;
#pragma unroll
                for (int nj = 0; nj < 4; nj++) {
                    const int col = id.n_warp + 8 * nj + id.c_in;
                    float2 bb = *(const float2*)(b1 + col);
                    float a = sspf(acc[mi][nj][half * 2 + 0] + bb.x);
                    float b = sspf(acc[mi][nj][half * 2 + 1] + bb.y);
                    uint32_t hi, lo;
                    split_pack(a, b, hi, lo);
                    const int kh = col >> 6;
                    uint32_t off = (uint32_t)row * RS + (col & 63) * 2;
                    *(uint32_t*)(smem + hiB[kh] + off) = hi;
                    *(uint32_t*)(smem + loB[kh] + off) = lo;
                }
            }

        ZERO_ACC4(acc);
#pragma unroll
        for (int kh = 0; kh < 2; kh++) {
            __syncthreads();
            copy_w(smem + 2 * MAT_SZ, img2 + (size_t)kh * IMG_SZ, t);
            __syncthreads();
            mma_passM<4>(acc, aHi[kh], aLo[kh], bHi, bLo);
        }
        __syncthreads();

        const bool wr = (i < R - 1);
#pragma unroll
        for (int mi = 0; mi < 4; mi++)
#pragma unroll
            for (int half = 0; half < 2; half++) {
                const int row = id.m_warp + 16 * mi + half * 8 + id.r_in;
                const bool ok = row < nrows;
                const size_t grow = (size_t)(row0 + row) * 128;
#pragma unroll
                for (int nj = 0; nj < 4; nj++) {
                    const int col = id.n_warp + 8 * nj + id.c_in;
                    float2 bb = *(const float2*)(b2 + col);
                    float2 tv = ok ? *(const float2*)(tin + grow + col)
                                   : make_float2(0.f, 0.f);
                    float ox = acc[mi][nj][half * 2 + 0] + bb.x + tv.x;
                    float oy = acc[mi][nj][half * 2 + 1] + bb.y + tv.y;
                    if (wr && ok) *(float2*)(tbuf + grow + col) = make_float2(ox, oy);
                    uint32_t hi, lo;
                    split_pack(sspf(ox), sspf(oy), hi, lo);
                    const int kh = col >> 6;
                    uint32_t off = (uint32_t)row * RS + (col & 63) * 2;
                    *(uint32_t*)(smem + hiB[kh] + off) = hi;
                    *(uint32_t*)(smem + loB[kh] + off) = lo;
                }
            }
        tin = tbuf;
    }

    // final GEMM (slot 2+2R)
    const char* imgL = g_wimg + (size_t)((2 + 2 * R) * 2) * IMG_SZ;
    ZERO_ACC4(acc);
#pragma unroll
    for (int kh = 0; kh < 2; kh++) {
        __syncthreads();
        copy_w(smem + 2 * MAT_SZ, imgL + (size_t)kh * IMG_SZ, t);
        __syncthreads();
        mma_passM<4>(acc, aHi[kh], aLo[kh], bHi, bLo);
    }
#pragma unroll
    for (int mi = 0; mi < 4; mi++)
#pragma unroll
        for (int half = 0; half < 2; half++) {
            const int row = id.m_warp + 16 * mi + half * 8 + id.r_in;
            if (row >= nrows) continue;
            const size_t grow = (size_t)(row0 + row) * 128;
#pragma unroll
            for (int nj = 0; nj < 4; nj++) {
                const int col = id.n_warp + 8 * nj + id.c_in;
                float2 bb = *(const float2*)(blast + col);
                float2 xv = *(const float2*)(x + grow + col);
                float2 uv = *(const float2*)(u + col);
                float2 o;
                o.x = acc[mi][nj][half * 2 + 0] + bb.x + xv.x * uv.x;
                o.y = acc[mi][nj][half * 2 + 1] + bb.y + xv.y * uv.y;
                *(float2*)(out1 + grow + col) = o;
            }
        }
}

// ---------------------------------------------------------------------------
// edge_kernel v3: 128 edges/block as 2x64 sub-tiles; W image copied once.
// smem: W hi/lo [0, 36864); ea tiles + gate scratch [36864, 71680).
// ---------------------------------------------------------------------------
constexpr int GSTR = 136;
constexpr int EEA      = 2 * MAT_SZ;                 // ea hi at 36864
constexpr int EEA_LO   = EEA + 64 * RS;              // ea lo at 46080
constexpr int ESM_TOT3 = 2 * MAT_SZ + 64 * GSTR * 4; // 71680

__global__ __launch_bounds__(256, 3)
void edge_kernel(const void* __restrict__ idx_raw,
                 const float* __restrict__ ea,
                 const float* __restrict__ tdiff,
                 float* __restrict__ aggr,
                 const char* __restrict__ gwimg,
                 int E)
{
    extern __shared__ char smem[];
    const uint32_t sbase = smem_u32(smem);
    float* gsm = (float*)(smem + EEA);

    const int t    = threadIdx.x;
    const int lane = t & 31;
    const int w    = t >> 5;
    const int e0   = blockIdx.x * 128;

    // W image copy (lives across both sub-tiles)
    copy_w(smem, gwimg, t);

    // prefetch (src,dst) for both sub-tiles
    const bool idx64 = (*(volatile unsigned*)&g_or) == 0u;
    const long long* ll = (const long long*)idx_raw;
    const int*       ii = (const int*)idx_raw;
    long long sReg[2] = {0, 0}, dReg[2] = {0, 0};
    if (lane < 8) {
#pragma unroll
        for (int s = 0; s < 2; s++) {
            int e = e0 + s * 64 + w * 8 + lane;
            if (e < E) {
                if (idx64) { sReg[s] = ll[e]; dReg[s] = ll[E + e]; }
                else       { sReg[s] = ii[e]; dReg[s] = ii[E + e]; }
            }
        }
    }

    // warp grid: 2 (m) x 4 (n); warp tile 32 x 32
    const int m_warp = (w >> 2) * 32;
    const int n_warp = (w & 3) * 32;

    const int a_row = m_warp + ((lane >> 3) & 1) * 8 + (lane & 7);
    const int a_kh  = (lane >> 4) * 16;
    uint32_t aHiA[2], aLoA[2];
#pragma unroll
    for (int mi = 0; mi < 2; mi++) {
        uint32_t off = (uint32_t)(a_row + 16 * mi) * RS + a_kh;
        aHiA[mi] = sbase + EEA + off;
        aLoA[mi] = sbase + EEA_LO + off;
    }
    const int b_lane = lane & 15;
    const int b_rowl = b_lane & 7;
    const int b_kh   = ((b_lane >> 3) & 1) * 16;
    uint32_t bHiA[4], bLoA[4];
#pragma unroll
    for (int nj = 0; nj < 4; nj++) {
        uint32_t off = (uint32_t)(n_warp + 8 * nj + b_rowl) * RS + b_kh;
        bHiA[nj] = sbase + off;             // W hi at smem 0
        bLoA[nj] = sbase + MAT_SZ + off;    // W lo at smem MAT_SZ
    }

    const int r_in = lane >> 2;
    const int c_in = (lane & 3) * 2;

#pragma unroll
    for (int s = 0; s < 2; s++) {
        const int e0s = e0 + s * 64;
        if (e0s >= E) break;
        const int nrows = min(64, E - e0s);

        if (s) __syncthreads();   // gate scratch from sub-tile 0 consumed
        fill_64(smem, EEA, EEA_LO, ea, 64, e0s, nrows, t);
        __syncthreads();

        float acc[2][4][4];
#pragma unroll
        for (int mi = 0; mi < 2; mi++)
#pragma unroll
            for (int nj = 0; nj < 4; nj++)
#pragma unroll
                for (int q = 0; q < 4; q++) acc[mi][nj][q] = 0.0f;

        mma_passM<2>(acc, aHiA, aLoA, bHiA, bLoA);
        __syncthreads();   // ea consumed; stage gate over it

#pragma unroll
        for (int mi = 0; mi < 2; mi++)
#pragma unroll
            for (int half = 0; half < 2; half++) {
                const int row = m_warp + 16 * mi + half * 8 + r_in;
#pragma unroll
                for (int nj = 0; nj < 4; nj++) {
                    const int col = n_warp + 8 * nj + c_in;
                    float2 o;
                    o.x = acc[mi][nj][half * 2 + 0];
                    o.y = acc[mi][nj][half * 2 + 1];
                    *(float2*)(gsm + (size_t)row * GSTR + col) = o;
                }
            }
        __syncthreads();

        // scatter: warp w owns edges [w*8, w*8+8); batch gathers (MLP=8)
        float4 t4[8];
#pragma unroll
        for (int el = 0; el < 8; el++) {
            long long sidx = __shfl_sync(0xffffffffu, sReg[s], el);
            t4[el] = *(const float4*)(tdiff + (size_t)sidx * 128 + lane * 4);
        }
#pragma unroll
        for (int el = 0; el < 8; el++) {
            int e = e0s + w * 8 + el;
            if (e >= E) break;
            long long d = __shfl_sync(0xffffffffu, dReg[s], el);
            float4 g4 = *(const float4*)(gsm + (size_t)(w * 8 + el) * GSTR + lane * 4);
            float4 m;
            m.x = g4.x * t4[el].x; m.y = g4.y * t4[el].y;
            m.z = g4.z * t4[el].z; m.w = g4.w * t4[el].w;
            float* p = aggr + (size_t)d * 128 + lane * 4;
            asm volatile("red.global.add.v4.f32 [%0], {%1, %2, %3, %4};"
                         :: "l"(p), "f"(m.x), "f"(m.y), "f"(m.z), "f"(m.w)
                         : "memory");
        }
    }
}

// ---------------------------------------------------------------------------
// launch
// ---------------------------------------------------------------------------
extern "C" void kernel_launch(void* const* d_in, const int* in_sizes, int n_in,
                              void* d_out, int out_size)
{
    const float* x     = (const float*)d_in[0];
    const void*  ei    = d_in[1];
    const float* ea    = (const float*)d_in[2];
    const float* Wsame = (const float*)d_in[3];
    const float* bsame = (const float*)d_in[4];
    const float* Wdiff = (const float*)d_in[5];
    const float* bdiff = (const float*)d_in[6];
    const float* Gw    = (const float*)d_in[7];
    const float* rW1   = (const float*)d_in[8];
    const float* rb1   = (const float*)d_in[9];
    const float* rW2   = (const float*)d_in[10];
    const float* rb2   = (const float*)d_in[11];
    const float* Wlast = (const float*)d_in[12];
    const float* blast = (const float*)d_in[13];
    const float* u     = (const float*)d_in[14];

    const int N = in_sizes[0] / 128;
    const int E = in_sizes[2] / 64;
    const int R = in_sizes[8] / (128 * 128);

    float* out1  = (float*)d_out;
    float* msged = (float*)d_out + (size_t)N * 128;

    float *tdiff_p, *t_p;
    char* wimg_p;
    cudaGetSymbolAddress((void**)&tdiff_p, g_tdiff);
    cudaGetSymbolAddress((void**)&t_p, g_t);
    cudaGetSymbolAddress((void**)&wimg_p, g_wimg);

    const int nblk = (N + 127) / 128;
    const int eblk = (E + 127) / 128;
    const int nsq  = 3 + 2 * R;

    cudaFuncSetAttribute(tc_dual,
                         cudaFuncAttributeMaxDynamicSharedMemorySize, SM_TOTAL6);
    cudaFuncSetAttribute(res_chain,
                         cudaFuncAttributeMaxDynamicSharedMemorySize, SM_TOTAL6);
    cudaFuncSetAttribute(edge_kernel,
                         cudaFuncAttributeMaxDynamicSharedMemorySize, ESM_TOT3);

    // index dtype detection + weight image prep (deterministic per replay)
    reset_or_kernel<<<1, 1>>>();
    scan_odd_kernel<<<256, 256>>>((const unsigned*)ei, E);
    prep_w<<<2 * nsq + 1, 256>>>(Wsame, Wdiff, rW1, rW2, Wlast, Gw, R);

    // t_same -> msged, t_diff -> g_tdiff (shared A fill)
    tc_dual<<<nblk, 256, SM_TOTAL6>>>(x, bsame, bdiff, msged, tdiff_p, N);

    // edge gate + message + scatter-add into msged
    edge_kernel<<<eblk, 256, ESM_TOT3>>>(ei, ea, tdiff_p, msged,
                                         wimg_p + (size_t)(2 * nsq) * IMG_SZ, E);

    // residual stack + final GEMM, one kernel
    res_chain<<<nblk, 256, SM_TOTAL6>>>(msged, t_p, rb1, rb2,
                                        blast, x, u, out1, N, R);
}

// round 11
// speedup vs baseline: 2.2802x; 1.1000x over previous
#include <cuda_runtime.h>
#include <cuda_bf16.h>
#include <cstdint>

// ---------------------------------------------------------------------------
// InteractionModule (PhysNet message passing + residual stack)
// All GEMMs on HMMA mma.sync m16n8k16 bf16, hi/lo split 3-term emulation.
// Weights pre-converted ONCE per replay into mma B-fragment register layout
// (prep_w); GEMM inner loops LDG B-frags directly from global (L2-hot),
// eliminating the W smem buffer, STS/LDSM-B, and all intra-GEMM syncs.
// ---------------------------------------------------------------------------

#define SSP_LOG2 0.69314718055994530942f

__device__ __forceinline__ float sspf(float x) {
    return fmaxf(x, 0.0f) + __logf(1.0f + __expf(-fabsf(x))) - SSP_LOG2;
}

constexpr int FD   = 128;
constexpr int NMAX = 50176;

constexpr int RS      = 144;               // A-tile row stride bytes (9 x 16B)
constexpr int MAT_SZ  = 128 * RS;          // 18432 B per [128 x 64] bf16 tile
constexpr int FRAG_SZ = 32768;             // one K-half B-frag image
constexpr int SM_A4   = 4 * MAT_SZ;        // node kernels: A only, 73728 B

__device__ float    g_tdiff[NMAX * FD];
__device__ float    g_t[NMAX * FD];
__device__ char     g_wimg[20 * FRAG_SZ];  // B-frag images (18 square + Gw)
__device__ unsigned g_or;

// ---------------------------------------------------------------------------
// edge_index dtype detection: odd 32-bit words all zero <=> int64
// ---------------------------------------------------------------------------
__global__ void reset_or_kernel() { g_or = 0u; }
__global__ void scan_odd_kernel(const unsigned* __restrict__ w, int E) {
    unsigned v = 0;
    for (int i = blockIdx.x * blockDim.x + threadIdx.x; i < E;
         i += gridDim.x * blockDim.x)
        v |= w[2 * i + 1];
    v = __reduce_or_sync(0xffffffffu, v);
    if ((threadIdx.x & 31) == 0 && v) atomicOr(&g_or, 1u);
}

// ---------------------------------------------------------------------------
// warp MMA helpers (generic PTX, sm_80+)
// ---------------------------------------------------------------------------
__device__ __forceinline__ uint32_t smem_u32(const void* p) {
    uint32_t a;
    asm("{ .reg .u64 t; cvta.to.shared.u64 t, %1; cvt.u32.u64 %0, t; }"
        : "=r"(a) : "l"(p));
    return a;
}
__device__ __forceinline__ void ldmx4(uint32_t* r, uint32_t addr) {
    asm volatile("ldmatrix.sync.aligned.m8n8.x4.shared.b16 {%0,%1,%2,%3}, [%4];"
                 : "=r"(r[0]), "=r"(r[1]), "=r"(r[2]), "=r"(r[3]) : "r"(addr));
}
__device__ __forceinline__ void mma16816(float* d, const uint32_t* a,
                                         uint32_t b0, uint32_t b1) {
    asm volatile("mma.sync.aligned.m16n8k16.row.col.f32.bf16.bf16.f32 "
                 "{%0,%1,%2,%3}, {%4,%5,%6,%7}, {%8,%9}, {%0,%1,%2,%3};"
                 : "+f"(d[0]), "+f"(d[1]), "+f"(d[2]), "+f"(d[3])
                 : "r"(a[0]), "r"(a[1]), "r"(a[2]), "r"(a[3]),
                   "r"(b0), "r"(b1));
}

__device__ __forceinline__ void split_pack(float a, float b,
                                           uint32_t& hi, uint32_t& lo) {
    __nv_bfloat16 ah = __float2bfloat16(a);
    __nv_bfloat16 bh = __float2bfloat16(b);
    __nv_bfloat16 al = __float2bfloat16(a - __bfloat162float(ah));
    __nv_bfloat16 bl = __float2bfloat16(b - __bfloat162float(bh));
    hi = ((uint32_t)*(uint16_t*)&bh << 16) | *(uint16_t*)&ah;
    lo = ((uint32_t)*(uint16_t*)&bl << 16) | *(uint16_t*)&al;
}

// fill a [128 x 64] fp32 sub-tile (col offset kh*64, row stride src_ld)
// into hi/lo bf16 A-tiles (row stride RS bytes)
template <bool DO_SSP>
__device__ __forceinline__ void fill_half(char* dst, int hi_off, int lo_off,
                                          const float* __restrict__ src,
                                          int src_ld, int row0, int nrows,
                                          int kh, int t) {
    const int kg = t & 7;
    const int r0 = t >> 3;
#pragma unroll
    for (int p = 0; p < 4; p++) {
        int row = r0 + p * 32;
        float v[8];
        if (row < nrows) {
            const float* rp = src + (size_t)(row0 + row) * src_ld + kh * 64 + kg * 8;
            float4 va = *(const float4*)(rp);
            float4 vb = *(const float4*)(rp + 4);
            v[0] = va.x; v[1] = va.y; v[2] = va.z; v[3] = va.w;
            v[4] = vb.x; v[5] = vb.y; v[6] = vb.z; v[7] = vb.w;
        } else {
#pragma unroll
            for (int i = 0; i < 8; i++) v[i] = 0.0f;
        }
        uint32_t hi[4], lo[4];
#pragma unroll
        for (int i = 0; i < 4; i++) {
            float a = v[2 * i], b = v[2 * i + 1];
            if (DO_SSP) { a = sspf(a); b = sspf(b); }
            split_pack(a, b, hi[i], lo[i]);
        }
        uint32_t off = (uint32_t)row * RS + kg * 16;
        *(uint4*)(dst + hi_off + off) = make_uint4(hi[0], hi[1], hi[2], hi[3]);
        *(uint4*)(dst + lo_off + off) = make_uint4(lo[0], lo[1], lo[2], lo[3]);
    }
}

// fill a [64 x 64] fp32 tile into hi/lo bf16 smem tiles
__device__ __forceinline__ void fill_64(char* dst, int hi_off, int lo_off,
                                        const float* __restrict__ src,
                                        int src_ld, int row0, int nrows, int t) {
    const int kg = t & 7;
    const int r0 = t >> 3;
#pragma unroll
    for (int p = 0; p < 2; p++) {
        int row = r0 + p * 32;
        float v[8];
        if (row < nrows) {
            const float* rp = src + (size_t)(row0 + row) * src_ld + kg * 8;
            float4 va = *(const float4*)(rp);
            float4 vb = *(const float4*)(rp + 4);
            v[0] = va.x; v[1] = va.y; v[2] = va.z; v[3] = va.w;
            v[4] = vb.x; v[5] = vb.y; v[6] = vb.z; v[7] = vb.w;
        } else {
#pragma unroll
            for (int i = 0; i < 8; i++) v[i] = 0.0f;
        }
        uint32_t hi[4], lo[4];
#pragma unroll
        for (int i = 0; i < 4; i++)
            split_pack(v[2 * i], v[2 * i + 1], hi[i], lo[i]);
        uint32_t off = (uint32_t)row * RS + kg * 16;
        *(uint4*)(dst + hi_off + off) = make_uint4(hi[0], hi[1], hi[2], hi[3]);
        *(uint4*)(dst + lo_off + off) = make_uint4(lo[0], lo[1], lo[2], lo[3]);
    }
}

// one K=64 MMA pass; A from smem (ldmatrix), B frags via LDG from frag image.
// image entry index: ((nw*4 + ks)*4 + nj)*32 + lane; uint4 = {h0,h1,l0,l1}.
template <int MI>
__device__ __forceinline__ void mma_passG(float acc[MI][4][4],
                                          const uint32_t aHiA[MI],
                                          const uint32_t aLoA[MI],
                                          const uint4* __restrict__ bimg,
                                          int nw, int lane) {
#pragma unroll
    for (int ks = 0; ks < 4; ks++) {
        uint4 b[4];
#pragma unroll
        for (int nj = 0; nj < 4; nj++)
            b[nj] = bimg[((nw * 4 + ks) * 4 + nj) * 32 + lane];
        const uint32_t koff = ks * 32;
        uint32_t af[MI][4];
#pragma unroll
        for (int mi = 0; mi < MI; mi++) ldmx4(af[mi], aHiA[mi] + koff);
#pragma unroll
        for (int mi = 0; mi < MI; mi++)
#pragma unroll
            for (int nj = 0; nj < 4; nj++) {
                mma16816(acc[mi][nj], af[mi], b[nj].x, b[nj].y);   // Ah*Wh
                mma16816(acc[mi][nj], af[mi], b[nj].z, b[nj].w);   // Ah*Wl
            }
#pragma unroll
        for (int mi = 0; mi < MI; mi++) ldmx4(af[mi], aLoA[mi] + koff);
#pragma unroll
        for (int mi = 0; mi < MI; mi++)
#pragma unroll
            for (int nj = 0; nj < 4; nj++)
                mma16816(acc[mi][nj], af[mi], b[nj].x, b[nj].y);   // Al*Wh
    }
}

#define ZERO_ACC4(acc) do {                                                   \
    _Pragma("unroll") for (int mi = 0; mi < 4; mi++)                          \
    _Pragma("unroll") for (int nj = 0; nj < 4; nj++)                          \
    _Pragma("unroll") for (int q = 0; q < 4; q++) (acc)[mi][nj][q] = 0.0f;    \
} while (0)

struct TileIds {
    int lane, w, m_warp, nw, r_in, c_in;
    uint32_t aOff[4];
};
__device__ __forceinline__ TileIds make_ids(int t) {
    TileIds id;
    id.lane  = t & 31;
    id.w     = t >> 5;
    id.m_warp = (id.w >> 2) * 64;
    id.nw    = id.w & 3;
    id.r_in  = id.lane >> 2;
    id.c_in  = (id.lane & 3) * 2;
    const int a_row = id.m_warp + ((id.lane >> 3) & 1) * 8 + (id.lane & 7);
    const int a_kh  = (id.lane >> 4) * 16;
#pragma unroll
    for (int mi = 0; mi < 4; mi++)
        id.aOff[mi] = (uint32_t)(a_row + 16 * mi) * RS + a_kh;
    return id;
}

// ---------------------------------------------------------------------------
// prep_w: convert weights to mma B-fragment images, once per replay.
// For entry (nw, ks, nj, lane): n = nw*32 + nj*8 + lane/4,
// k0 = kh*64 + ks*16 + (lane%4)*2; uint4 = {hi(k0,k0+1), hi(k0+8,k0+9),
// lo(k0,k0+1), lo(k0+8,k0+9)}  — identical to ldmatrix.x2 frag distribution.
// blocks: b < 2*nsq -> square weight (slot=b/2, kh=b&1); b == 2*nsq -> Gw.
// ---------------------------------------------------------------------------
__global__ void prep_w(const float* __restrict__ Wsame,
                       const float* __restrict__ Wdiff,
                       const float* __restrict__ rW1,
                       const float* __restrict__ rW2,
                       const float* __restrict__ Wlast,
                       const float* __restrict__ Gw, int R)
{
    const int bq = blockIdx.x, t = threadIdx.x;
    const int nsq = 3 + 2 * R;
    const float* W;
    int ld, kh;
    char* img;
    if (bq < 2 * nsq) {
        const int slot = bq >> 1;
        kh = bq & 1;
        ld = 128;
        if (slot == 0) W = Wsame;
        else if (slot == 1) W = Wdiff;
        else if (slot < 2 + 2 * R) {
            int i = (slot - 2) >> 1;
            W = ((slot - 2) & 1) ? rW2 + (size_t)i * 16384
                                 : rW1 + (size_t)i * 16384;
        } else W = Wlast;
        img = g_wimg + (size_t)bq * FRAG_SZ;
    } else {
        W = Gw; ld = 64; kh = 0;
        img = g_wimg + (size_t)(2 * nsq) * FRAG_SZ;
    }
    uint4* out = (uint4*)img;
    for (int e = t; e < 2048; e += 256) {
        const int lane = e & 31, nj = (e >> 5) & 3, ks = (e >> 7) & 3, nw = e >> 9;
        const int n  = nw * 32 + nj * 8 + (lane >> 2);
        const int k0 = kh * 64 + ks * 16 + (lane & 3) * 2;
        const float* p = W + (size_t)n * ld + k0;
        uint32_t h0, l0, h1, l1;
        split_pack(p[0], p[1], h0, l0);
        split_pack(p[8], p[9], h1, l1);
        out[e] = make_uint4(h0, h1, l0, l1);
    }
}

// ---------------------------------------------------------------------------
// tc_dual: A = ssp(x) filled once (4 smem buffers: kh0 hi/lo, kh1 hi/lo);
// two sync-free GEMMs with B from frag images.
// ---------------------------------------------------------------------------
__global__ __launch_bounds__(256, 2)
void tc_dual(const float* __restrict__ x,
             const float* __restrict__ bsame, const float* __restrict__ bdiff,
             float* __restrict__ msged, float* __restrict__ tdiff, int N)
{
    extern __shared__ char smem[];
    const uint32_t sbase = smem_u32(smem);
    const int t     = threadIdx.x;
    const int row0  = blockIdx.x * 128;
    const int nrows = min(128, N - row0);
    TileIds id = make_ids(t);

    uint32_t aHi[2][4], aLo[2][4];
#pragma unroll
    for (int mi = 0; mi < 4; mi++) {
        aHi[0][mi] = sbase + 0 * MAT_SZ + id.aOff[mi];
        aLo[0][mi] = sbase + 1 * MAT_SZ + id.aOff[mi];
        aHi[1][mi] = sbase + 2 * MAT_SZ + id.aOff[mi];
        aLo[1][mi] = sbase + 3 * MAT_SZ + id.aOff[mi];
    }

    fill_half<true>(smem, 0 * MAT_SZ, 1 * MAT_SZ, x, 128, row0, nrows, 0, t);
    fill_half<true>(smem, 2 * MAT_SZ, 3 * MAT_SZ, x, 128, row0, nrows, 1, t);
    __syncthreads();

    float acc[4][4][4];
    const float* bp[2] = {bsame, bdiff};
    float*       op[2] = {msged, tdiff};

#pragma unroll
    for (int g = 0; g < 2; g++) {
        ZERO_ACC4(acc);
#pragma unroll
        for (int kh = 0; kh < 2; kh++) {
            const uint4* bimg = (const uint4*)(g_wimg + (size_t)(g * 2 + kh) * FRAG_SZ);
            mma_passG<4>(acc, aHi[kh], aLo[kh], bimg, id.nw, id.lane);
        }
#pragma unroll
        for (int mi = 0; mi < 4; mi++)
#pragma unroll
            for (int half = 0; half < 2; half++) {
                const int row = id.m_warp + 16 * mi + half * 8 + id.r_in;
                if (row >= nrows) continue;
                const size_t grow = (size_t)(row0 + row) * 128;
#pragma unroll
                for (int nj = 0; nj < 4; nj++) {
                    const int col = id.nw * 32 + 8 * nj + id.c_in;
                    float2 bb = *(const float2*)(bp[g] + col);
                    float2 o;
                    o.x = sspf(acc[mi][nj][half * 2 + 0] + bb.x);
                    o.y = sspf(acc[mi][nj][half * 2 + 1] + bb.y);
                    *(float2*)(op[g] + grow + col) = o;
                }
            }
    }
}

// ---------------------------------------------------------------------------
// res_chain: R fused residual layers + final GEMM, one kernel.
// Syncs only around the in-smem A conversions; GEMMs themselves sync-free.
// ---------------------------------------------------------------------------
__global__ __launch_bounds__(256, 2)
void res_chain(const float* __restrict__ msged, float* __restrict__ tbuf,
               const float* __restrict__ rb1, const float* __restrict__ rb2,
               const float* __restrict__ blast,
               const float* __restrict__ x, const float* __restrict__ u,
               float* __restrict__ out1, int N, int R)
{
    extern __shared__ char smem[];
    const uint32_t sbase = smem_u32(smem);
    const int t     = threadIdx.x;
    const int row0  = blockIdx.x * 128;
    const int nrows = min(128, N - row0);
    TileIds id = make_ids(t);

    uint32_t aHi[2][4], aLo[2][4];
#pragma unroll
    for (int mi = 0; mi < 4; mi++) {
        aHi[0][mi] = sbase + 0 * MAT_SZ + id.aOff[mi];
        aLo[0][mi] = sbase + 1 * MAT_SZ + id.aOff[mi];
        aHi[1][mi] = sbase + 2 * MAT_SZ + id.aOff[mi];
        aLo[1][mi] = sbase + 3 * MAT_SZ + id.aOff[mi];
    }
    const int hiB[2] = {0 * MAT_SZ, 2 * MAT_SZ};
    const int loB[2] = {1 * MAT_SZ, 3 * MAT_SZ};

    fill_half<true>(smem, hiB[0], loB[0], msged, 128, row0, nrows, 0, t);
    fill_half<true>(smem, hiB[1], loB[1], msged, 128, row0, nrows, 1, t);
    __syncthreads();

    const float* tin = msged;
    float acc[4][4][4];

    for (int i = 0; i < R; i++) {
        const float* b1 = rb1 + (size_t)i * 128;
        const float* b2 = rb2 + (size_t)i * 128;
        const char* img1 = g_wimg + (size_t)((2 + 2 * i) * 2) * FRAG_SZ;
        const char* img2 = g_wimg + (size_t)((3 + 2 * i) * 2) * FRAG_SZ;

        // phase 1: acc = ssp(t) @ W1^T (sync-free)
        ZERO_ACC4(acc);
#pragma unroll
        for (int kh = 0; kh < 2; kh++)
            mma_passG<4>(acc, aHi[kh], aLo[kh],
                         (const uint4*)(img1 + (size_t)kh * FRAG_SZ),
                         id.nw, id.lane);
        __syncthreads();   // all warps done reading A

        // convert y = ssp(acc + b1) -> A tiles
#pragma unroll
        for (int mi = 0; mi < 4; mi++)
#pragma unroll
            for (int half = 0; half < 2; half++) {
                const int row = id.m_warp + 16 * mi + half * 8 + id.r_in;
#pragma unroll
                for (int nj = 0; nj < 4; nj++) {
                    const int col = id.nw * 32 + 8 * nj + id.c_in;
                    float2 bb = *(const float2*)(b1 + col);
                    float a = sspf(acc[mi][nj][half * 2 + 0] + bb.x);
                    float b = sspf(acc[mi][nj][half * 2 + 1] + bb.y);
                    uint32_t hi, lo;
                    split_pack(a, b, hi, lo);
                    const int kh = col >> 6;
                    uint32_t off = (uint32_t)row * RS + (col & 63) * 2;
                    *(uint32_t*)(smem + hiB[kh] + off) = hi;
                    *(uint32_t*)(smem + loB[kh] + off) = lo;
                }
            }
        __syncthreads();

        // phase 2: acc = ssp(y) @ W2^T (sync-free)
        ZERO_ACC4(acc);
#pragma unroll
        for (int kh = 0; kh < 2; kh++)
            mma_passG<4>(acc, aHi[kh], aLo[kh],
                         (const uint4*)(img2 + (size_t)kh * FRAG_SZ),
                         id.nw, id.lane);
        __syncthreads();   // all warps done reading A

        // t' = t + acc + b2 -> global addend (except last) + A tiles
        const bool wr = (i < R - 1);
#pragma unroll
        for (int mi = 0; mi < 4; mi++)
#pragma unroll
            for (int half = 0; half < 2; half++) {
                const int row = id.m_warp + 16 * mi + half * 8 + id.r_in;
                const bool ok = row < nrows;
                const size_t grow = (size_t)(row0 + row) * 128;
#pragma unroll
                for (int nj = 0; nj < 4; nj++) {
                    const int col = id.nw * 32 + 8 * nj + id.c_in;
                    float2 bb = *(const float2*)(b2 + col);
                    float2 tv = ok ? *(const float2*)(tin + grow + col)
                                   : make_float2(0.f, 0.f);
                    float ox = acc[mi][nj][half * 2 + 0] + bb.x + tv.x;
                    float oy = acc[mi][nj][half * 2 + 1] + bb.y + tv.y;
                    if (wr && ok) *(float2*)(tbuf + grow + col) = make_float2(ox, oy);
                    uint32_t hi, lo;
                    split_pack(sspf(ox), sspf(oy), hi, lo);
                    const int kh = col >> 6;
                    uint32_t off = (uint32_t)row * RS + (col & 63) * 2;
                    *(uint32_t*)(smem + hiB[kh] + off) = hi;
                    *(uint32_t*)(smem + loB[kh] + off) = lo;
                }
            }
        __syncthreads();
        tin = tbuf;
    }

    // final GEMM (slot 2+2R), sync-free
    const char* imgL = g_wimg + (size_t)((2 + 2 * R) * 2) * FRAG_SZ;
    ZERO_ACC4(acc);
#pragma unroll
    for (int kh = 0; kh < 2; kh++)
        mma_passG<4>(acc, aHi[kh], aLo[kh],
                     (const uint4*)(imgL + (size_t)kh * FRAG_SZ),
                     id.nw, id.lane);
#pragma unroll
    for (int mi = 0; mi < 4; mi++)
#pragma unroll
        for (int half = 0; half < 2; half++) {
            const int row = id.m_warp + 16 * mi + half * 8 + id.r_in;
            if (row >= nrows) continue;
            const size_t grow = (size_t)(row0 + row) * 128;
#pragma unroll
            for (int nj = 0; nj < 4; nj++) {
                const int col = id.nw * 32 + 8 * nj + id.c_in;
                float2 bb = *(const float2*)(blast + col);
                float2 xv = *(const float2*)(x + grow + col);
                float2 uv = *(const float2*)(u + col);
                float2 o;
                o.x = acc[mi][nj][half * 2 + 0] + bb.x + xv.x * uv.x;
                o.y = acc[mi][nj][half * 2 + 1] + bb.y + xv.y * uv.y;
                *(float2*)(out1 + grow + col) = o;
            }
        }
}

// ---------------------------------------------------------------------------
// edge_kernel v4: 64 edges/block, no W smem (B frags via LDG).
// smem: ea hi/lo [0, 18432); gate scratch overlaps [0, 34816).
// ---------------------------------------------------------------------------
constexpr int GSTR = 136;
constexpr int ESM_TOT4 = 64 * GSTR * 4;    // 34816

__global__ __launch_bounds__(256, 3)
void edge_kernel(const void* __restrict__ idx_raw,
                 const float* __restrict__ ea,
                 const float* __restrict__ tdiff,
                 float* __restrict__ aggr,
                 const char* __restrict__ gwimg,
                 int E)
{
    extern __shared__ char smem[];
    const uint32_t sbase = smem_u32(smem);
    float* gsm = (float*)smem;

    const int t    = threadIdx.x;
    const int lane = t & 31;
    const int w    = t >> 5;
    const int e0   = blockIdx.x * 64;
    const int nrows = min(64, E - e0);

    // warp grid: 2 (m) x 4 (n); warp tile 32 x 32
    const int m_warp = (w >> 2) * 32;
    const int nw     = w & 3;

    fill_64(smem, 0, 64 * RS, ea, 64, e0, nrows, t);

    // prefetch (src,dst); latency hides under the MMA
    const bool idx64 = (*(volatile unsigned*)&g_or) == 0u;
    const long long* ll = (const long long*)idx_raw;
    const int*       ii = (const int*)idx_raw;
    long long sReg = 0, dReg = 0;
    if (lane < 8) {
        int e = e0 + w * 8 + lane;
        if (e < E) {
            if (idx64) { sReg = ll[e]; dReg = ll[E + e]; }
            else       { sReg = ii[e]; dReg = ii[E + e]; }
        }
    }
    __syncthreads();

    const int a_row = m_warp + ((lane >> 3) & 1) * 8 + (lane & 7);
    const int a_kh  = (lane >> 4) * 16;
    uint32_t aHiA[2], aLoA[2];
#pragma unroll
    for (int mi = 0; mi < 2; mi++) {
        uint32_t off = (uint32_t)(a_row + 16 * mi) * RS + a_kh;
        aHiA[mi] = sbase + off;
        aLoA[mi] = sbase + 64 * RS + off;
    }

    float acc[2][4][4];
#pragma unroll
    for (int mi = 0; mi < 2; mi++)
#pragma unroll
        for (int nj = 0; nj < 4; nj++)
#pragma unroll
            for (int q = 0; q < 4; q++) acc[mi][nj][q] = 0.0f;

    mma_passG<2>(acc, aHiA, aLoA, (const uint4*)gwimg, nw, lane);
    __syncthreads();   // ea consumed; reuse smem for fp32 gate

    const int r_in = lane >> 2;
    const int c_in = (lane & 3) * 2;
#pragma unroll
    for (int mi = 0; mi < 2; mi++)
#pragma unroll
        for (int half = 0; half < 2; half++) {
            const int row = m_warp + 16 * mi + half * 8 + r_in;
#pragma unroll
            for (int nj = 0; nj < 4; nj++) {
                const int col = nw * 32 + 8 * nj + c_in;
                float2 o;
                o.x = acc[mi][nj][half * 2 + 0];
                o.y = acc[mi][nj][half * 2 + 1];
                *(float2*)(gsm + (size_t)row * GSTR + col) = o;
            }
        }
    __syncthreads();

    // scatter: warp w owns edges [w*8, w*8+8); batch gathers (MLP=8)
    float4 t4[8];
#pragma unroll
    for (int el = 0; el < 8; el++) {
        long long s = __shfl_sync(0xffffffffu, sReg, el);
        t4[el] = *(const float4*)(tdiff + (size_t)s * 128 + lane * 4);
    }
#pragma unroll
    for (int el = 0; el < 8; el++) {
        int e = e0 + w * 8 + el;
        if (e >= E) break;
        long long d = __shfl_sync(0xffffffffu, dReg, el);
        float4 g4 = *(const float4*)(gsm + (size_t)(w * 8 + el) * GSTR + lane * 4);
        float4 m;
        m.x = g4.x * t4[el].x; m.y = g4.y * t4[el].y;
        m.z = g4.z * t4[el].z; m.w = g4.w * t4[el].w;
        float* p = aggr + (size_t)d * 128 + lane * 4;
        asm volatile("red.global.add.v4.f32 [%0], {%1, %2, %3, %4};"
                     :: "l"(p), "f"(m.x), "f"(m.y), "f"(m.z), "f"(m.w)
                     : "memory");
    }
}

// ---------------------------------------------------------------------------
// launch
// ---------------------------------------------------------------------------
extern "C" void kernel_launch(void* const* d_in, const int* in_sizes, int n_in,
                              void* d_out, int out_size)
{
    const float* x     = (const float*)d_in[0];
    const void*  ei    = d_in[1];
    const float* ea    = (const float*)d_in[2];
    const float* Wsame = (const float*)d_in[3];
    const float* bsame = (const float*)d_in[4];
    const float* Wdiff = (const float*)d_in[5];
    const float* bdiff = (const float*)d_in[6];
    const float* Gw    = (const float*)d_in[7];
    const float* rW1   = (const float*)d_in[8];
    const float* rb1   = (const float*)d_in[9];
    const float* rW2   = (const float*)d_in[10];
    const float* rb2   = (const float*)d_in[11];
    const float* Wlast = (const float*)d_in[12];
    const float* blast = (const float*)d_in[13];
    const float* u     = (const float*)d_in[14];

    const int N = in_sizes[0] / 128;
    const int E = in_sizes[2] / 64;
    const int R = in_sizes[8] / (128 * 128);

    float* out1  = (float*)d_out;
    float* msged = (float*)d_out + (size_t)N * 128;

    float *tdiff_p, *t_p;
    char* wimg_p;
    cudaGetSymbolAddress((void**)&tdiff_p, g_tdiff);
    cudaGetSymbolAddress((void**)&t_p, g_t);
    cudaGetSymbolAddress((void**)&wimg_p, g_wimg);

    const int nblk = (N + 127) / 128;
    const int eblk = (E + 63) / 64;
    const int nsq  = 3 + 2 * R;

    cudaFuncSetAttribute(tc_dual,
                         cudaFuncAttributeMaxDynamicSharedMemorySize, SM_A4);
    cudaFuncSetAttribute(res_chain,
                         cudaFuncAttributeMaxDynamicSharedMemorySize, SM_A4);
    cudaFuncSetAttribute(edge_kernel,
                         cudaFuncAttributeMaxDynamicSharedMemorySize, ESM_TOT4);

    // index dtype detection + weight frag-image prep (deterministic per replay)
    reset_or_kernel<<<1, 1>>>();
    scan_odd_kernel<<<256, 256>>>((const unsigned*)ei, E);
    prep_w<<<2 * nsq + 1, 256>>>(Wsame, Wdiff, rW1, rW2, Wlast, Gw, R);

    // t_same -> msged, t_diff -> g_tdiff (shared A fill)
    tc_dual<<<nblk, 256, SM_A4>>>(x, bsame, bdiff, msged, tdiff_p, N);

    // edge gate + message + scatter-add into msged
    edge_kernel<<<eblk, 256, ESM_TOT4>>>(ei, ea, tdiff_p, msged,
                                         wimg_p + (size_t)(2 * nsq) * FRAG_SZ, E);

    // residual stack + final GEMM, one kernel
    res_chain<<<nblk, 256, SM_A4>>>(msged, t_p, rb1, rb2,
                                    blast, x, u, out1, N, R);
}

// round 12
// speedup vs baseline: 2.3545x; 1.0326x over previous
#include <cuda_runtime.h>
#include <cuda_bf16.h>
#include <cstdint>

// ---------------------------------------------------------------------------
// InteractionModule (PhysNet message passing + residual stack)
// All GEMMs on HMMA mma.sync m16n8k16 bf16, hi/lo split 3-term emulation.
// Weights pre-converted once per replay into mma B-fragment images (prep_w);
// GEMMs LDG B-frags from global (L2-hot): no W smem, no intra-GEMM syncs.
// Node kernels use M=64 CTA tiles -> 3 CTAs/SM (occupancy + wave packing).
// ---------------------------------------------------------------------------

#define SSP_LOG2 0.69314718055994530942f

__device__ __forceinline__ float sspf(float x) {
    return fmaxf(x, 0.0f) + __logf(1.0f + __expf(-fabsf(x))) - SSP_LOG2;
}

constexpr int FD   = 128;
constexpr int NMAX = 50176;

constexpr int RS      = 144;               // A-tile row stride bytes (9 x 16B)
constexpr int TILE64  = 64 * RS;           // 9216 B per [64 x 64] bf16 tile
constexpr int FRAG_SZ = 32768;             // one K-half B-frag image
constexpr int SM_A64  = 4 * TILE64;        // node kernels: 36864 B

__device__ float    g_tdiff[NMAX * FD];
__device__ float    g_t[NMAX * FD];
__device__ char     g_wimg[20 * FRAG_SZ];  // B-frag images (18 square + Gw)
__device__ unsigned g_or;

// ---------------------------------------------------------------------------
// edge_index dtype detection: odd 32-bit words all zero <=> int64
// ---------------------------------------------------------------------------
__global__ void reset_or_kernel() { g_or = 0u; }
__global__ void scan_odd_kernel(const unsigned* __restrict__ w, int E) {
    unsigned v = 0;
    for (int i = blockIdx.x * blockDim.x + threadIdx.x; i < E;
         i += gridDim.x * blockDim.x)
        v |= w[2 * i + 1];
    v = __reduce_or_sync(0xffffffffu, v);
    if ((threadIdx.x & 31) == 0 && v) atomicOr(&g_or, 1u);
}

// ---------------------------------------------------------------------------
// warp MMA helpers (generic PTX, sm_80+)
// ---------------------------------------------------------------------------
__device__ __forceinline__ uint32_t smem_u32(const void* p) {
    uint32_t a;
    asm("{ .reg .u64 t; cvta.to.shared.u64 t, %1; cvt.u32.u64 %0, t; }"
        : "=r"(a) : "l"(p));
    return a;
}
__device__ __forceinline__ void ldmx4(uint32_t* r, uint32_t addr) {
    asm volatile("ldmatrix.sync.aligned.m8n8.x4.shared.b16 {%0,%1,%2,%3}, [%4];"
                 : "=r"(r[0]), "=r"(r[1]), "=r"(r[2]), "=r"(r[3]) : "r"(addr));
}
__device__ __forceinline__ void mma16816(float* d, const uint32_t* a,
                                         uint32_t b0, uint32_t b1) {
    asm volatile("mma.sync.aligned.m16n8k16.row.col.f32.bf16.bf16.f32 "
                 "{%0,%1,%2,%3}, {%4,%5,%6,%7}, {%8,%9}, {%0,%1,%2,%3};"
                 : "+f"(d[0]), "+f"(d[1]), "+f"(d[2]), "+f"(d[3])
                 : "r"(a[0]), "r"(a[1]), "r"(a[2]), "r"(a[3]),
                   "r"(b0), "r"(b1));
}

__device__ __forceinline__ void split_pack(float a, float b,
                                           uint32_t& hi, uint32_t& lo) {
    __nv_bfloat16 ah = __float2bfloat16(a);
    __nv_bfloat16 bh = __float2bfloat16(b);
    __nv_bfloat16 al = __float2bfloat16(a - __bfloat162float(ah));
    __nv_bfloat16 bl = __float2bfloat16(b - __bfloat162float(bh));
    hi = ((uint32_t)*(uint16_t*)&bh << 16) | *(uint16_t*)&ah;
    lo = ((uint32_t)*(uint16_t*)&bl << 16) | *(uint16_t*)&al;
}

// fill a [64 x 64] fp32 sub-tile (col offset kh*64, row stride src_ld)
// into hi/lo bf16 A-tiles (row stride RS bytes)
template <bool DO_SSP>
__device__ __forceinline__ void fill_64h(char* dst, int hi_off, int lo_off,
                                         const float* __restrict__ src,
                                         int src_ld, int row0, int nrows,
                                         int kh, int t) {
    const int kg = t & 7;
    const int r0 = t >> 3;
#pragma unroll
    for (int p = 0; p < 2; p++) {
        int row = r0 + p * 32;
        float v[8];
        if (row < nrows) {
            const float* rp = src + (size_t)(row0 + row) * src_ld + kh * 64 + kg * 8;
            float4 va = *(const float4*)(rp);
            float4 vb = *(const float4*)(rp + 4);
            v[0] = va.x; v[1] = va.y; v[2] = va.z; v[3] = va.w;
            v[4] = vb.x; v[5] = vb.y; v[6] = vb.z; v[7] = vb.w;
        } else {
#pragma unroll
            for (int i = 0; i < 8; i++) v[i] = 0.0f;
        }
        uint32_t hi[4], lo[4];
#pragma unroll
        for (int i = 0; i < 4; i++) {
            float a = v[2 * i], b = v[2 * i + 1];
            if (DO_SSP) { a = sspf(a); b = sspf(b); }
            split_pack(a, b, hi[i], lo[i]);
        }
        uint32_t off = (uint32_t)row * RS + kg * 16;
        *(uint4*)(dst + hi_off + off) = make_uint4(hi[0], hi[1], hi[2], hi[3]);
        *(uint4*)(dst + lo_off + off) = make_uint4(lo[0], lo[1], lo[2], lo[3]);
    }
}

// one K=64 MMA pass; A from smem (ldmatrix), B frags via LDG from frag image.
// image entry index: ((nw*4 + ks)*4 + nj)*32 + lane; uint4 = {h0,h1,l0,l1}.
template <int MI>
__device__ __forceinline__ void mma_passG(float acc[MI][4][4],
                                          const uint32_t aHiA[MI],
                                          const uint32_t aLoA[MI],
                                          const uint4* __restrict__ bimg,
                                          int nw, int lane) {
#pragma unroll
    for (int ks = 0; ks < 4; ks++) {
        uint4 b[4];
#pragma unroll
        for (int nj = 0; nj < 4; nj++)
            b[nj] = bimg[((nw * 4 + ks) * 4 + nj) * 32 + lane];
        const uint32_t koff = ks * 32;
        uint32_t af[MI][4];
#pragma unroll
        for (int mi = 0; mi < MI; mi++) ldmx4(af[mi], aHiA[mi] + koff);
#pragma unroll
        for (int mi = 0; mi < MI; mi++)
#pragma unroll
            for (int nj = 0; nj < 4; nj++) {
                mma16816(acc[mi][nj], af[mi], b[nj].x, b[nj].y);   // Ah*Wh
                mma16816(acc[mi][nj], af[mi], b[nj].z, b[nj].w);   // Ah*Wl
            }
#pragma unroll
        for (int mi = 0; mi < MI; mi++) ldmx4(af[mi], aLoA[mi] + koff);
#pragma unroll
        for (int mi = 0; mi < MI; mi++)
#pragma unroll
            for (int nj = 0; nj < 4; nj++)
                mma16816(acc[mi][nj], af[mi], b[nj].x, b[nj].y);   // Al*Wh
    }
}

#define ZERO_ACC2(acc) do {                                                   \
    _Pragma("unroll") for (int mi = 0; mi < 2; mi++)                          \
    _Pragma("unroll") for (int nj = 0; nj < 4; nj++)                          \
    _Pragma("unroll") for (int q = 0; q < 4; q++) (acc)[mi][nj][q] = 0.0f;    \
} while (0)

struct TileIds {
    int lane, w, m_warp, nw, r_in, c_in;
    uint32_t aOff[2];
};
__device__ __forceinline__ TileIds make_ids(int t) {
    TileIds id;
    id.lane  = t & 31;
    id.w     = t >> 5;
    id.m_warp = (id.w >> 2) * 32;
    id.nw    = id.w & 3;
    id.r_in  = id.lane >> 2;
    id.c_in  = (id.lane & 3) * 2;
    const int a_row = id.m_warp + ((id.lane >> 3) & 1) * 8 + (id.lane & 7);
    const int a_kh  = (id.lane >> 4) * 16;
#pragma unroll
    for (int mi = 0; mi < 2; mi++)
        id.aOff[mi] = (uint32_t)(a_row + 16 * mi) * RS + a_kh;
    return id;
}

// ---------------------------------------------------------------------------
// prep_w: convert weights to mma B-fragment images, once per replay.
// entry (nw, ks, nj, lane): n = nw*32 + nj*8 + lane/4,
// k0 = kh*64 + ks*16 + (lane%4)*2; uint4 = {hi(k0..), hi(k0+8..), lo, lo}.
// ---------------------------------------------------------------------------
__global__ void prep_w(const float* __restrict__ Wsame,
                       const float* __restrict__ Wdiff,
                       const float* __restrict__ rW1,
                       const float* __restrict__ rW2,
                       const float* __restrict__ Wlast,
                       const float* __restrict__ Gw, int R)
{
    const int bq = blockIdx.x, t = threadIdx.x;
    const int nsq = 3 + 2 * R;
    const float* W;
    int ld, kh;
    char* img;
    if (bq < 2 * nsq) {
        const int slot = bq >> 1;
        kh = bq & 1;
        ld = 128;
        if (slot == 0) W = Wsame;
        else if (slot == 1) W = Wdiff;
        else if (slot < 2 + 2 * R) {
            int i = (slot - 2) >> 1;
            W = ((slot - 2) & 1) ? rW2 + (size_t)i * 16384
                                 : rW1 + (size_t)i * 16384;
        } else W = Wlast;
        img = g_wimg + (size_t)bq * FRAG_SZ;
    } else {
        W = Gw; ld = 64; kh = 0;
        img = g_wimg + (size_t)(2 * nsq) * FRAG_SZ;
    }
    uint4* out = (uint4*)img;
    for (int e = t; e < 2048; e += 256) {
        const int lane = e & 31, nj = (e >> 5) & 3, ks = (e >> 7) & 3, nw = e >> 9;
        const int n  = nw * 32 + nj * 8 + (lane >> 2);
        const int k0 = kh * 64 + ks * 16 + (lane & 3) * 2;
        const float* p = W + (size_t)n * ld + k0;
        uint32_t h0, l0, h1, l1;
        split_pack(p[0], p[1], h0, l0);
        split_pack(p[8], p[9], h1, l1);
        out[e] = make_uint4(h0, h1, l0, l1);
    }
}

// ---------------------------------------------------------------------------
// tc_dual: M=64 tile; A = ssp(x) filled once (kh0 hi/lo, kh1 hi/lo);
// two sync-free GEMMs (W_same -> msged, W_diff -> tdiff).
// ---------------------------------------------------------------------------
__global__ __launch_bounds__(256, 3)
void tc_dual(const float* __restrict__ x,
             const float* __restrict__ bsame, const float* __restrict__ bdiff,
             float* __restrict__ msged, float* __restrict__ tdiff, int N)
{
    extern __shared__ char smem[];
    const uint32_t sbase = smem_u32(smem);
    const int t     = threadIdx.x;
    const int row0  = blockIdx.x * 64;
    const int nrows = min(64, N - row0);
    TileIds id = make_ids(t);

    uint32_t aHi[2][2], aLo[2][2];
#pragma unroll
    for (int mi = 0; mi < 2; mi++) {
        aHi[0][mi] = sbase + 0 * TILE64 + id.aOff[mi];
        aLo[0][mi] = sbase + 1 * TILE64 + id.aOff[mi];
        aHi[1][mi] = sbase + 2 * TILE64 + id.aOff[mi];
        aLo[1][mi] = sbase + 3 * TILE64 + id.aOff[mi];
    }

    fill_64h<true>(smem, 0 * TILE64, 1 * TILE64, x, 128, row0, nrows, 0, t);
    fill_64h<true>(smem, 2 * TILE64, 3 * TILE64, x, 128, row0, nrows, 1, t);
    __syncthreads();

    float acc[2][4][4];
    const float* bp[2] = {bsame, bdiff};
    float*       op[2] = {msged, tdiff};

#pragma unroll
    for (int g = 0; g < 2; g++) {
        ZERO_ACC2(acc);
#pragma unroll
        for (int kh = 0; kh < 2; kh++) {
            const uint4* bimg = (const uint4*)(g_wimg + (size_t)(g * 2 + kh) * FRAG_SZ);
            mma_passG<2>(acc, aHi[kh], aLo[kh], bimg, id.nw, id.lane);
        }
#pragma unroll
        for (int mi = 0; mi < 2; mi++)
#pragma unroll
            for (int half = 0; half < 2; half++) {
                const int row = id.m_warp + 16 * mi + half * 8 + id.r_in;
                if (row >= nrows) continue;
                const size_t grow = (size_t)(row0 + row) * 128;
#pragma unroll
                for (int nj = 0; nj < 4; nj++) {
                    const int col = id.nw * 32 + 8 * nj + id.c_in;
                    float2 bb = *(const float2*)(bp[g] + col);
                    float2 o;
                    o.x = sspf(acc[mi][nj][half * 2 + 0] + bb.x);
                    o.y = sspf(acc[mi][nj][half * 2 + 1] + bb.y);
                    *(float2*)(op[g] + grow + col) = o;
                }
            }
    }
}

// ---------------------------------------------------------------------------
// res_chain: M=64 tile; R fused residual layers + final GEMM, one kernel.
// ---------------------------------------------------------------------------
__global__ __launch_bounds__(256, 3)
void res_chain(const float* __restrict__ msged, float* __restrict__ tbuf,
               const float* __restrict__ rb1, const float* __restrict__ rb2,
               const float* __restrict__ blast,
               const float* __restrict__ x, const float* __restrict__ u,
               float* __restrict__ out1, int N, int R)
{
    extern __shared__ char smem[];
    const uint32_t sbase = smem_u32(smem);
    const int t     = threadIdx.x;
    const int row0  = blockIdx.x * 64;
    const int nrows = min(64, N - row0);
    TileIds id = make_ids(t);

    uint32_t aHi[2][2], aLo[2][2];
#pragma unroll
    for (int mi = 0; mi < 2; mi++) {
        aHi[0][mi] = sbase + 0 * TILE64 + id.aOff[mi];
        aLo[0][mi] = sbase + 1 * TILE64 + id.aOff[mi];
        aHi[1][mi] = sbase + 2 * TILE64 + id.aOff[mi];
        aLo[1][mi] = sbase + 3 * TILE64 + id.aOff[mi];
    }
    const int hiB[2] = {0 * TILE64, 2 * TILE64};
    const int loB[2] = {1 * TILE64, 3 * TILE64};

    fill_64h<true>(smem, hiB[0], loB[0], msged, 128, row0, nrows, 0, t);
    fill_64h<true>(smem, hiB[1], loB[1], msged, 128, row0, nrows, 1, t);
    __syncthreads();

    const float* tin = msged;
    float acc[2][4][4];

    for (int i = 0; i < R; i++) {
        const float* b1 = rb1 + (size_t)i * 128;
        const float* b2 = rb2 + (size_t)i * 128;
        const char* img1 = g_wimg + (size_t)((2 + 2 * i) * 2) * FRAG_SZ;
        const char* img2 = g_wimg + (size_t)((3 + 2 * i) * 2) * FRAG_SZ;

        // phase 1: acc = ssp(t) @ W1^T (sync-free)
        ZERO_ACC2(acc);
#pragma unroll
        for (int kh = 0; kh < 2; kh++)
            mma_passG<2>(acc, aHi[kh], aLo[kh],
                         (const uint4*)(img1 + (size_t)kh * FRAG_SZ),
                         id.nw, id.lane);
        __syncthreads();   // all warps done reading A

        // convert y = ssp(acc + b1) -> A tiles
#pragma unroll
        for (int mi = 0; mi < 2; mi++)
#pragma unroll
            for (int half = 0; half < 2; half++) {
                const int row = id.m_warp + 16 * mi + half * 8 + id.r_in;
#pragma unroll
                for (int nj = 0; nj < 4; nj++) {
                    const int col = id.nw * 32 + 8 * nj + id.c_in;
                    float2 bb = *(const float2*)(b1 + col);
                    float a = sspf(acc[mi][nj][half * 2 + 0] + bb.x);
                    float b = sspf(acc[mi][nj][half * 2 + 1] + bb.y);
                    uint32_t hi, lo;
                    split_pack(a, b, hi, lo);
                    const int kh = col >> 6;
                    uint32_t off = (uint32_t)row * RS + (col & 63) * 2;
                    *(uint32_t*)(smem + hiB[kh] + off) = hi;
                    *(uint32_t*)(smem + loB[kh] + off) = lo;
                }
            }
        __syncthreads();

        // phase 2: acc = ssp(y) @ W2^T (sync-free)
        ZERO_ACC2(acc);
#pragma unroll
        for (int kh = 0; kh < 2; kh++)
            mma_passG<2>(acc, aHi[kh], aLo[kh],
                         (const uint4*)(img2 + (size_t)kh * FRAG_SZ),
                         id.nw, id.lane);
        __syncthreads();   // all warps done reading A

        // t' = t + acc + b2 -> global addend (except last) + A tiles
        const bool wr = (i < R - 1);
#pragma unroll
        for (int mi = 0; mi < 2; mi++)
#pragma unroll
            for (int half = 0; half < 2; half++) {
                const int row = id.m_warp + 16 * mi + half * 8 + id.r_in;
                const bool ok = row < nrows;
                const size_t grow = (size_t)(row0 + row) * 128;
#pragma unroll
                for (int nj = 0; nj < 4; nj++) {
                    const int col = id.nw * 32 + 8 * nj + id.c_in;
                    float2 bb = *(const float2*)(b2 + col);
                    float2 tv = ok ? *(const float2*)(tin + grow + col)
                                   : make_float2(0.f, 0.f);
                    float ox = acc[mi][nj][half * 2 + 0] + bb.x + tv.x;
                    float oy = acc[mi][nj][half * 2 + 1] + bb.y + tv.y;
                    if (wr && ok) *(float2*)(tbuf + grow + col) = make_float2(ox, oy);
                    uint32_t hi, lo;
                    split_pack(sspf(ox), sspf(oy), hi, lo);
                    const int kh = col >> 6;
                    uint32_t off = (uint32_t)row * RS + (col & 63) * 2;
                    *(uint32_t*)(smem + hiB[kh] + off) = hi;
                    *(uint32_t*)(smem + loB[kh] + off) = lo;
                }
            }
        __syncthreads();
        tin = tbuf;
    }

    // final GEMM (slot 2+2R), sync-free
    const char* imgL = g_wimg + (size_t)((2 + 2 * R) * 2) * FRAG_SZ;
    ZERO_ACC2(acc);
#pragma unroll
    for (int kh = 0; kh < 2; kh++)
        mma_passG<2>(acc, aHi[kh], aLo[kh],
                     (const uint4*)(imgL + (size_t)kh * FRAG_SZ),
                     id.nw, id.lane);
#pragma unroll
    for (int mi = 0; mi < 2; mi++)
#pragma unroll
        for (int half = 0; half < 2; half++) {
            const int row = id.m_warp + 16 * mi + half * 8 + id.r_in;
            if (row >= nrows) continue;
            const size_t grow = (size_t)(row0 + row) * 128;
#pragma unroll
            for (int nj = 0; nj < 4; nj++) {
                const int col = id.nw * 32 + 8 * nj + id.c_in;
                float2 bb = *(const float2*)(blast + col);
                float2 xv = *(const float2*)(x + grow + col);
                float2 uv = *(const float2*)(u + col);
                float2 o;
                o.x = acc[mi][nj][half * 2 + 0] + bb.x + xv.x * uv.x;
                o.y = acc[mi][nj][half * 2 + 1] + bb.y + xv.y * uv.y;
                *(float2*)(out1 + grow + col) = o;
            }
        }
}

// ---------------------------------------------------------------------------
// edge_kernel: 64 edges/block, no W smem (B frags via LDG).
// smem: ea hi/lo [0, 18432); gate scratch overlaps [0, 34816).
// ---------------------------------------------------------------------------
constexpr int GSTR = 136;
constexpr int ESM_TOT4 = 64 * GSTR * 4;    // 34816

__global__ __launch_bounds__(256, 3)
void edge_kernel(const void* __restrict__ idx_raw,
                 const float* __restrict__ ea,
                 const float* __restrict__ tdiff,
                 float* __restrict__ aggr,
                 const char* __restrict__ gwimg,
                 int E)
{
    extern __shared__ char smem[];
    const uint32_t sbase = smem_u32(smem);
    float* gsm = (float*)smem;

    const int t    = threadIdx.x;
    const int lane = t & 31;
    const int w    = t >> 5;
    const int e0   = blockIdx.x * 64;
    const int nrows = min(64, E - e0);

    // warp grid: 2 (m) x 4 (n); warp tile 32 x 32
    const int m_warp = (w >> 2) * 32;
    const int nw     = w & 3;

    fill_64h<false>(smem, 0, 64 * RS, ea, 64, e0, nrows, 0, t);

    // prefetch (src,dst); latency hides under the MMA
    const bool idx64 = (*(volatile unsigned*)&g_or) == 0u;
    const long long* ll = (const long long*)idx_raw;
    const int*       ii = (const int*)idx_raw;
    long long sReg = 0, dReg = 0;
    if (lane < 8) {
        int e = e0 + w * 8 + lane;
        if (e < E) {
            if (idx64) { sReg = ll[e]; dReg = ll[E + e]; }
            else       { sReg = ii[e]; dReg = ii[E + e]; }
        }
    }
    __syncthreads();

    const int a_row = m_warp + ((lane >> 3) & 1) * 8 + (lane & 7);
    const int a_kh  = (lane >> 4) * 16;
    uint32_t aHiA[2], aLoA[2];
#pragma unroll
    for (int mi = 0; mi < 2; mi++) {
        uint32_t off = (uint32_t)(a_row + 16 * mi) * RS + a_kh;
        aHiA[mi] = sbase + off;
        aLoA[mi] = sbase + 64 * RS + off;
    }

    float acc[2][4][4];
    ZERO_ACC2(acc);
    mma_passG<2>(acc, aHiA, aLoA, (const uint4*)gwimg, nw, lane);
    __syncthreads();   // ea consumed; reuse smem for fp32 gate

    const int r_in = lane >> 2;
    const int c_in = (lane & 3) * 2;
#pragma unroll
    for (int mi = 0; mi < 2; mi++)
#pragma unroll
        for (int half = 0; half < 2; half++) {
            const int row = m_warp + 16 * mi + half * 8 + r_in;
#pragma unroll
            for (int nj = 0; nj < 4; nj++) {
                const int col = nw * 32 + 8 * nj + c_in;
                float2 o;
                o.x = acc[mi][nj][half * 2 + 0];
                o.y = acc[mi][nj][half * 2 + 1];
                *(float2*)(gsm + (size_t)row * GSTR + col) = o;
            }
        }
    __syncthreads();

    // scatter: warp w owns edges [w*8, w*8+8); batch gathers (MLP=8)
    float4 t4[8];
#pragma unroll
    for (int el = 0; el < 8; el++) {
        long long s = __shfl_sync(0xffffffffu, sReg, el);
        t4[el] = *(const float4*)(tdiff + (size_t)s * 128 + lane * 4);
    }
#pragma unroll
    for (int el = 0; el < 8; el++) {
        int e = e0 + w * 8 + el;
        if (e >= E) break;
        long long d = __shfl_sync(0xffffffffu, dReg, el);
        float4 g4 = *(const float4*)(gsm + (size_t)(w * 8 + el) * GSTR + lane * 4);
        float4 m;
        m.x = g4.x * t4[el].x; m.y = g4.y * t4[el].y;
        m.z = g4.z * t4[el].z; m.w = g4.w * t4[el].w;
        float* p = aggr + (size_t)d * 128 + lane * 4;
        asm volatile("red.global.add.v4.f32 [%0], {%1, %2, %3, %4};"
                     :: "l"(p), "f"(m.x), "f"(m.y), "f"(m.z), "f"(m.w)
                     : "memory");
    }
}

// ---------------------------------------------------------------------------
// launch
// ---------------------------------------------------------------------------
extern "C" void kernel_launch(void* const* d_in, const int* in_sizes, int n_in,
                              void* d_out, int out_size)
{
    const float* x     = (const float*)d_in[0];
    const void*  ei    = d_in[1];
    const float* ea    = (const float*)d_in[2];
    const float* Wsame = (const float*)d_in[3];
    const float* bsame = (const float*)d_in[4];
    const float* Wdiff = (const float*)d_in[5];
    const float* bdiff = (const float*)d_in[6];
    const float* Gw    = (const float*)d_in[7];
    const float* rW1   = (const float*)d_in[8];
    const float* rb1   = (const float*)d_in[9];
    const float* rW2   = (const float*)d_in[10];
    const float* rb2   = (const float*)d_in[11];
    const float* Wlast = (const float*)d_in[12];
    const float* blast = (const float*)d_in[13];
    const float* u     = (const float*)d_in[14];

    const int N = in_sizes[0] / 128;
    const int E = in_sizes[2] / 64;
    const int R = in_sizes[8] / (128 * 128);

    float* out1  = (float*)d_out;
    float* msged = (float*)d_out + (size_t)N * 128;

    float *tdiff_p, *t_p;
    char* wimg_p;
    cudaGetSymbolAddress((void**)&tdiff_p, g_tdiff);
    cudaGetSymbolAddress((void**)&t_p, g_t);
    cudaGetSymbolAddress((void**)&wimg_p, g_wimg);

    const int nblk = (N + 63) / 64;
    const int eblk = (E + 63) / 64;
    const int nsq  = 3 + 2 * R;

    cudaFuncSetAttribute(tc_dual,
                         cudaFuncAttributeMaxDynamicSharedMemorySize, SM_A64);
    cudaFuncSetAttribute(res_chain,
                         cudaFuncAttributeMaxDynamicSharedMemorySize, SM_A64);
    cudaFuncSetAttribute(edge_kernel,
                         cudaFuncAttributeMaxDynamicSharedMemorySize, ESM_TOT4);

    // index dtype detection + weight frag-image prep (deterministic per replay)
    reset_or_kernel<<<1, 1>>>();
    scan_odd_kernel<<<256, 256>>>((const unsigned*)ei, E);
    prep_w<<<2 * nsq + 1, 256>>>(Wsame, Wdiff, rW1, rW2, Wlast, Gw, R);

    // t_same -> msged, t_diff -> g_tdiff (shared A fill)
    tc_dual<<<nblk, 256, SM_A64>>>(x, bsame, bdiff, msged, tdiff_p, N);

    // edge gate + message + scatter-add into msged
    edge_kernel<<<eblk, 256, ESM_TOT4>>>(ei, ea, tdiff_p, msged,
                                         wimg_p + (size_t)(2 * nsq) * FRAG_SZ, E);

    // residual stack + final GEMM, one kernel
    res_chain<<<nblk, 256, SM_A64>>>(msged, t_p, rb1, rb2,
                                     blast, x, u, out1, N, R);
}

// round 13
// speedup vs baseline: 2.5013x; 1.0624x over previous
#include <cuda_runtime.h>
#include <cuda_bf16.h>
#include <cstdint>

// ---------------------------------------------------------------------------
// InteractionModule (PhysNet message passing + residual stack)
// All GEMMs on HMMA mma.sync m16n8k16 bf16, hi/lo split 3-term emulation.
// Weights pre-converted once per replay into mma B-fragment images (prep_w,
// which also scans the edge-index dtype); GEMMs LDG B-frags from global
// (L2-hot): no W smem, no intra-GEMM syncs. Node kernels: M=64, 3 CTAs/SM.
// Edge kernel: gathers split into 2 batches, each hidden under prior work.
// 4 launches: prep_w(+scan), tc_dual, edge_kernel, res_chain.
// ---------------------------------------------------------------------------

#define SSP_LOG2 0.69314718055994530942f

__device__ __forceinline__ float sspf(float x) {
    return fmaxf(x, 0.0f) + __logf(1.0f + __expf(-fabsf(x))) - SSP_LOG2;
}

constexpr int FD   = 128;
constexpr int NMAX = 50176;

constexpr int RS      = 144;               // A-tile row stride bytes (9 x 16B)
constexpr int TILE64  = 64 * RS;           // 9216 B per [64 x 64] bf16 tile
constexpr int FRAG_SZ = 32768;             // one K-half B-frag image
constexpr int SM_A64  = 4 * TILE64;        // node kernels: 36864 B

__device__ float    g_tdiff[NMAX * FD];
__device__ float    g_t[NMAX * FD];
__device__ char     g_wimg[20 * FRAG_SZ];  // B-frag images (18 square + Gw)
__device__ unsigned g_or = 0u;             // idempotent across replays

// ---------------------------------------------------------------------------
// warp MMA helpers (generic PTX, sm_80+)
// ---------------------------------------------------------------------------
__device__ __forceinline__ uint32_t smem_u32(const void* p) {
    uint32_t a;
    asm("{ .reg .u64 t; cvta.to.shared.u64 t, %1; cvt.u32.u64 %0, t; }"
        : "=r"(a) : "l"(p));
    return a;
}
__device__ __forceinline__ void ldmx4(uint32_t* r, uint32_t addr) {
    asm volatile("ldmatrix.sync.aligned.m8n8.x4.shared.b16 {%0,%1,%2,%3}, [%4];"
                 : "=r"(r[0]), "=r"(r[1]), "=r"(r[2]), "=r"(r[3]) : "r"(addr));
}
__device__ __forceinline__ void mma16816(float* d, const uint32_t* a,
                                         uint32_t b0, uint32_t b1) {
    asm volatile("mma.sync.aligned.m16n8k16.row.col.f32.bf16.bf16.f32 "
                 "{%0,%1,%2,%3}, {%4,%5,%6,%7}, {%8,%9}, {%0,%1,%2,%3};"
                 : "+f"(d[0]), "+f"(d[1]), "+f"(d[2]), "+f"(d[3])
                 : "r"(a[0]), "r"(a[1]), "r"(a[2]), "r"(a[3]),
                   "r"(b0), "r"(b1));
}

__device__ __forceinline__ void split_pack(float a, float b,
                                           uint32_t& hi, uint32_t& lo) {
    __nv_bfloat16 ah = __float2bfloat16(a);
    __nv_bfloat16 bh = __float2bfloat16(b);
    __nv_bfloat16 al = __float2bfloat16(a - __bfloat162float(ah));
    __nv_bfloat16 bl = __float2bfloat16(b - __bfloat162float(bh));
    hi = ((uint32_t)*(uint16_t*)&bh << 16) | *(uint16_t*)&ah;
    lo = ((uint32_t)*(uint16_t*)&bl << 16) | *(uint16_t*)&al;
}

// fill a [64 x 64] fp32 sub-tile (col offset kh*64, row stride src_ld)
// into hi/lo bf16 A-tiles (row stride RS bytes)
template <bool DO_SSP>
__device__ __forceinline__ void fill_64h(char* dst, int hi_off, int lo_off,
                                         const float* __restrict__ src,
                                         int src_ld, int row0, int nrows,
                                         int kh, int t) {
    const int kg = t & 7;
    const int r0 = t >> 3;
#pragma unroll
    for (int p = 0; p < 2; p++) {
        int row = r0 + p * 32;
        float v[8];
        if (row < nrows) {
            const float* rp = src + (size_t)(row0 + row) * src_ld + kh * 64 + kg * 8;
            float4 va = *(const float4*)(rp);
            float4 vb = *(const float4*)(rp + 4);
            v[0] = va.x; v[1] = va.y; v[2] = va.z; v[3] = va.w;
            v[4] = vb.x; v[5] = vb.y; v[6] = vb.z; v[7] = vb.w;
        } else {
#pragma unroll
            for (int i = 0; i < 8; i++) v[i] = 0.0f;
        }
        uint32_t hi[4], lo[4];
#pragma unroll
        for (int i = 0; i < 4; i++) {
            float a = v[2 * i], b = v[2 * i + 1];
            if (DO_SSP) { a = sspf(a); b = sspf(b); }
            split_pack(a, b, hi[i], lo[i]);
        }
        uint32_t off = (uint32_t)row * RS + kg * 16;
        *(uint4*)(dst + hi_off + off) = make_uint4(hi[0], hi[1], hi[2], hi[3]);
        *(uint4*)(dst + lo_off + off) = make_uint4(lo[0], lo[1], lo[2], lo[3]);
    }
}

// one K=64 MMA pass; A from smem (ldmatrix), B frags via LDG from frag image.
// image entry index: ((nw*4 + ks)*4 + nj)*32 + lane; uint4 = {h0,h1,l0,l1}.
template <int MI>
__device__ __forceinline__ void mma_passG(float acc[MI][4][4],
                                          const uint32_t aHiA[MI],
                                          const uint32_t aLoA[MI],
                                          const uint4* __restrict__ bimg,
                                          int nw, int lane) {
#pragma unroll
    for (int ks = 0; ks < 4; ks++) {
        uint4 b[4];
#pragma unroll
        for (int nj = 0; nj < 4; nj++)
            b[nj] = bimg[((nw * 4 + ks) * 4 + nj) * 32 + lane];
        const uint32_t koff = ks * 32;
        uint32_t af[MI][4];
#pragma unroll
        for (int mi = 0; mi < MI; mi++) ldmx4(af[mi], aHiA[mi] + koff);
#pragma unroll
        for (int mi = 0; mi < MI; mi++)
#pragma unroll
            for (int nj = 0; nj < 4; nj++) {
                mma16816(acc[mi][nj], af[mi], b[nj].x, b[nj].y);   // Ah*Wh
                mma16816(acc[mi][nj], af[mi], b[nj].z, b[nj].w);   // Ah*Wl
            }
#pragma unroll
        for (int mi = 0; mi < MI; mi++) ldmx4(af[mi], aLoA[mi] + koff);
#pragma unroll
        for (int mi = 0; mi < MI; mi++)
#pragma unroll
            for (int nj = 0; nj < 4; nj++)
                mma16816(acc[mi][nj], af[mi], b[nj].x, b[nj].y);   // Al*Wh
    }
}

#define ZERO_ACC2(acc) do {                                                   \
    _Pragma("unroll") for (int mi = 0; mi < 2; mi++)                          \
    _Pragma("unroll") for (int nj = 0; nj < 4; nj++)                          \
    _Pragma("unroll") for (int q = 0; q < 4; q++) (acc)[mi][nj][q] = 0.0f;    \
} while (0)

struct TileIds {
    int lane, w, m_warp, nw, r_in, c_in;
    uint32_t aOff[2];
};
__device__ __forceinline__ TileIds make_ids(int t) {
    TileIds id;
    id.lane  = t & 31;
    id.w     = t >> 5;
    id.m_warp = (id.w >> 2) * 32;
    id.nw    = id.w & 3;
    id.r_in  = id.lane >> 2;
    id.c_in  = (id.lane & 3) * 2;
    const int a_row = id.m_warp + ((id.lane >> 3) & 1) * 8 + (id.lane & 7);
    const int a_kh  = (id.lane >> 4) * 16;
#pragma unroll
    for (int mi = 0; mi < 2; mi++)
        id.aOff[mi] = (uint32_t)(a_row + 16 * mi) * RS + a_kh;
    return id;
}

// ---------------------------------------------------------------------------
// prep_w: weight B-frag images + edge-index dtype scan, one launch.
// entry (nw, ks, nj, lane): n = nw*32 + nj*8 + lane/4,
// k0 = kh*64 + ks*16 + (lane%4)*2; uint4 = {hi(k0..), hi(k0+8..), lo, lo}.
// blocks [0, 2*nsq]: weights + Gw. blocks beyond: OR-scan of odd idx words
// (idempotent across replays for fixed input; g_or zero-initialized).
// ---------------------------------------------------------------------------
constexpr int SCAN_BLKS = 128;

__global__ void prep_w(const float* __restrict__ Wsame,
                       const float* __restrict__ Wdiff,
                       const float* __restrict__ rW1,
                       const float* __restrict__ rW2,
                       const float* __restrict__ Wlast,
                       const float* __restrict__ Gw, int R,
                       const unsigned* __restrict__ eiw, int E)
{
    const int bq = blockIdx.x, t = threadIdx.x;
    const int nsq = 3 + 2 * R;
    if (bq > 2 * nsq) {
        // scan blocks
        const int sb = bq - (2 * nsq + 1);
        unsigned v = 0;
        for (int i = sb * 256 + t; i < E; i += SCAN_BLKS * 256)
            v |= eiw[2 * i + 1];
        v = __reduce_or_sync(0xffffffffu, v);
        if ((t & 31) == 0 && v) atomicOr(&g_or, 1u);
        return;
    }
    const float* W;
    int ld, kh;
    char* img;
    if (bq < 2 * nsq) {
        const int slot = bq >> 1;
        kh = bq & 1;
        ld = 128;
        if (slot == 0) W = Wsame;
        else if (slot == 1) W = Wdiff;
        else if (slot < 2 + 2 * R) {
            int i = (slot - 2) >> 1;
            W = ((slot - 2) & 1) ? rW2 + (size_t)i * 16384
                                 : rW1 + (size_t)i * 16384;
        } else W = Wlast;
        img = g_wimg + (size_t)bq * FRAG_SZ;
    } else {
        W = Gw; ld = 64; kh = 0;
        img = g_wimg + (size_t)(2 * nsq) * FRAG_SZ;
    }
    uint4* out = (uint4*)img;
    for (int e = t; e < 2048; e += 256) {
        const int lane = e & 31, nj = (e >> 5) & 3, ks = (e >> 7) & 3, nw = e >> 9;
        const int n  = nw * 32 + nj * 8 + (lane >> 2);
        const int k0 = kh * 64 + ks * 16 + (lane & 3) * 2;
        const float* p = W + (size_t)n * ld + k0;
        uint32_t h0, l0, h1, l1;
        split_pack(p[0], p[1], h0, l0);
        split_pack(p[8], p[9], h1, l1);
        out[e] = make_uint4(h0, h1, l0, l1);
    }
}

// ---------------------------------------------------------------------------
// tc_dual: M=64 tile; A = ssp(x) filled once (kh0 hi/lo, kh1 hi/lo);
// two sync-free GEMMs (W_same -> msged, W_diff -> tdiff).
// ---------------------------------------------------------------------------
__global__ __launch_bounds__(256, 3)
void tc_dual(const float* __restrict__ x,
             const float* __restrict__ bsame, const float* __restrict__ bdiff,
             float* __restrict__ msged, float* __restrict__ tdiff, int N)
{
    extern __shared__ char smem[];
    const uint32_t sbase = smem_u32(smem);
    const int t     = threadIdx.x;
    const int row0  = blockIdx.x * 64;
    const int nrows = min(64, N - row0);
    TileIds id = make_ids(t);

    uint32_t aHi[2][2], aLo[2][2];
#pragma unroll
    for (int mi = 0; mi < 2; mi++) {
        aHi[0][mi] = sbase + 0 * TILE64 + id.aOff[mi];
        aLo[0][mi] = sbase + 1 * TILE64 + id.aOff[mi];
        aHi[1][mi] = sbase + 2 * TILE64 + id.aOff[mi];
        aLo[1][mi] = sbase + 3 * TILE64 + id.aOff[mi];
    }

    fill_64h<true>(smem, 0 * TILE64, 1 * TILE64, x, 128, row0, nrows, 0, t);
    fill_64h<true>(smem, 2 * TILE64, 3 * TILE64, x, 128, row0, nrows, 1, t);
    __syncthreads();

    float acc[2][4][4];
    const float* bp[2] = {bsame, bdiff};
    float*       op[2] = {msged, tdiff};

#pragma unroll
    for (int g = 0; g < 2; g++) {
        ZERO_ACC2(acc);
#pragma unroll
        for (int kh = 0; kh < 2; kh++) {
            const uint4* bimg = (const uint4*)(g_wimg + (size_t)(g * 2 + kh) * FRAG_SZ);
            mma_passG<2>(acc, aHi[kh], aLo[kh], bimg, id.nw, id.lane);
        }
#pragma unroll
        for (int mi = 0; mi < 2; mi++)
#pragma unroll
            for (int half = 0; half < 2; half++) {
                const int row = id.m_warp + 16 * mi + half * 8 + id.r_in;
                if (row >= nrows) continue;
                const size_t grow = (size_t)(row0 + row) * 128;
#pragma unroll
                for (int nj = 0; nj < 4; nj++) {
                    const int col = id.nw * 32 + 8 * nj + id.c_in;
                    float2 bb = *(const float2*)(bp[g] + col);
                    float2 o;
                    o.x = sspf(acc[mi][nj][half * 2 + 0] + bb.x);
                    o.y = sspf(acc[mi][nj][half * 2 + 1] + bb.y);
                    *(float2*)(op[g] + grow + col) = o;
                }
            }
    }
}

// ---------------------------------------------------------------------------
// res_chain: M=64 tile; R fused residual layers + final GEMM, one kernel.
// ---------------------------------------------------------------------------
__global__ __launch_bounds__(256, 3)
void res_chain(const float* __restrict__ msged, float* __restrict__ tbuf,
               const float* __restrict__ rb1, const float* __restrict__ rb2,
               const float* __restrict__ blast,
               const float* __restrict__ x, const float* __restrict__ u,
               float* __restrict__ out1, int N, int R)
{
    extern __shared__ char smem[];
    const uint32_t sbase = smem_u32(smem);
    const int t     = threadIdx.x;
    const int row0  = blockIdx.x * 64;
    const int nrows = min(64, N - row0);
    TileIds id = make_ids(t);

    uint32_t aHi[2][2], aLo[2][2];
#pragma unroll
    for (int mi = 0; mi < 2; mi++) {
        aHi[0][mi] = sbase + 0 * TILE64 + id.aOff[mi];
        aLo[0][mi] = sbase + 1 * TILE64 + id.aOff[mi];
        aHi[1][mi] = sbase + 2 * TILE64 + id.aOff[mi];
        aLo[1][mi] = sbase + 3 * TILE64 + id.aOff[mi];
    }
    const int hiB[2] = {0 * TILE64, 2 * TILE64};
    const int loB[2] = {1 * TILE64, 3 * TILE64};

    fill_64h<true>(smem, hiB[0], loB[0], msged, 128, row0, nrows, 0, t);
    fill_64h<true>(smem, hiB[1], loB[1], msged, 128, row0, nrows, 1, t);
    __syncthreads();

    const float* tin = msged;
    float acc[2][4][4];

    for (int i = 0; i < R; i++) {
        const float* b1 = rb1 + (size_t)i * 128;
        const float* b2 = rb2 + (size_t)i * 128;
        const char* img1 = g_wimg + (size_t)((2 + 2 * i) * 2) * FRAG_SZ;
        const char* img2 = g_wimg + (size_t)((3 + 2 * i) * 2) * FRAG_SZ;

        // phase 1: acc = ssp(t) @ W1^T (sync-free)
        ZERO_ACC2(acc);
#pragma unroll
        for (int kh = 0; kh < 2; kh++)
            mma_passG<2>(acc, aHi[kh], aLo[kh],
                         (const uint4*)(img1 + (size_t)kh * FRAG_SZ),
                         id.nw, id.lane);
        __syncthreads();   // all warps done reading A

        // convert y = ssp(acc + b1) -> A tiles
#pragma unroll
        for (int mi = 0; mi < 2; mi++)
#pragma unroll
            for (int half = 0; half < 2; half++) {
                const int row = id.m_warp + 16 * mi + half * 8 + id.r_in;
#pragma unroll
                for (int nj = 0; nj < 4; nj++) {
                    const int col = id.nw * 32 + 8 * nj + id.c_in;
                    float2 bb = *(const float2*)(b1 + col);
                    float a = sspf(acc[mi][nj][half * 2 + 0] + bb.x);
                    float b = sspf(acc[mi][nj][half * 2 + 1] + bb.y);
                    uint32_t hi, lo;
                    split_pack(a, b, hi, lo);
                    const int kh = col >> 6;
                    uint32_t off = (uint32_t)row * RS + (col & 63) * 2;
                    *(uint32_t*)(smem + hiB[kh] + off) = hi;
                    *(uint32_t*)(smem + loB[kh] + off) = lo;
                }
            }
        __syncthreads();

        // phase 2: acc = ssp(y) @ W2^T (sync-free)
        ZERO_ACC2(acc);
#pragma unroll
        for (int kh = 0; kh < 2; kh++)
            mma_passG<2>(acc, aHi[kh], aLo[kh],
                         (const uint4*)(img2 + (size_t)kh * FRAG_SZ),
                         id.nw, id.lane);
        __syncthreads();   // all warps done reading A

        // t' = t + acc + b2 -> global addend (except last) + A tiles
        const bool wr = (i < R - 1);
#pragma unroll
        for (int mi = 0; mi < 2; mi++)
#pragma unroll
            for (int half = 0; half < 2; half++) {
                const int row = id.m_warp + 16 * mi + half * 8 + id.r_in;
                const bool ok = row < nrows;
                const size_t grow = (size_t)(row0 + row) * 128;
#pragma unroll
                for (int nj = 0; nj < 4; nj++) {
                    const int col = id.nw * 32 + 8 * nj + id.c_in;
                    float2 bb = *(const float2*)(b2 + col);
                    float2 tv = ok ? *(const float2*)(tin + grow + col)
                                   : make_float2(0.f, 0.f);
                    float ox = acc[mi][nj][half * 2 + 0] + bb.x + tv.x;
                    float oy = acc[mi][nj][half * 2 + 1] + bb.y + tv.y;
                    if (wr && ok) *(float2*)(tbuf + grow + col) = make_float2(ox, oy);
                    uint32_t hi, lo;
                    split_pack(sspf(ox), sspf(oy), hi, lo);
                    const int kh = col >> 6;
                    uint32_t off = (uint32_t)row * RS + (col & 63) * 2;
                    *(uint32_t*)(smem + hiB[kh] + off) = hi;
                    *(uint32_t*)(smem + loB[kh] + off) = lo;
                }
            }
        __syncthreads();
        tin = tbuf;
    }

    // final GEMM (slot 2+2R), sync-free
    const char* imgL = g_wimg + (size_t)((2 + 2 * R) * 2) * FRAG_SZ;
    ZERO_ACC2(acc);
#pragma unroll
    for (int kh = 0; kh < 2; kh++)
        mma_passG<2>(acc, aHi[kh], aLo[kh],
                     (const uint4*)(imgL + (size_t)kh * FRAG_SZ),
                     id.nw, id.lane);
#pragma unroll
    for (int mi = 0; mi < 2; mi++)
#pragma unroll
        for (int half = 0; half < 2; half++) {
            const int row = id.m_warp + 16 * mi + half * 8 + id.r_in;
            if (row >= nrows) continue;
            const size_t grow = (size_t)(row0 + row) * 128;
#pragma unroll
            for (int nj = 0; nj < 4; nj++) {
                const int col = id.nw * 32 + 8 * nj + id.c_in;
                float2 bb = *(const float2*)(blast + col);
                float2 xv = *(const float2*)(x + grow + col);
                float2 uv = *(const float2*)(u + col);
                float2 o;
                o.x = acc[mi][nj][half * 2 + 0] + bb.x + xv.x * uv.x;
                o.y = acc[mi][nj][half * 2 + 1] + bb.y + xv.y * uv.y;
                *(float2*)(out1 + grow + col) = o;
            }
        }
}

// ---------------------------------------------------------------------------
// edge_kernel: 64 edges/block, no W smem (B frags via LDG).
// smem: ea hi/lo [0, 18432); gate scratch overlaps [0, 34816).
// Gathers split in two 4-edge batches: batch A issued before the MMA
// (latency hidden under HMMA), batch B issued before batch-A reds.
// ---------------------------------------------------------------------------
constexpr int GSTR = 136;
constexpr int ESM_TOT4 = 64 * GSTR * 4;    // 34816

__global__ __launch_bounds__(256, 3)
void edge_kernel(const void* __restrict__ idx_raw,
                 const float* __restrict__ ea,
                 const float* __restrict__ tdiff,
                 float* __restrict__ aggr,
                 const char* __restrict__ gwimg,
                 int E)
{
    extern __shared__ char smem[];
    const uint32_t sbase = smem_u32(smem);
    float* gsm = (float*)smem;

    const int t    = threadIdx.x;
    const int lane = t & 31;
    const int w    = t >> 5;
    const int e0   = blockIdx.x * 64;
    const int nrows = min(64, E - e0);

    // prefetch (src,dst) first; DRAM latency overlaps the ea fill
    const bool idx64 = (*(volatile unsigned*)&g_or) == 0u;
    const long long* ll = (const long long*)idx_raw;
    const int*       ii = (const int*)idx_raw;
    long long sReg = 0, dReg = 0;
    if (lane < 8) {
        int e = e0 + w * 8 + lane;
        if (e < E) {
            if (idx64) { sReg = ll[e]; dReg = ll[E + e]; }
            else       { sReg = ii[e]; dReg = ii[E + e]; }
        }
    }

    // warp grid: 2 (m) x 4 (n); warp tile 32 x 32
    const int m_warp = (w >> 2) * 32;
    const int nw     = w & 3;

    fill_64h<false>(smem, 0, 64 * RS, ea, 64, e0, nrows, 0, t);
    __syncthreads();

    const int a_row = m_warp + ((lane >> 3) & 1) * 8 + (lane & 7);
    const int a_kh  = (lane >> 4) * 16;
    uint32_t aHiA[2], aLoA[2];
#pragma unroll
    for (int mi = 0; mi < 2; mi++) {
        uint32_t off = (uint32_t)(a_row + 16 * mi) * RS + a_kh;
        aHiA[mi] = sbase + off;
        aLoA[mi] = sbase + 64 * RS + off;
    }

    // batch A gathers (edges 0..3): latency hidden under the MMA
    float4 t4a[4];
#pragma unroll
    for (int el = 0; el < 4; el++) {
        long long s = __shfl_sync(0xffffffffu, sReg, el);
        t4a[el] = *(const float4*)(tdiff + (size_t)s * 128 + lane * 4);
    }

    float acc[2][4][4];
    ZERO_ACC2(acc);
    mma_passG<2>(acc, aHiA, aLoA, (const uint4*)gwimg, nw, lane);
    __syncthreads();   // ea consumed; reuse smem for fp32 gate

    const int r_in = lane >> 2;
    const int c_in = (lane & 3) * 2;
#pragma unroll
    for (int mi = 0; mi < 2; mi++)
#pragma unroll
        for (int half = 0; half < 2; half++) {
            const int row = m_warp + 16 * mi + half * 8 + r_in;
#pragma unroll
            for (int nj = 0; nj < 4; nj++) {
                const int col = nw * 32 + 8 * nj + c_in;
                float2 o;
                o.x = acc[mi][nj][half * 2 + 0];
                o.y = acc[mi][nj][half * 2 + 1];
                *(float2*)(gsm + (size_t)row * GSTR + col) = o;
            }
        }
    __syncthreads();

    // batch B gathers (edges 4..7): latency hidden under batch-A reds
    float4 t4b[4];
#pragma unroll
    for (int el = 0; el < 4; el++) {
        long long s = __shfl_sync(0xffffffffu, sReg, el + 4);
        t4b[el] = *(const float4*)(tdiff + (size_t)s * 128 + lane * 4);
    }

#pragma unroll
    for (int el = 0; el < 4; el++) {
        int e = e0 + w * 8 + el;
        if (e >= E) break;
        long long d = __shfl_sync(0xffffffffu, dReg, el);
        float4 g4 = *(const float4*)(gsm + (size_t)(w * 8 + el) * GSTR + lane * 4);
        float4 m;
        m.x = g4.x * t4a[el].x; m.y = g4.y * t4a[el].y;
        m.z = g4.z * t4a[el].z; m.w = g4.w * t4a[el].w;
        float* p = aggr + (size_t)d * 128 + lane * 4;
        asm volatile("red.global.add.v4.f32 [%0], {%1, %2, %3, %4};"
                     :: "l"(p), "f"(m.x), "f"(m.y), "f"(m.z), "f"(m.w)
                     : "memory");
    }
#pragma unroll
    for (int el = 0; el < 4; el++) {
        int e = e0 + w * 8 + 4 + el;
        if (e >= E) break;
        long long d = __shfl_sync(0xffffffffu, dReg, el + 4);
        float4 g4 = *(const float4*)(gsm + (size_t)(w * 8 + 4 + el) * GSTR + lane * 4);
        float4 m;
        m.x = g4.x * t4b[el].x; m.y = g4.y * t4b[el].y;
        m.z = g4.z * t4b[el].z; m.w = g4.w * t4b[el].w;
        float* p = aggr + (size_t)d * 128 + lane * 4;
        asm volatile("red.global.add.v4.f32 [%0], {%1, %2, %3, %4};"
                     :: "l"(p), "f"(m.x), "f"(m.y), "f"(m.z), "f"(m.w)
                     : "memory");
    }
}

// ---------------------------------------------------------------------------
// launch
// ---------------------------------------------------------------------------
extern "C" void kernel_launch(void* const* d_in, const int* in_sizes, int n_in,
                              void* d_out, int out_size)
{
    const float* x     = (const float*)d_in[0];
    const void*  ei    = d_in[1];
    const float* ea    = (const float*)d_in[2];
    const float* Wsame = (const float*)d_in[3];
    const float* bsame = (const float*)d_in[4];
    const float* Wdiff = (const float*)d_in[5];
    const float* bdiff = (const float*)d_in[6];
    const float* Gw    = (const float*)d_in[7];
    const float* rW1   = (const float*)d_in[8];
    const float* rb1   = (const float*)d_in[9];
    const float* rW2   = (const float*)d_in[10];
    const float* rb2   = (const float*)d_in[11];
    const float* Wlast = (const float*)d_in[12];
    const float* blast = (const float*)d_in[13];
    const float* u     = (const float*)d_in[14];

    const int N = in_sizes[0] / 128;
    const int E = in_sizes[2] / 64;
    const int R = in_sizes[8] / (128 * 128);

    float* out1  = (float*)d_out;
    float* msged = (float*)d_out + (size_t)N * 128;

    float *tdiff_p, *t_p;
    char* wimg_p;
    cudaGetSymbolAddress((void**)&tdiff_p, g_tdiff);
    cudaGetSymbolAddress((void**)&t_p, g_t);
    cudaGetSymbolAddress((void**)&wimg_p, g_wimg);

    const int nblk = (N + 63) / 64;
    const int eblk = (E + 63) / 64;
    const int nsq  = 3 + 2 * R;

    cudaFuncSetAttribute(tc_dual,
                         cudaFuncAttributeMaxDynamicSharedMemorySize, SM_A64);
    cudaFuncSetAttribute(res_chain,
                         cudaFuncAttributeMaxDynamicSharedMemorySize, SM_A64);
    cudaFuncSetAttribute(edge_kernel,
                         cudaFuncAttributeMaxDynamicSharedMemorySize, ESM_TOT4);

    // weight frag-image prep + idx dtype scan (deterministic per replay)
    prep_w<<<2 * nsq + 1 + SCAN_BLKS, 256>>>(Wsame, Wdiff, rW1, rW2, Wlast,
                                             Gw, R, (const unsigned*)ei, E);

    // t_same -> msged, t_diff -> g_tdiff (shared A fill)
    tc_dual<<<nblk, 256, SM_A64>>>(x, bsame, bdiff, msged, tdiff_p, N);

    // edge gate + message + scatter-add into msged
    edge_kernel<<<eblk, 256, ESM_TOT4>>>(ei, ea, tdiff_p, msged,
                                         wimg_p + (size_t)(2 * nsq) * FRAG_SZ, E);

    // residual stack + final GEMM, one kernel
    res_chain<<<nblk, 256, SM_A64>>>(msged, t_p, rb1, rb2,
                                     blast, x, u, out1, N, R);
}